// round 2
// baseline (speedup 1.0000x reference)
#include <cuda_runtime.h>
#include <math.h>

#define Bsz 4
#define SEQ 2048
#define DIM 512
#define NH  8
#define HDm 64
#define FFm 1024
#define C2m 128
#define HFm 64
#define WFm 64
#define EPSf 1e-6f

// ---------------- static scratch (no allocation allowed) ----------------
__device__ float g_feats[Bsz*SEQ*C2m];        // 4 MB
__device__ float g_x   [Bsz*SEQ*DIM];         // 16 MB
__device__ float g_xn  [Bsz*SEQ*DIM];
__device__ float g_qkv [Bsz*SEQ*3*DIM];       // 48 MB
__device__ float g_o   [Bsz*SEQ*DIM];
__device__ float g_x2  [Bsz*SEQ*DIM];
__device__ float g_xn2 [Bsz*SEQ*DIM];
__device__ float g_h   [Bsz*SEQ*2*FFm];       // 64 MB
__device__ float g_hg  [Bsz*SEQ*FFm];         // 32 MB

// ---------------- helpers ----------------
__device__ __forceinline__ float warpSum(float v){
    #pragma unroll
    for (int o = 16; o > 0; o >>= 1) v += __shfl_xor_sync(0xFFFFFFFFu, v, o);
    return v;
}
__device__ __forceinline__ float warpMax(float v){
    #pragma unroll
    for (int o = 16; o > 0; o >>= 1) v = fmaxf(v, __shfl_xor_sync(0xFFFFFFFFu, v, o));
    return v;
}

// ---------------- bilinear sample: feats[b,n,c] ----------------
__global__ void bilinear_kernel(const float* __restrict__ fmaps,
                                const float* __restrict__ coords){
    int bn = blockIdx.x;             // b*SEQ + n
    int b  = bn / SEQ;
    int c  = threadIdx.x;            // 0..127
    float xc = coords[(size_t)bn*2 + 0];
    float yc = coords[(size_t)bn*2 + 1];
    xc = fminf(fmaxf(xc, 0.f), (float)(WFm-1));
    yc = fminf(fmaxf(yc, 0.f), (float)(HFm-1));
    float x0 = floorf(xc), y0 = floorf(yc);
    float wx = xc - x0,    wy = yc - y0;
    int x0i = (int)x0, y0i = (int)y0;
    int x1i = min(x0i+1, WFm-1), y1i = min(y0i+1, HFm-1);
    const float* img = fmaps + ((size_t)(b*C2m + c))*HFm*WFm;
    float f00 = img[y0i*WFm + x0i];
    float f01 = img[y0i*WFm + x1i];
    float f10 = img[y1i*WFm + x0i];
    float f11 = img[y1i*WFm + x1i];
    float top = f00*(1.f-wx) + f01*wx;
    float bot = f10*(1.f-wx) + f11*wx;
    g_feats[(size_t)bn*C2m + c] = top*(1.f-wy) + bot*wy;
}

// ---------------- GEMM: C[M,Nout] = A[M,K] @ W[Nout,K]^T (+bias)(+resid) ----------------
__global__ __launch_bounds__(256)
void gemm_kernel(const float* __restrict__ A, const float* __restrict__ W,
                 const float* __restrict__ bias, const float* __restrict__ resid,
                 float* __restrict__ C, int M, int Nout, int K){
    __shared__ float As[16][64];
    __shared__ float Bs[16][64];
    int tid = threadIdx.x;
    int tx = tid & 15, ty = tid >> 4;
    int m0 = blockIdx.y * 64, n0 = blockIdx.x * 64;
    int lr = tid >> 2;          // 0..63
    int lc = (tid & 3) * 4;     // 0,4,8,12
    const float* Ap = A + (size_t)(m0 + lr) * K + lc;
    const float* Wp = W + (size_t)(n0 + lr) * K + lc;
    float acc[4][4] = {};
    for (int k0 = 0; k0 < K; k0 += 16){
        float4 a4 = *(const float4*)(Ap + k0);
        float4 b4 = *(const float4*)(Wp + k0);
        As[lc+0][lr]=a4.x; As[lc+1][lr]=a4.y; As[lc+2][lr]=a4.z; As[lc+3][lr]=a4.w;
        Bs[lc+0][lr]=b4.x; Bs[lc+1][lr]=b4.y; Bs[lc+2][lr]=b4.z; Bs[lc+3][lr]=b4.w;
        __syncthreads();
        #pragma unroll
        for (int k = 0; k < 16; k++){
            float4 a = *(const float4*)(&As[k][ty*4]);
            float4 b = *(const float4*)(&Bs[k][tx*4]);
            float ar[4] = {a.x,a.y,a.z,a.w};
            float br[4] = {b.x,b.y,b.z,b.w};
            #pragma unroll
            for (int i = 0; i < 4; i++)
                #pragma unroll
                for (int j = 0; j < 4; j++)
                    acc[i][j] += ar[i]*br[j];
        }
        __syncthreads();
    }
    #pragma unroll
    for (int i = 0; i < 4; i++){
        int m = m0 + ty*4 + i;
        size_t off = (size_t)m * Nout + n0 + tx*4;
        float4 r = make_float4(acc[i][0], acc[i][1], acc[i][2], acc[i][3]);
        if (bias){
            float4 bb = *(const float4*)(bias + n0 + tx*4);
            r.x += bb.x; r.y += bb.y; r.z += bb.z; r.w += bb.w;
        }
        if (resid){
            float4 rr = *(const float4*)(resid + off);
            r.x += rr.x; r.y += rr.y; r.z += rr.z; r.w += rr.w;
        }
        *(float4*)(C + off) = r;
    }
}

// ---------------- RMSNorm over DIM=512 ----------------
__global__ void rmsnorm_kernel(const float* __restrict__ X,
                               const float* __restrict__ scale,
                               float* __restrict__ Y){
    int row = blockIdx.x;
    int t   = threadIdx.x;  // 128
    const float4* x4 = (const float4*)(X + (size_t)row*DIM);
    float4 v = x4[t];
    float ss = v.x*v.x + v.y*v.y + v.z*v.z + v.w*v.w;
    ss = warpSum(ss);
    __shared__ float red[4];
    if ((t & 31) == 0) red[t >> 5] = ss;
    __syncthreads();
    if (t == 0) red[0] = red[0] + red[1] + red[2] + red[3];
    __syncthreads();
    float inv = rsqrtf(red[0] / (float)DIM + EPSf);
    float4 s = ((const float4*)scale)[t];
    float4 o;
    o.x = v.x * s.x * inv; o.y = v.y * s.y * inv;
    o.z = v.z * s.z * inv; o.w = v.w * s.w * inv;
    ((float4*)(Y + (size_t)row*DIM))[t] = o;
}

// ---------------- per-head RMSNorm + rotary on q,k (in-place) ----------------
__global__ void qkprep_kernel(float* __restrict__ qkv, const float* __restrict__ theta,
                              const float* __restrict__ sq, const float* __restrict__ sk){
    int t = blockIdx.x;
    int isK = t & 1; int rest = t >> 1;
    int h = rest % NH; rest /= NH;
    int n = rest % SEQ; int b = rest / SEQ;
    int lane = threadIdx.x;  // 32
    float* p = qkv + ((size_t)(b*SEQ + n))*(3*DIM) + isK*DIM + h*HDm;
    float v0 = p[lane], v1 = p[lane + 32];
    float ss = warpSum(v0*v0 + v1*v1);
    float inv = rsqrtf(ss / (float)HDm + EPSf);
    const float* sc = isK ? sk : sq;
    v0 = v0 * sc[lane]      * inv;
    v1 = v1 * sc[lane + 32] * inv;
    float th = theta[(((size_t)(b*NH + h))*SEQ + n)*(HDm/2) + lane];
    float cs = cosf(th), sn = sinf(th);
    float y0 = v0*cs - v1*sn;
    float y1 = v1*cs + v0*sn;
    p[lane]      = y0;
    p[lane + 32] = y1;
}

// ---------------- attention: softmax(q k^T) v, 4 queries / block ----------------
#define QT 4
__global__ __launch_bounds__(128)
void attn_kernel(const float* __restrict__ qkv, float* __restrict__ O){
    __shared__ float qs[QT][HDm];
    __shared__ float sc[QT][SEQ];
    __shared__ float opart[32][HDm + 4];
    __shared__ float red[4];
    __shared__ float mden[2*QT];

    int blk = blockIdx.x;
    int nq = SEQ / QT;
    int qt = blk % nq; int rest = blk / nq;
    int h = rest % NH; int b = rest / NH;
    int i0 = qt * QT;
    int tid = threadIdx.x;

    for (int idx = tid; idx < QT*HDm; idx += 128){
        int qi = idx / HDm, d = idx % HDm;
        qs[qi][d] = qkv[((size_t)(b*SEQ + i0 + qi))*(3*DIM) + h*HDm + d];
    }
    __syncthreads();

    // scores (no 1/sqrt(d) scaling in reference)
    for (int j = tid; j < SEQ; j += 128){
        const float* kp = qkv + ((size_t)(b*SEQ + j))*(3*DIM) + DIM + h*HDm;
        float dot[QT] = {0.f,0.f,0.f,0.f};
        #pragma unroll
        for (int dd = 0; dd < HDm; dd += 4){
            float4 kv = *(const float4*)(kp + dd);
            #pragma unroll
            for (int q = 0; q < QT; q++){
                float4 qv = *(const float4*)(&qs[q][dd]);
                dot[q] += qv.x*kv.x + qv.y*kv.y + qv.z*kv.z + qv.w*kv.w;
            }
        }
        #pragma unroll
        for (int q = 0; q < QT; q++) sc[q][j] = dot[q];
    }
    __syncthreads();

    // softmax per query row
    for (int q = 0; q < QT; q++){
        float pm = -INFINITY;
        for (int j = tid; j < SEQ; j += 128) pm = fmaxf(pm, sc[q][j]);
        pm = warpMax(pm);
        if ((tid & 31) == 0) red[tid >> 5] = pm;
        __syncthreads();
        if (tid == 0) mden[q] = fmaxf(fmaxf(red[0], red[1]), fmaxf(red[2], red[3]));
        __syncthreads();
        float m = mden[q];
        float ps = 0.f;
        for (int j = tid; j < SEQ; j += 128){
            float e = __expf(sc[q][j] - m);
            sc[q][j] = e;
            ps += e;
        }
        ps = warpSum(ps);
        if ((tid & 31) == 0) red[tid >> 5] = ps;
        __syncthreads();
        if (tid == 0) mden[QT + q] = red[0] + red[1] + red[2] + red[3];
        __syncthreads();
    }

    // output: o[q][d] = sum_j p[q][j] * v[j][d]
    int jg = tid >> 2, dg = tid & 3;
    float acc[QT][16];
    #pragma unroll
    for (int q = 0; q < QT; q++)
        #pragma unroll
        for (int i = 0; i < 16; i++) acc[q][i] = 0.f;

    int jbase = jg * (SEQ/32);   // 64 keys per group
    for (int jj = 0; jj < SEQ/32; jj++){
        int j = jbase + jj;
        const float* vp = qkv + ((size_t)(b*SEQ + j))*(3*DIM) + 2*DIM + h*HDm + dg*16;
        float4 v0 = *(const float4*)(vp + 0);
        float4 v1 = *(const float4*)(vp + 4);
        float4 v2 = *(const float4*)(vp + 8);
        float4 v3 = *(const float4*)(vp + 12);
        #pragma unroll
        for (int q = 0; q < QT; q++){
            float p = sc[q][j];
            acc[q][0]  += p*v0.x; acc[q][1]  += p*v0.y; acc[q][2]  += p*v0.z; acc[q][3]  += p*v0.w;
            acc[q][4]  += p*v1.x; acc[q][5]  += p*v1.y; acc[q][6]  += p*v1.z; acc[q][7]  += p*v1.w;
            acc[q][8]  += p*v2.x; acc[q][9]  += p*v2.y; acc[q][10] += p*v2.z; acc[q][11] += p*v2.w;
            acc[q][12] += p*v3.x; acc[q][13] += p*v3.y; acc[q][14] += p*v3.z; acc[q][15] += p*v3.w;
        }
    }
    for (int q = 0; q < QT; q++){
        __syncthreads();
        #pragma unroll
        for (int i = 0; i < 16; i++) opart[jg][dg*16 + i] = acc[q][i];
        __syncthreads();
        if (tid < HDm){
            float s = 0.f;
            #pragma unroll
            for (int g = 0; g < 32; g++) s += opart[g][tid];
            O[((size_t)(b*SEQ) + i0 + q)*DIM + h*HDm + tid] = s / mden[QT + q];
        }
    }
}

// ---------------- gated GELU ----------------
__global__ void glu_kernel(const float* __restrict__ Hh, float* __restrict__ Hg){
    size_t i = (size_t)blockIdx.x * 256 + threadIdx.x;
    size_t m = i / FFm, f = i % FFm;
    float hx = Hh[m*(2*FFm) + f];
    float g  = Hh[m*(2*FFm) + FFm + f];
    float ge = 0.5f * g * (1.f + erff(g * 0.70710678118654752f));
    Hg[i] = hx * ge;
}

// ---------------- launch ----------------
extern "C" void kernel_launch(void* const* d_in, const int* in_sizes, int n_in,
                              void* d_out, int out_size){
    const float* x       = (const float*)d_in[0];
    const float* theta   = (const float*)d_in[1];
    const float* fmaps   = (const float*)d_in[2];
    const float* coords  = (const float*)d_in[3];
    const float* w_corr  = (const float*)d_in[4];
    const float* norm1   = (const float*)d_in[5];
    const float* sq      = (const float*)d_in[6];
    const float* sk      = (const float*)d_in[7];
    const float* w_qkv   = (const float*)d_in[8];
    const float* w_out   = (const float*)d_in[9];
    const float* norm2   = (const float*)d_in[10];
    const float* w_ff1   = (const float*)d_in[11];
    const float* b_ff1   = (const float*)d_in[12];
    const float* w_ff2   = (const float*)d_in[13];
    float* out = (float*)d_out;

    float *p_feats, *p_x, *p_xn, *p_qkv, *p_o, *p_x2, *p_xn2, *p_h, *p_hg;
    cudaGetSymbolAddress((void**)&p_feats, g_feats);
    cudaGetSymbolAddress((void**)&p_x,     g_x);
    cudaGetSymbolAddress((void**)&p_xn,    g_xn);
    cudaGetSymbolAddress((void**)&p_qkv,   g_qkv);
    cudaGetSymbolAddress((void**)&p_o,     g_o);
    cudaGetSymbolAddress((void**)&p_x2,    g_x2);
    cudaGetSymbolAddress((void**)&p_xn2,   g_xn2);
    cudaGetSymbolAddress((void**)&p_h,     g_h);
    cudaGetSymbolAddress((void**)&p_hg,    g_hg);

    const int M = Bsz * SEQ;   // 8192

    // 1. bilinear features
    bilinear_kernel<<<M, C2m>>>(fmaps, coords);
    // 2. x = x_in + feats @ w_corr^T
    gemm_kernel<<<dim3(DIM/64, M/64), 256>>>(p_feats, w_corr, nullptr, x, p_x, M, DIM, C2m);
    // 3. xn = rmsnorm(x, norm1)
    rmsnorm_kernel<<<M, 128>>>(p_x, norm1, p_xn);
    // 4. qkv = xn @ w_qkv^T
    gemm_kernel<<<dim3(3*DIM/64, M/64), 256>>>(p_xn, w_qkv, nullptr, nullptr, p_qkv, M, 3*DIM, DIM);
    // 5. per-head rmsnorm + rotary on q,k
    qkprep_kernel<<<M*NH*2, 32>>>(p_qkv, theta, sq, sk);
    // 6. attention -> o  (layout [b,n,h,hd] == [b,n,D])
    attn_kernel<<<Bsz*NH*(SEQ/QT), 128>>>(p_qkv, p_o);
    // 7. x2 = x + o @ w_out^T
    gemm_kernel<<<dim3(DIM/64, M/64), 256>>>(p_o, w_out, nullptr, p_x, p_x2, M, DIM, DIM);
    // 8. xn2 = rmsnorm(x2, norm2)
    rmsnorm_kernel<<<M, 128>>>(p_x2, norm2, p_xn2);
    // 9. h = xn2 @ w_ff1^T + b_ff1
    gemm_kernel<<<dim3(2*FFm/64, M/64), 256>>>(p_xn2, w_ff1, b_ff1, nullptr, p_h, M, 2*FFm, DIM);
    // 10. hg = hx * gelu(gate)
    glu_kernel<<<(Bsz*SEQ*FFm)/256, 256>>>(p_h, p_hg);
    // 11. out = x2 + hg @ w_ff2^T
    gemm_kernel<<<dim3(DIM/64, M/64), 256>>>(p_hg, w_ff2, nullptr, p_x2, out, M, DIM, FFm);
}

// round 3
// speedup vs baseline: 1.7455x; 1.7455x over previous
#include <cuda_runtime.h>
#include <math.h>

#define Bsz 4
#define SEQ 2048
#define DIM 512
#define NH  8
#define HDm 64
#define FFm 1024
#define C2m 128
#define HFm 64
#define WFm 64
#define EPSf 1e-6f

// ---------------- static scratch (no allocation allowed) ----------------
__device__ float g_feats[Bsz*SEQ*C2m];
__device__ float g_x   [Bsz*SEQ*DIM];
__device__ float g_xn  [Bsz*SEQ*DIM];
__device__ float g_qkv [Bsz*SEQ*3*DIM];
__device__ float g_o   [Bsz*SEQ*DIM];
__device__ float g_x2  [Bsz*SEQ*DIM];
__device__ float g_xn2 [Bsz*SEQ*DIM];
__device__ float g_h   [Bsz*SEQ*2*FFm];
__device__ float g_hg  [Bsz*SEQ*FFm];

__device__ __forceinline__ float warpSum(float v){
    #pragma unroll
    for (int o = 16; o > 0; o >>= 1) v += __shfl_xor_sync(0xFFFFFFFFu, v, o);
    return v;
}
__device__ __forceinline__ float warpMax(float v){
    #pragma unroll
    for (int o = 16; o > 0; o >>= 1) v = fmaxf(v, __shfl_xor_sync(0xFFFFFFFFu, v, o));
    return v;
}

// ---------------- bilinear sample ----------------
__global__ void bilinear_kernel(const float* __restrict__ fmaps,
                                const float* __restrict__ coords){
    int bn = blockIdx.x;
    int b  = bn / SEQ;
    int c  = threadIdx.x;
    float xc = coords[(size_t)bn*2 + 0];
    float yc = coords[(size_t)bn*2 + 1];
    xc = fminf(fmaxf(xc, 0.f), (float)(WFm-1));
    yc = fminf(fmaxf(yc, 0.f), (float)(HFm-1));
    float x0 = floorf(xc), y0 = floorf(yc);
    float wx = xc - x0,    wy = yc - y0;
    int x0i = (int)x0, y0i = (int)y0;
    int x1i = min(x0i+1, WFm-1), y1i = min(y0i+1, HFm-1);
    const float* img = fmaps + ((size_t)(b*C2m + c))*HFm*WFm;
    float f00 = img[y0i*WFm + x0i];
    float f01 = img[y0i*WFm + x1i];
    float f10 = img[y1i*WFm + x0i];
    float f11 = img[y1i*WFm + x1i];
    float top = f00*(1.f-wx) + f01*wx;
    float bot = f10*(1.f-wx) + f11*wx;
    g_feats[(size_t)bn*C2m + c] = top*(1.f-wy) + bot*wy;
}

// ---------------- GEMM: C[M,Nout] = A[M,K] @ W[Nout,K]^T (+bias)(+resid) ----------------
// 128x128 tile, 16-wide K panel, 256 threads, 8x8 microtile.
__global__ __launch_bounds__(256)
void gemm_kernel(const float* __restrict__ A, const float* __restrict__ W,
                 const float* __restrict__ bias, const float* __restrict__ resid,
                 float* __restrict__ C, int M, int Nout, int K){
    __shared__ float As[16][128];
    __shared__ float Bs[16][128];
    int tid = threadIdx.x;
    int m0 = blockIdx.y * 128, n0 = blockIdx.x * 128;
    int lrow = tid >> 1;            // 0..127
    int lcol = (tid & 1) * 8;       // 0 or 8
    const float* Ap = A + (size_t)(m0 + lrow) * K + lcol;
    const float* Wp = W + (size_t)(n0 + lrow) * K + lcol;
    int tx = tid & 15, ty = tid >> 4;   // n-group 0..15, m-group 0..15
    float acc[8][8] = {};
    for (int k0 = 0; k0 < K; k0 += 16){
        float4 a0 = *(const float4*)(Ap + k0);
        float4 a1 = *(const float4*)(Ap + k0 + 4);
        float4 b0 = *(const float4*)(Wp + k0);
        float4 b1 = *(const float4*)(Wp + k0 + 4);
        __syncthreads();
        As[lcol+0][lrow]=a0.x; As[lcol+1][lrow]=a0.y; As[lcol+2][lrow]=a0.z; As[lcol+3][lrow]=a0.w;
        As[lcol+4][lrow]=a1.x; As[lcol+5][lrow]=a1.y; As[lcol+6][lrow]=a1.z; As[lcol+7][lrow]=a1.w;
        Bs[lcol+0][lrow]=b0.x; Bs[lcol+1][lrow]=b0.y; Bs[lcol+2][lrow]=b0.z; Bs[lcol+3][lrow]=b0.w;
        Bs[lcol+4][lrow]=b1.x; Bs[lcol+5][lrow]=b1.y; Bs[lcol+6][lrow]=b1.z; Bs[lcol+7][lrow]=b1.w;
        __syncthreads();
        #pragma unroll
        for (int k = 0; k < 16; k++){
            float a[8], b[8];
            *(float4*)(a)   = *(const float4*)(&As[k][ty*8]);
            *(float4*)(a+4) = *(const float4*)(&As[k][ty*8+4]);
            *(float4*)(b)   = *(const float4*)(&Bs[k][tx*8]);
            *(float4*)(b+4) = *(const float4*)(&Bs[k][tx*8+4]);
            #pragma unroll
            for (int i = 0; i < 8; i++)
                #pragma unroll
                for (int j = 0; j < 8; j++)
                    acc[i][j] += a[i]*b[j];
        }
    }
    #pragma unroll
    for (int i = 0; i < 8; i++){
        int m = m0 + ty*8 + i;
        size_t off = (size_t)m * Nout + n0 + tx*8;
        float4 r0 = make_float4(acc[i][0], acc[i][1], acc[i][2], acc[i][3]);
        float4 r1 = make_float4(acc[i][4], acc[i][5], acc[i][6], acc[i][7]);
        if (bias){
            float4 bb0 = *(const float4*)(bias + n0 + tx*8);
            float4 bb1 = *(const float4*)(bias + n0 + tx*8 + 4);
            r0.x += bb0.x; r0.y += bb0.y; r0.z += bb0.z; r0.w += bb0.w;
            r1.x += bb1.x; r1.y += bb1.y; r1.z += bb1.z; r1.w += bb1.w;
        }
        if (resid){
            float4 rr0 = *(const float4*)(resid + off);
            float4 rr1 = *(const float4*)(resid + off + 4);
            r0.x += rr0.x; r0.y += rr0.y; r0.z += rr0.z; r0.w += rr0.w;
            r1.x += rr1.x; r1.y += rr1.y; r1.z += rr1.z; r1.w += rr1.w;
        }
        *(float4*)(C + off)     = r0;
        *(float4*)(C + off + 4) = r1;
    }
}

// ---------------- RMSNorm over DIM=512 ----------------
__global__ void rmsnorm_kernel(const float* __restrict__ X,
                               const float* __restrict__ scale,
                               float* __restrict__ Y){
    int row = blockIdx.x;
    int t   = threadIdx.x;  // 128
    const float4* x4 = (const float4*)(X + (size_t)row*DIM);
    float4 v = x4[t];
    float ss = v.x*v.x + v.y*v.y + v.z*v.z + v.w*v.w;
    ss = warpSum(ss);
    __shared__ float red[4];
    if ((t & 31) == 0) red[t >> 5] = ss;
    __syncthreads();
    if (t == 0) red[0] = red[0] + red[1] + red[2] + red[3];
    __syncthreads();
    float inv = rsqrtf(red[0] / (float)DIM + EPSf);
    float4 s = ((const float4*)scale)[t];
    float4 o;
    o.x = v.x * s.x * inv; o.y = v.y * s.y * inv;
    o.z = v.z * s.z * inv; o.w = v.w * s.w * inv;
    ((float4*)(Y + (size_t)row*DIM))[t] = o;
}

// ---------------- per-head RMSNorm + rotary on q,k (in-place) ----------------
__global__ void qkprep_kernel(float* __restrict__ qkv, const float* __restrict__ theta,
                              const float* __restrict__ sq, const float* __restrict__ sk){
    int t = blockIdx.x;
    int isK = t & 1; int rest = t >> 1;
    int h = rest % NH; rest /= NH;
    int n = rest % SEQ; int b = rest / SEQ;
    int lane = threadIdx.x;  // 32
    float* p = qkv + ((size_t)(b*SEQ + n))*(3*DIM) + isK*DIM + h*HDm;
    float v0 = p[lane], v1 = p[lane + 32];
    float ss = warpSum(v0*v0 + v1*v1);
    float inv = rsqrtf(ss / (float)HDm + EPSf);
    const float* sc = isK ? sk : sq;
    v0 = v0 * sc[lane]      * inv;
    v1 = v1 * sc[lane + 32] * inv;
    float th = theta[(((size_t)(b*NH + h))*SEQ + n)*(HDm/2) + lane];
    float cs = cosf(th), sn = sinf(th);
    float y0 = v0*cs - v1*sn;
    float y1 = v1*cs + v0*sn;
    p[lane]      = y0;
    p[lane + 32] = y1;
}

// ---------------- attention: 16 queries/block, 256 threads, dynamic smem ----------------
#define QT 16
// dynamic smem layout (floats):
//   sc   : [QT][SEQ]        = 32768
//   qs   : [QT][HDm]        =  1024
//   opart: [2][32][HDm]     =  4096   (2 queries reduced at a time)
#define SC_OFF 0
#define QS_OFF (QT*SEQ)
#define OP_OFF (QT*SEQ + QT*HDm)
#define ATTN_SMEM_BYTES ((QT*SEQ + QT*HDm + 2*32*HDm)*4)

__global__ __launch_bounds__(256)
void attn_kernel(const float* __restrict__ qkv, float* __restrict__ O){
    extern __shared__ float sm[];
    float* sc = sm + SC_OFF;
    float* qs = sm + QS_OFF;
    float* op = sm + OP_OFF;
    __shared__ float mden[QT];

    int blk = blockIdx.x;
    int nq = SEQ / QT;
    int qt = blk % nq; int rest = blk / nq;
    int h = rest % NH; int b = rest / NH;
    int i0 = qt * QT;
    int tid = threadIdx.x;

    // load Q tile
    for (int idx = tid; idx < QT*HDm; idx += 256){
        int qi = idx >> 6, d = idx & 63;
        qs[qi*HDm + d] = qkv[((size_t)(b*SEQ + i0 + qi))*(3*DIM) + h*HDm + d];
    }
    __syncthreads();

    // scores: each thread owns 8 keys (stride 256). No 1/sqrt(d) scaling in reference.
    for (int j = tid; j < SEQ; j += 256){
        const float* kp = qkv + ((size_t)(b*SEQ + j))*(3*DIM) + DIM + h*HDm;
        float dot[QT];
        #pragma unroll
        for (int q = 0; q < QT; q++) dot[q] = 0.f;
        #pragma unroll
        for (int dd = 0; dd < HDm; dd += 4){
            float4 kv = *(const float4*)(kp + dd);
            #pragma unroll
            for (int q = 0; q < QT; q++){
                float4 qv = *(const float4*)(&qs[q*HDm + dd]);
                dot[q] += qv.x*kv.x + qv.y*kv.y + qv.z*kv.z + qv.w*kv.w;
            }
        }
        #pragma unroll
        for (int q = 0; q < QT; q++) sc[q*SEQ + j] = dot[q];
    }
    __syncthreads();

    // softmax: warp w handles rows 2w, 2w+1 (no block syncs inside)
    {
        int w = tid >> 5, lane = tid & 31;
        #pragma unroll
        for (int qq = 0; qq < 2; qq++){
            int q = w*2 + qq;
            float* row = sc + q*SEQ;
            float pm = -INFINITY;
            for (int j = lane; j < SEQ; j += 32) pm = fmaxf(pm, row[j]);
            pm = warpMax(pm);
            float ps = 0.f;
            for (int j = lane; j < SEQ; j += 32){
                float e = __expf(row[j] - pm);
                row[j] = e;
                ps += e;
            }
            ps = warpSum(ps);
            if (lane == 0) mden[q] = ps;
        }
    }
    __syncthreads();

    // output: jg = tid>>3 (32 groups, j = jg + 32*jj interleaved), dg = tid&7 (8 dims)
    int jg = tid >> 3, dg = tid & 7;
    float acc[QT][8];
    #pragma unroll
    for (int q = 0; q < QT; q++)
        #pragma unroll
        for (int i = 0; i < 8; i++) acc[q][i] = 0.f;

    for (int jj = 0; jj < SEQ/32; jj++){
        int j = jg + 32*jj;
        const float* vp = qkv + ((size_t)(b*SEQ + j))*(3*DIM) + 2*DIM + h*HDm + dg*8;
        float4 v0 = *(const float4*)(vp + 0);
        float4 v1 = *(const float4*)(vp + 4);
        #pragma unroll
        for (int q = 0; q < QT; q++){
            float p = sc[q*SEQ + j];
            acc[q][0] += p*v0.x; acc[q][1] += p*v0.y; acc[q][2] += p*v0.z; acc[q][3] += p*v0.w;
            acc[q][4] += p*v1.x; acc[q][5] += p*v1.y; acc[q][6] += p*v1.z; acc[q][7] += p*v1.w;
        }
    }

    // reduce across the 32 j-groups, 2 queries at a time
    for (int qc = 0; qc < QT; qc += 2){
        __syncthreads();
        #pragma unroll
        for (int s = 0; s < 2; s++){
            float* dst = op + s*32*HDm + jg*HDm + dg*8;
            #pragma unroll
            for (int i = 0; i < 8; i++) dst[i] = acc[qc+s][i];
        }
        __syncthreads();
        if (tid < 128){
            int s = tid >> 6;       // which of the 2 queries
            int d = tid & 63;
            const float* src = op + s*32*HDm;
            float sum = 0.f;
            #pragma unroll
            for (int g = 0; g < 32; g++) sum += src[g*HDm + d];
            int q = qc + s;
            O[((size_t)(b*SEQ) + i0 + q)*DIM + h*HDm + d] = sum / mden[q];
        }
    }
}

// ---------------- gated GELU ----------------
__global__ void glu_kernel(const float* __restrict__ Hh, float* __restrict__ Hg){
    size_t i = (size_t)blockIdx.x * 256 + threadIdx.x;
    size_t m = i / FFm, f = i % FFm;
    float hx = Hh[m*(2*FFm) + f];
    float g  = Hh[m*(2*FFm) + FFm + f];
    float ge = 0.5f * g * (1.f + erff(g * 0.70710678118654752f));
    Hg[i] = hx * ge;
}

// ---------------- launch ----------------
extern "C" void kernel_launch(void* const* d_in, const int* in_sizes, int n_in,
                              void* d_out, int out_size){
    const float* x       = (const float*)d_in[0];
    const float* theta   = (const float*)d_in[1];
    const float* fmaps   = (const float*)d_in[2];
    const float* coords  = (const float*)d_in[3];
    const float* w_corr  = (const float*)d_in[4];
    const float* norm1   = (const float*)d_in[5];
    const float* sq      = (const float*)d_in[6];
    const float* sk      = (const float*)d_in[7];
    const float* w_qkv   = (const float*)d_in[8];
    const float* w_out   = (const float*)d_in[9];
    const float* norm2   = (const float*)d_in[10];
    const float* w_ff1   = (const float*)d_in[11];
    const float* b_ff1   = (const float*)d_in[12];
    const float* w_ff2   = (const float*)d_in[13];
    float* out = (float*)d_out;

    float *p_feats, *p_x, *p_xn, *p_qkv, *p_o, *p_x2, *p_xn2, *p_h, *p_hg;
    cudaGetSymbolAddress((void**)&p_feats, g_feats);
    cudaGetSymbolAddress((void**)&p_x,     g_x);
    cudaGetSymbolAddress((void**)&p_xn,    g_xn);
    cudaGetSymbolAddress((void**)&p_qkv,   g_qkv);
    cudaGetSymbolAddress((void**)&p_o,     g_o);
    cudaGetSymbolAddress((void**)&p_x2,    g_x2);
    cudaGetSymbolAddress((void**)&p_xn2,   g_xn2);
    cudaGetSymbolAddress((void**)&p_h,     g_h);
    cudaGetSymbolAddress((void**)&p_hg,    g_hg);

    static bool attn_cfg = false;
    if (!attn_cfg){
        cudaFuncSetAttribute(attn_kernel, cudaFuncAttributeMaxDynamicSharedMemorySize,
                             ATTN_SMEM_BYTES);
        attn_cfg = true;
    }

    const int M = Bsz * SEQ;   // 8192

    bilinear_kernel<<<M, C2m>>>(fmaps, coords);
    gemm_kernel<<<dim3(DIM/128, M/128), 256>>>(p_feats, w_corr, nullptr, x, p_x, M, DIM, C2m);
    rmsnorm_kernel<<<M, 128>>>(p_x, norm1, p_xn);
    gemm_kernel<<<dim3(3*DIM/128, M/128), 256>>>(p_xn, w_qkv, nullptr, nullptr, p_qkv, M, 3*DIM, DIM);
    qkprep_kernel<<<M*NH*2, 32>>>(p_qkv, theta, sq, sk);
    attn_kernel<<<Bsz*NH*(SEQ/QT), 256, ATTN_SMEM_BYTES>>>(p_qkv, p_o);
    gemm_kernel<<<dim3(DIM/128, M/128), 256>>>(p_o, w_out, nullptr, p_x, p_x2, M, DIM, DIM);
    rmsnorm_kernel<<<M, 128>>>(p_x2, norm2, p_xn2);
    gemm_kernel<<<dim3(2*FFm/128, M/128), 256>>>(p_xn2, w_ff1, b_ff1, nullptr, p_h, M, 2*FFm, DIM);
    glu_kernel<<<(Bsz*SEQ*FFm)/256, 256>>>(p_h, p_hg);
    gemm_kernel<<<dim3(DIM/128, M/128), 256>>>(p_hg, w_ff2, nullptr, p_x2, out, M, DIM, FFm);
}

// round 5
// speedup vs baseline: 2.2442x; 1.2857x over previous
#include <cuda_runtime.h>
#include <math.h>
#include <stdint.h>

#define Bsz 4
#define SEQ 2048
#define DIM 512
#define NH  8
#define HDm 64
#define FFm 1024
#define C2m 128
#define HFm 64
#define WFm 64
#define EPSf 1e-6f

// ---------------- static scratch ----------------
__device__ float g_feats[Bsz*SEQ*C2m];
__device__ float g_x   [Bsz*SEQ*DIM];
__device__ float g_xn  [Bsz*SEQ*DIM];
__device__ float g_qkv [Bsz*SEQ*3*DIM];
__device__ float g_o   [Bsz*SEQ*DIM];
__device__ float g_x2  [Bsz*SEQ*DIM];
__device__ float g_xn2 [Bsz*SEQ*DIM];
__device__ float g_h   [Bsz*SEQ*2*FFm];
__device__ float g_hg  [Bsz*SEQ*FFm];

__device__ __forceinline__ float warpSum(float v){
    #pragma unroll
    for (int o = 16; o > 0; o >>= 1) v += __shfl_xor_sync(0xFFFFFFFFu, v, o);
    return v;
}
__device__ __forceinline__ float warpMax(float v){
    #pragma unroll
    for (int o = 16; o > 0; o >>= 1) v = fmaxf(v, __shfl_xor_sync(0xFFFFFFFFu, v, o));
    return v;
}
__device__ __forceinline__ uint32_t f2tf32(float f){
    uint32_t u;
    asm("cvt.rna.tf32.f32 %0, %1;" : "=r"(u) : "f"(f));
    return u;
}
__device__ __forceinline__ void mma_tf32(float* c, const uint32_t* a, uint32_t b0, uint32_t b1){
    asm volatile(
        "mma.sync.aligned.m16n8k8.row.col.f32.tf32.tf32.f32 "
        "{%0,%1,%2,%3}, {%4,%5,%6,%7}, {%8,%9}, {%0,%1,%2,%3};"
        : "+f"(c[0]), "+f"(c[1]), "+f"(c[2]), "+f"(c[3])
        : "r"(a[0]), "r"(a[1]), "r"(a[2]), "r"(a[3]), "r"(b0), "r"(b1));
}

// ---------------- bilinear ----------------
__global__ void bilinear_kernel(const float* __restrict__ fmaps,
                                const float* __restrict__ coords){
    int bn = blockIdx.x;
    int b  = bn / SEQ;
    int c  = threadIdx.x;
    float xc = coords[(size_t)bn*2 + 0];
    float yc = coords[(size_t)bn*2 + 1];
    xc = fminf(fmaxf(xc, 0.f), (float)(WFm-1));
    yc = fminf(fmaxf(yc, 0.f), (float)(HFm-1));
    float x0 = floorf(xc), y0 = floorf(yc);
    float wx = xc - x0,    wy = yc - y0;
    int x0i = (int)x0, y0i = (int)y0;
    int x1i = min(x0i+1, WFm-1), y1i = min(y0i+1, HFm-1);
    const float* img = fmaps + ((size_t)(b*C2m + c))*HFm*WFm;
    float f00 = img[y0i*WFm + x0i];
    float f01 = img[y0i*WFm + x1i];
    float f10 = img[y1i*WFm + x0i];
    float f11 = img[y1i*WFm + x1i];
    float top = f00*(1.f-wx) + f01*wx;
    float bot = f10*(1.f-wx) + f11*wx;
    g_feats[(size_t)bn*C2m + c] = top*(1.f-wy) + bot*wy;
}

// ---------------- tf32 mma.sync GEMM: C[M,Nout] = A @ W^T (+bias)(+resid) ----------------
// 128x128 tile, BK=32, 256 threads = 8 warps (4 m x 2 n), warp tile 32x64.
#define BK 32
#define GPAD 36
#define GBUF (128*GPAD)              // floats per operand buffer
#define GEMM_SMEM (4*GBUF*4)         // 2 buffers * (A+B) * 4B = 73728

__global__ __launch_bounds__(256)
void gemm_mma(const float* __restrict__ A, const float* __restrict__ W,
              const float* __restrict__ bias, const float* __restrict__ resid,
              float* __restrict__ C, int M, int Nout, int K){
    extern __shared__ float sm[];
    // buffer b: A at sm + b*2*GBUF, B at sm + b*2*GBUF + GBUF
    int tid = threadIdx.x;
    int wid = tid >> 5, lane = tid & 31;
    int qr = lane >> 2, qc = lane & 3;   // quad row / col
    int warp_m = wid & 3, warp_n = wid >> 2;
    int m0 = blockIdx.y * 128, n0 = blockIdx.x * 128;

    const float* Abase = A + (size_t)m0 * K;
    const float* Wbase = W + (size_t)n0 * K;

    // LDG staging: 4 float4 for A, 4 for B
    float4 ra[4], rb[4];
    int ldr = tid >> 1;              // 0..127 (row)
    int ldc = (tid & 1) * 16;        // 0 or 16 (col, floats)

    // prologue: load tile 0
    #pragma unroll
    for (int i = 0; i < 4; i++){
        ra[i] = *(const float4*)(Abase + (size_t)ldr*K + ldc + i*4);
        rb[i] = *(const float4*)(Wbase + (size_t)ldr*K + ldc + i*4);
    }
    {
        uint32_t* As = (uint32_t*)(sm);
        uint32_t* Bs = (uint32_t*)(sm + GBUF);
        #pragma unroll
        for (int i = 0; i < 4; i++){
            int c = ldc + i*4;
            As[ldr*GPAD + c + 0] = f2tf32(ra[i].x);
            As[ldr*GPAD + c + 1] = f2tf32(ra[i].y);
            As[ldr*GPAD + c + 2] = f2tf32(ra[i].z);
            As[ldr*GPAD + c + 3] = f2tf32(ra[i].w);
            Bs[ldr*GPAD + c + 0] = f2tf32(rb[i].x);
            Bs[ldr*GPAD + c + 1] = f2tf32(rb[i].y);
            Bs[ldr*GPAD + c + 2] = f2tf32(rb[i].z);
            Bs[ldr*GPAD + c + 3] = f2tf32(rb[i].w);
        }
    }
    __syncthreads();

    float acc[2][8][4];
    #pragma unroll
    for (int mt = 0; mt < 2; mt++)
        #pragma unroll
        for (int nt = 0; nt < 8; nt++)
            #pragma unroll
            for (int i = 0; i < 4; i++) acc[mt][nt][i] = 0.f;

    int T = K / BK;
    for (int t = 0; t < T; t++){
        int buf = t & 1;
        // prefetch next tile from global
        if (t + 1 < T){
            int k0 = (t+1) * BK;
            #pragma unroll
            for (int i = 0; i < 4; i++){
                ra[i] = *(const float4*)(Abase + (size_t)ldr*K + k0 + ldc + i*4);
                rb[i] = *(const float4*)(Wbase + (size_t)ldr*K + k0 + ldc + i*4);
            }
        }
        // compute on current buffer
        const uint32_t* As = (const uint32_t*)(sm + buf*2*GBUF);
        const uint32_t* Bs = (const uint32_t*)(sm + buf*2*GBUF + GBUF);
        #pragma unroll
        for (int ks = 0; ks < 4; ks++){
            int k0 = ks * 8;
            uint32_t af[2][4];
            #pragma unroll
            for (int mt = 0; mt < 2; mt++){
                int rbse = warp_m*32 + mt*16;
                af[mt][0] = As[(rbse + qr     )*GPAD + k0 + qc    ];
                af[mt][1] = As[(rbse + 8 + qr )*GPAD + k0 + qc    ];
                af[mt][2] = As[(rbse + qr     )*GPAD + k0 + 4 + qc];
                af[mt][3] = As[(rbse + 8 + qr )*GPAD + k0 + 4 + qc];
            }
            #pragma unroll
            for (int nt = 0; nt < 8; nt++){
                int cbse = warp_n*64 + nt*8;
                uint32_t b0 = Bs[(cbse + qr)*GPAD + k0 + qc    ];
                uint32_t b1 = Bs[(cbse + qr)*GPAD + k0 + 4 + qc];
                mma_tf32(acc[0][nt], af[0], b0, b1);
                mma_tf32(acc[1][nt], af[1], b0, b1);
            }
        }
        __syncthreads();
        if (t + 1 < T){
            int nbuf = (t+1) & 1;
            uint32_t* Aw = (uint32_t*)(sm + nbuf*2*GBUF);
            uint32_t* Bw = (uint32_t*)(sm + nbuf*2*GBUF + GBUF);
            #pragma unroll
            for (int i = 0; i < 4; i++){
                int c = ldc + i*4;
                Aw[ldr*GPAD + c + 0] = f2tf32(ra[i].x);
                Aw[ldr*GPAD + c + 1] = f2tf32(ra[i].y);
                Aw[ldr*GPAD + c + 2] = f2tf32(ra[i].z);
                Aw[ldr*GPAD + c + 3] = f2tf32(ra[i].w);
                Bw[ldr*GPAD + c + 0] = f2tf32(rb[i].x);
                Bw[ldr*GPAD + c + 1] = f2tf32(rb[i].y);
                Bw[ldr*GPAD + c + 2] = f2tf32(rb[i].z);
                Bw[ldr*GPAD + c + 3] = f2tf32(rb[i].w);
            }
            __syncthreads();
        }
    }

    // epilogue: direct register stores (float2), fused bias/residual
    #pragma unroll
    for (int mt = 0; mt < 2; mt++){
        #pragma unroll
        for (int nt = 0; nt < 8; nt++){
            int row = m0 + warp_m*32 + mt*16 + qr;
            int col = n0 + warp_n*64 + nt*8 + qc*2;
            float2 v0 = make_float2(acc[mt][nt][0], acc[mt][nt][1]);
            float2 v1 = make_float2(acc[mt][nt][2], acc[mt][nt][3]);
            if (bias){
                float2 bb = *(const float2*)(bias + col);
                v0.x += bb.x; v0.y += bb.y;
                v1.x += bb.x; v1.y += bb.y;
            }
            size_t off0 = (size_t)row * Nout + col;
            size_t off1 = (size_t)(row + 8) * Nout + col;
            if (resid){
                float2 r0 = *(const float2*)(resid + off0);
                float2 r1 = *(const float2*)(resid + off1);
                v0.x += r0.x; v0.y += r0.y;
                v1.x += r1.x; v1.y += r1.y;
            }
            *(float2*)(C + off0) = v0;
            *(float2*)(C + off1) = v1;
        }
    }
}

// ---------------- RMSNorm over DIM=512 ----------------
__global__ void rmsnorm_kernel(const float* __restrict__ X,
                               const float* __restrict__ scale,
                               float* __restrict__ Y){
    int row = blockIdx.x;
    int t   = threadIdx.x;  // 128
    const float4* x4 = (const float4*)(X + (size_t)row*DIM);
    float4 v = x4[t];
    float ss = v.x*v.x + v.y*v.y + v.z*v.z + v.w*v.w;
    ss = warpSum(ss);
    __shared__ float red[4];
    if ((t & 31) == 0) red[t >> 5] = ss;
    __syncthreads();
    if (t == 0) red[0] = red[0] + red[1] + red[2] + red[3];
    __syncthreads();
    float inv = rsqrtf(red[0] / (float)DIM + EPSf);
    float4 s = ((const float4*)scale)[t];
    float4 o;
    o.x = v.x * s.x * inv; o.y = v.y * s.y * inv;
    o.z = v.z * s.z * inv; o.w = v.w * s.w * inv;
    ((float4*)(Y + (size_t)row*DIM))[t] = o;
}

// ---------------- per-head RMSNorm + rotary ----------------
__global__ void qkprep_kernel(float* __restrict__ qkv, const float* __restrict__ theta,
                              const float* __restrict__ sq, const float* __restrict__ sk){
    int t = blockIdx.x;
    int isK = t & 1; int rest = t >> 1;
    int h = rest % NH; rest /= NH;
    int n = rest % SEQ; int b = rest / SEQ;
    int lane = threadIdx.x;  // 32
    float* p = qkv + ((size_t)(b*SEQ + n))*(3*DIM) + isK*DIM + h*HDm;
    float v0 = p[lane], v1 = p[lane + 32];
    float ss = warpSum(v0*v0 + v1*v1);
    float inv = rsqrtf(ss / (float)HDm + EPSf);
    const float* sc = isK ? sk : sq;
    v0 = v0 * sc[lane]      * inv;
    v1 = v1 * sc[lane + 32] * inv;
    float th = theta[(((size_t)(b*NH + h))*SEQ + n)*(HDm/2) + lane];
    float cs = cosf(th), sn = sinf(th);
    float y0 = v0*cs - v1*sn;
    float y1 = v1*cs + v0*sn;
    p[lane]      = y0;
    p[lane + 32] = y1;
}

// ---------------- attention: 16 queries/block, 256 threads ----------------
#define QT 16
#define SC_OFF 0
#define QS_OFF (QT*SEQ)
#define OP_OFF (QT*SEQ + QT*HDm)
#define ATTN_SMEM_BYTES ((QT*SEQ + QT*HDm + 2*32*HDm)*4)

__global__ __launch_bounds__(256)
void attn_kernel(const float* __restrict__ qkv, float* __restrict__ O){
    extern __shared__ float sm[];
    float* sc = sm + SC_OFF;
    float* qs = sm + QS_OFF;
    float* op = sm + OP_OFF;
    __shared__ float mden[QT];

    int blk = blockIdx.x;
    int nq = SEQ / QT;
    int qt = blk % nq; int rest = blk / nq;
    int h = rest % NH; int b = rest / NH;
    int i0 = qt * QT;
    int tid = threadIdx.x;

    for (int idx = tid; idx < QT*HDm; idx += 256){
        int qi = idx >> 6, d = idx & 63;
        qs[qi*HDm + d] = qkv[((size_t)(b*SEQ + i0 + qi))*(3*DIM) + h*HDm + d];
    }
    __syncthreads();

    for (int j = tid; j < SEQ; j += 256){
        const float* kp = qkv + ((size_t)(b*SEQ + j))*(3*DIM) + DIM + h*HDm;
        float dot[QT];
        #pragma unroll
        for (int q = 0; q < QT; q++) dot[q] = 0.f;
        #pragma unroll
        for (int dd = 0; dd < HDm; dd += 4){
            float4 kv = *(const float4*)(kp + dd);
            #pragma unroll
            for (int q = 0; q < QT; q++){
                float4 qv = *(const float4*)(&qs[q*HDm + dd]);
                dot[q] += qv.x*kv.x + qv.y*kv.y + qv.z*kv.z + qv.w*kv.w;
            }
        }
        #pragma unroll
        for (int q = 0; q < QT; q++) sc[q*SEQ + j] = dot[q];
    }
    __syncthreads();

    {
        int w = tid >> 5, lane = tid & 31;
        #pragma unroll
        for (int qq = 0; qq < 2; qq++){
            int q = w*2 + qq;
            float* row = sc + q*SEQ;
            float pm = -INFINITY;
            for (int j = lane; j < SEQ; j += 32) pm = fmaxf(pm, row[j]);
            pm = warpMax(pm);
            float ps = 0.f;
            for (int j = lane; j < SEQ; j += 32){
                float e = __expf(row[j] - pm);
                row[j] = e;
                ps += e;
            }
            ps = warpSum(ps);
            if (lane == 0) mden[q] = ps;
        }
    }
    __syncthreads();

    int jg = tid >> 3, dg = tid & 7;
    float acc[QT][8];
    #pragma unroll
    for (int q = 0; q < QT; q++)
        #pragma unroll
        for (int i = 0; i < 8; i++) acc[q][i] = 0.f;

    for (int jj = 0; jj < SEQ/32; jj++){
        int j = jg + 32*jj;
        const float* vp = qkv + ((size_t)(b*SEQ + j))*(3*DIM) + 2*DIM + h*HDm + dg*8;
        float4 v0 = *(const float4*)(vp + 0);
        float4 v1 = *(const float4*)(vp + 4);
        #pragma unroll
        for (int q = 0; q < QT; q++){
            float p = sc[q*SEQ + j];
            acc[q][0] += p*v0.x; acc[q][1] += p*v0.y; acc[q][2] += p*v0.z; acc[q][3] += p*v0.w;
            acc[q][4] += p*v1.x; acc[q][5] += p*v1.y; acc[q][6] += p*v1.z; acc[q][7] += p*v1.w;
        }
    }

    for (int qc = 0; qc < QT; qc += 2){
        __syncthreads();
        #pragma unroll
        for (int s = 0; s < 2; s++){
            float* dst = op + s*32*HDm + jg*HDm + dg*8;
            #pragma unroll
            for (int i = 0; i < 8; i++) dst[i] = acc[qc+s][i];
        }
        __syncthreads();
        if (tid < 128){
            int s = tid >> 6;
            int d = tid & 63;
            const float* src = op + s*32*HDm;
            float sum = 0.f;
            #pragma unroll
            for (int g = 0; g < 32; g++) sum += src[g*HDm + d];
            int q = qc + s;
            O[((size_t)(b*SEQ) + i0 + q)*DIM + h*HDm + d] = sum / mden[q];
        }
    }
}

// ---------------- gated GELU ----------------
__global__ void glu_kernel(const float* __restrict__ Hh, float* __restrict__ Hg){
    size_t i = (size_t)blockIdx.x * 256 + threadIdx.x;
    size_t m = i / FFm, f = i % FFm;
    float hx = Hh[m*(2*FFm) + f];
    float g  = Hh[m*(2*FFm) + FFm + f];
    float ge = 0.5f * g * (1.f + erff(g * 0.70710678118654752f));
    Hg[i] = hx * ge;
}

// ---------------- launch ----------------
extern "C" void kernel_launch(void* const* d_in, const int* in_sizes, int n_in,
                              void* d_out, int out_size){
    const float* x       = (const float*)d_in[0];
    const float* theta   = (const float*)d_in[1];
    const float* fmaps   = (const float*)d_in[2];
    const float* coords  = (const float*)d_in[3];
    const float* w_corr  = (const float*)d_in[4];
    const float* norm1   = (const float*)d_in[5];
    const float* sq      = (const float*)d_in[6];
    const float* sk      = (const float*)d_in[7];
    const float* w_qkv   = (const float*)d_in[8];
    const float* w_out   = (const float*)d_in[9];
    const float* norm2   = (const float*)d_in[10];
    const float* w_ff1   = (const float*)d_in[11];
    const float* b_ff1   = (const float*)d_in[12];
    const float* w_ff2   = (const float*)d_in[13];
    float* out = (float*)d_out;

    float *p_feats, *p_x, *p_xn, *p_qkv, *p_o, *p_x2, *p_xn2, *p_h, *p_hg;
    cudaGetSymbolAddress((void**)&p_feats, g_feats);
    cudaGetSymbolAddress((void**)&p_x,     g_x);
    cudaGetSymbolAddress((void**)&p_xn,    g_xn);
    cudaGetSymbolAddress((void**)&p_qkv,   g_qkv);
    cudaGetSymbolAddress((void**)&p_o,     g_o);
    cudaGetSymbolAddress((void**)&p_x2,    g_x2);
    cudaGetSymbolAddress((void**)&p_xn2,   g_xn2);
    cudaGetSymbolAddress((void**)&p_h,     g_h);
    cudaGetSymbolAddress((void**)&p_hg,    g_hg);

    static bool cfg = false;
    if (!cfg){
        cudaFuncSetAttribute(attn_kernel, cudaFuncAttributeMaxDynamicSharedMemorySize,
                             ATTN_SMEM_BYTES);
        cudaFuncSetAttribute(gemm_mma, cudaFuncAttributeMaxDynamicSharedMemorySize,
                             GEMM_SMEM);
        cfg = true;
    }

    const int M = Bsz * SEQ;   // 8192

    bilinear_kernel<<<M, C2m>>>(fmaps, coords);
    gemm_mma<<<dim3(DIM/128, M/128), 256, GEMM_SMEM>>>(p_feats, w_corr, nullptr, x, p_x, M, DIM, C2m);
    rmsnorm_kernel<<<M, 128>>>(p_x, norm1, p_xn);
    gemm_mma<<<dim3(3*DIM/128, M/128), 256, GEMM_SMEM>>>(p_xn, w_qkv, nullptr, nullptr, p_qkv, M, 3*DIM, DIM);
    qkprep_kernel<<<M*NH*2, 32>>>(p_qkv, theta, sq, sk);
    attn_kernel<<<Bsz*NH*(SEQ/QT), 256, ATTN_SMEM_BYTES>>>(p_qkv, p_o);
    gemm_mma<<<dim3(DIM/128, M/128), 256, GEMM_SMEM>>>(p_o, w_out, nullptr, p_x, p_x2, M, DIM, DIM);
    rmsnorm_kernel<<<M, 128>>>(p_x2, norm2, p_xn2);
    gemm_mma<<<dim3(2*FFm/128, M/128), 256, GEMM_SMEM>>>(p_xn2, w_ff1, b_ff1, nullptr, p_h, M, 2*FFm, DIM);
    glu_kernel<<<(Bsz*SEQ*FFm)/256, 256>>>(p_h, p_hg);
    gemm_mma<<<dim3(DIM/128, M/128), 256, GEMM_SMEM>>>(p_hg, w_ff2, nullptr, p_x2, out, M, DIM, FFm);
}

// round 6
// speedup vs baseline: 5.0830x; 2.2649x over previous
#include <cuda_runtime.h>
#include <math.h>
#include <stdint.h>

#define Bsz 4
#define SEQ 2048
#define DIM 512
#define NH  8
#define HDm 64
#define FFm 1024
#define C2m 128
#define HFm 64
#define WFm 64
#define EPSf 1e-6f

// ---------------- static scratch ----------------
__device__ float g_feats[Bsz*SEQ*C2m];
__device__ float g_x   [Bsz*SEQ*DIM];
__device__ float g_xn  [Bsz*SEQ*DIM];
__device__ float g_qkv [Bsz*SEQ*3*DIM];
__device__ float g_o   [Bsz*SEQ*DIM];
__device__ float g_x2  [Bsz*SEQ*DIM];
__device__ float g_xn2 [Bsz*SEQ*DIM];
__device__ float g_h   [Bsz*SEQ*2*FFm];
__device__ float g_hg  [Bsz*SEQ*FFm];

__device__ __forceinline__ float warpSum(float v){
    #pragma unroll
    for (int o = 16; o > 0; o >>= 1) v += __shfl_xor_sync(0xFFFFFFFFu, v, o);
    return v;
}
__device__ __forceinline__ uint32_t f2tf32(float f){
    uint32_t u;
    asm("cvt.rna.tf32.f32 %0, %1;" : "=r"(u) : "f"(f));
    return u;
}
__device__ __forceinline__ void mma_tf32(float* c, const uint32_t* a, uint32_t b0, uint32_t b1){
    asm volatile(
        "mma.sync.aligned.m16n8k8.row.col.f32.tf32.tf32.f32 "
        "{%0,%1,%2,%3}, {%4,%5,%6,%7}, {%8,%9}, {%0,%1,%2,%3};"
        : "+f"(c[0]), "+f"(c[1]), "+f"(c[2]), "+f"(c[3])
        : "r"(a[0]), "r"(a[1]), "r"(a[2]), "r"(a[3]), "r"(b0), "r"(b1));
}

// ---------------- bilinear ----------------
__global__ void bilinear_kernel(const float* __restrict__ fmaps,
                                const float* __restrict__ coords){
    int bn = blockIdx.x;
    int b  = bn / SEQ;
    int c  = threadIdx.x;
    float xc = coords[(size_t)bn*2 + 0];
    float yc = coords[(size_t)bn*2 + 1];
    xc = fminf(fmaxf(xc, 0.f), (float)(WFm-1));
    yc = fminf(fmaxf(yc, 0.f), (float)(HFm-1));
    float x0 = floorf(xc), y0 = floorf(yc);
    float wx = xc - x0,    wy = yc - y0;
    int x0i = (int)x0, y0i = (int)y0;
    int x1i = min(x0i+1, WFm-1), y1i = min(y0i+1, HFm-1);
    const float* img = fmaps + ((size_t)(b*C2m + c))*HFm*WFm;
    float f00 = img[y0i*WFm + x0i];
    float f01 = img[y0i*WFm + x1i];
    float f10 = img[y1i*WFm + x0i];
    float f11 = img[y1i*WFm + x1i];
    float top = f00*(1.f-wx) + f01*wx;
    float bot = f10*(1.f-wx) + f11*wx;
    g_feats[(size_t)bn*C2m + c] = top*(1.f-wy) + bot*wy;
}

// ---------------- tf32 mma.sync GEMM (unchanged from R4) ----------------
#define BK 32
#define GPAD 36
#define GBUF (128*GPAD)
#define GEMM_SMEM (4*GBUF*4)

__global__ __launch_bounds__(256)
void gemm_mma(const float* __restrict__ A, const float* __restrict__ W,
              const float* __restrict__ bias, const float* __restrict__ resid,
              float* __restrict__ C, int M, int Nout, int K){
    extern __shared__ float sm[];
    int tid = threadIdx.x;
    int wid = tid >> 5, lane = tid & 31;
    int qr = lane >> 2, qc = lane & 3;
    int warp_m = wid & 3, warp_n = wid >> 2;
    int m0 = blockIdx.y * 128, n0 = blockIdx.x * 128;

    const float* Abase = A + (size_t)m0 * K;
    const float* Wbase = W + (size_t)n0 * K;

    float4 ra[4], rb[4];
    int ldr = tid >> 1;
    int ldc = (tid & 1) * 16;

    #pragma unroll
    for (int i = 0; i < 4; i++){
        ra[i] = *(const float4*)(Abase + (size_t)ldr*K + ldc + i*4);
        rb[i] = *(const float4*)(Wbase + (size_t)ldr*K + ldc + i*4);
    }
    {
        uint32_t* As = (uint32_t*)(sm);
        uint32_t* Bs = (uint32_t*)(sm + GBUF);
        #pragma unroll
        for (int i = 0; i < 4; i++){
            int c = ldc + i*4;
            As[ldr*GPAD + c + 0] = f2tf32(ra[i].x);
            As[ldr*GPAD + c + 1] = f2tf32(ra[i].y);
            As[ldr*GPAD + c + 2] = f2tf32(ra[i].z);
            As[ldr*GPAD + c + 3] = f2tf32(ra[i].w);
            Bs[ldr*GPAD + c + 0] = f2tf32(rb[i].x);
            Bs[ldr*GPAD + c + 1] = f2tf32(rb[i].y);
            Bs[ldr*GPAD + c + 2] = f2tf32(rb[i].z);
            Bs[ldr*GPAD + c + 3] = f2tf32(rb[i].w);
        }
    }
    __syncthreads();

    float acc[2][8][4];
    #pragma unroll
    for (int mt = 0; mt < 2; mt++)
        #pragma unroll
        for (int nt = 0; nt < 8; nt++)
            #pragma unroll
            for (int i = 0; i < 4; i++) acc[mt][nt][i] = 0.f;

    int T = K / BK;
    for (int t = 0; t < T; t++){
        int buf = t & 1;
        if (t + 1 < T){
            int k0 = (t+1) * BK;
            #pragma unroll
            for (int i = 0; i < 4; i++){
                ra[i] = *(const float4*)(Abase + (size_t)ldr*K + k0 + ldc + i*4);
                rb[i] = *(const float4*)(Wbase + (size_t)ldr*K + k0 + ldc + i*4);
            }
        }
        const uint32_t* As = (const uint32_t*)(sm + buf*2*GBUF);
        const uint32_t* Bs = (const uint32_t*)(sm + buf*2*GBUF + GBUF);
        #pragma unroll
        for (int ks = 0; ks < 4; ks++){
            int k0 = ks * 8;
            uint32_t af[2][4];
            #pragma unroll
            for (int mt = 0; mt < 2; mt++){
                int rbse = warp_m*32 + mt*16;
                af[mt][0] = As[(rbse + qr     )*GPAD + k0 + qc    ];
                af[mt][1] = As[(rbse + 8 + qr )*GPAD + k0 + qc    ];
                af[mt][2] = As[(rbse + qr     )*GPAD + k0 + 4 + qc];
                af[mt][3] = As[(rbse + 8 + qr )*GPAD + k0 + 4 + qc];
            }
            #pragma unroll
            for (int nt = 0; nt < 8; nt++){
                int cbse = warp_n*64 + nt*8;
                uint32_t b0 = Bs[(cbse + qr)*GPAD + k0 + qc    ];
                uint32_t b1 = Bs[(cbse + qr)*GPAD + k0 + 4 + qc];
                mma_tf32(acc[0][nt], af[0], b0, b1);
                mma_tf32(acc[1][nt], af[1], b0, b1);
            }
        }
        __syncthreads();
        if (t + 1 < T){
            int nbuf = (t+1) & 1;
            uint32_t* Aw = (uint32_t*)(sm + nbuf*2*GBUF);
            uint32_t* Bw = (uint32_t*)(sm + nbuf*2*GBUF + GBUF);
            #pragma unroll
            for (int i = 0; i < 4; i++){
                int c = ldc + i*4;
                Aw[ldr*GPAD + c + 0] = f2tf32(ra[i].x);
                Aw[ldr*GPAD + c + 1] = f2tf32(ra[i].y);
                Aw[ldr*GPAD + c + 2] = f2tf32(ra[i].z);
                Aw[ldr*GPAD + c + 3] = f2tf32(ra[i].w);
                Bw[ldr*GPAD + c + 0] = f2tf32(rb[i].x);
                Bw[ldr*GPAD + c + 1] = f2tf32(rb[i].y);
                Bw[ldr*GPAD + c + 2] = f2tf32(rb[i].z);
                Bw[ldr*GPAD + c + 3] = f2tf32(rb[i].w);
            }
            __syncthreads();
        }
    }

    #pragma unroll
    for (int mt = 0; mt < 2; mt++){
        #pragma unroll
        for (int nt = 0; nt < 8; nt++){
            int row = m0 + warp_m*32 + mt*16 + qr;
            int col = n0 + warp_n*64 + nt*8 + qc*2;
            float2 v0 = make_float2(acc[mt][nt][0], acc[mt][nt][1]);
            float2 v1 = make_float2(acc[mt][nt][2], acc[mt][nt][3]);
            if (bias){
                float2 bb = *(const float2*)(bias + col);
                v0.x += bb.x; v0.y += bb.y;
                v1.x += bb.x; v1.y += bb.y;
            }
            size_t off0 = (size_t)row * Nout + col;
            size_t off1 = (size_t)(row + 8) * Nout + col;
            if (resid){
                float2 r0 = *(const float2*)(resid + off0);
                float2 r1 = *(const float2*)(resid + off1);
                v0.x += r0.x; v0.y += r0.y;
                v1.x += r1.x; v1.y += r1.y;
            }
            *(float2*)(C + off0) = v0;
            *(float2*)(C + off1) = v1;
        }
    }
}

// ---------------- RMSNorm over DIM=512 ----------------
__global__ void rmsnorm_kernel(const float* __restrict__ X,
                               const float* __restrict__ scale,
                               float* __restrict__ Y){
    int row = blockIdx.x;
    int t   = threadIdx.x;  // 128
    const float4* x4 = (const float4*)(X + (size_t)row*DIM);
    float4 v = x4[t];
    float ss = v.x*v.x + v.y*v.y + v.z*v.z + v.w*v.w;
    ss = warpSum(ss);
    __shared__ float red[4];
    if ((t & 31) == 0) red[t >> 5] = ss;
    __syncthreads();
    if (t == 0) red[0] = red[0] + red[1] + red[2] + red[3];
    __syncthreads();
    float inv = rsqrtf(red[0] / (float)DIM + EPSf);
    float4 s = ((const float4*)scale)[t];
    float4 o;
    o.x = v.x * s.x * inv; o.y = v.y * s.y * inv;
    o.z = v.z * s.z * inv; o.w = v.w * s.w * inv;
    ((float4*)(Y + (size_t)row*DIM))[t] = o;
}

// ---------------- per-head RMSNorm + rotary ----------------
__global__ void qkprep_kernel(float* __restrict__ qkv, const float* __restrict__ theta,
                              const float* __restrict__ sq, const float* __restrict__ sk){
    int t = blockIdx.x;
    int isK = t & 1; int rest = t >> 1;
    int h = rest % NH; rest /= NH;
    int n = rest % SEQ; int b = rest / SEQ;
    int lane = threadIdx.x;  // 32
    float* p = qkv + ((size_t)(b*SEQ + n))*(3*DIM) + isK*DIM + h*HDm;
    float v0 = p[lane], v1 = p[lane + 32];
    float ss = warpSum(v0*v0 + v1*v1);
    float inv = rsqrtf(ss / (float)HDm + EPSf);
    const float* sc = isK ? sk : sq;
    v0 = v0 * sc[lane]      * inv;
    v1 = v1 * sc[lane + 32] * inv;
    float th = theta[(((size_t)(b*NH + h))*SEQ + n)*(HDm/2) + lane];
    float cs = cosf(th), sn = sinf(th);
    float y0 = v0*cs - v1*sn;
    float y1 = v1*cs + v0*sn;
    p[lane]      = y0;
    p[lane + 32] = y1;
}

// ---------------- flash attention, tf32 mma.sync ----------------
// CTA: 128 queries of one (b,h); 256 thr = 8 warps, warp owns 16 rows.
// KV tiles of 128. smem floats: Qs[128][68], Ks[128][68], Vt[64][132], Ps[128][132].
#define QPAD 68
#define VPAD 132
#define AQS_OFF 0
#define AKS_OFF (128*QPAD)
#define AVT_OFF (2*128*QPAD)
#define APS_OFF (2*128*QPAD + 64*VPAD)
#define ATTN_SMEM ((2*128*QPAD + 64*VPAD + 128*VPAD)*4)

__global__ __launch_bounds__(256)
void fattn_kernel(const float* __restrict__ qkv, float* __restrict__ O){
    extern __shared__ float sm[];
    uint32_t* Qs = (uint32_t*)(sm + AQS_OFF);
    uint32_t* Ks = (uint32_t*)(sm + AKS_OFF);
    uint32_t* Vt = (uint32_t*)(sm + AVT_OFF);
    uint32_t* Ps = (uint32_t*)(sm + APS_OFF);

    int tid = threadIdx.x;
    int w = tid >> 5, lane = tid & 31;
    int qr = lane >> 2, qc = lane & 3;
    int bh = blockIdx.x >> 4;        // b*NH + h
    int qt = blockIdx.x & 15;
    int b = bh >> 3, h = bh & 7;
    int i0 = qt * 128;

    int ldr = tid >> 1;              // 0..127
    int ldc = (tid & 1) * 32;        // 0 / 32

    // load Q tile -> Qs (tf32)
    {
        const float* src = qkv + ((size_t)(b*SEQ + i0 + ldr))*(3*DIM) + h*HDm + ldc;
        #pragma unroll
        for (int i = 0; i < 8; i++){
            float4 v = *(const float4*)(src + i*4);
            uint4 u = make_uint4(f2tf32(v.x), f2tf32(v.y), f2tf32(v.z), f2tf32(v.w));
            *(uint4*)(Qs + ldr*QPAD + ldc + i*4) = u;
        }
    }
    __syncthreads();

    // preload Q fragments (held all kernel)
    uint32_t aQ[8][4];
    #pragma unroll
    for (int ks = 0; ks < 8; ks++){
        int r0 = w*16 + qr, r1 = w*16 + 8 + qr;
        aQ[ks][0] = Qs[r0*QPAD + ks*8 + qc];
        aQ[ks][1] = Qs[r1*QPAD + ks*8 + qc];
        aQ[ks][2] = Qs[r0*QPAD + ks*8 + 4 + qc];
        aQ[ks][3] = Qs[r1*QPAD + ks*8 + 4 + qc];
    }

    float Oacc[8][4];
    #pragma unroll
    for (int nt = 0; nt < 8; nt++)
        #pragma unroll
        for (int i = 0; i < 4; i++) Oacc[nt][i] = 0.f;
    float m0 = -INFINITY, m1 = -INFINITY, l0 = 0.f, l1 = 0.f;

    for (int t = 0; t < SEQ/128; t++){
        int j0 = t * 128;
        __syncthreads();   // prev PV done reading Ks/Vt/Ps
        // load K tile
        {
            const float* src = qkv + ((size_t)(b*SEQ + j0 + ldr))*(3*DIM) + DIM + h*HDm + ldc;
            #pragma unroll
            for (int i = 0; i < 8; i++){
                float4 v = *(const float4*)(src + i*4);
                uint4 u = make_uint4(f2tf32(v.x), f2tf32(v.y), f2tf32(v.z), f2tf32(v.w));
                *(uint4*)(Ks + ldr*QPAD + ldc + i*4) = u;
            }
        }
        // load V tile transposed
        {
            const float* src = qkv + ((size_t)(b*SEQ + j0 + ldr))*(3*DIM) + 2*DIM + h*HDm + ldc;
            #pragma unroll
            for (int i = 0; i < 8; i++){
                float4 v = *(const float4*)(src + i*4);
                int c = ldc + i*4;
                Vt[(c+0)*VPAD + ldr] = f2tf32(v.x);
                Vt[(c+1)*VPAD + ldr] = f2tf32(v.y);
                Vt[(c+2)*VPAD + ldr] = f2tf32(v.z);
                Vt[(c+3)*VPAD + ldr] = f2tf32(v.w);
            }
        }
        __syncthreads();

        // S = Q K^T : warp computes 16x128
        float S[16][4];
        #pragma unroll
        for (int nt = 0; nt < 16; nt++){
            S[nt][0] = S[nt][1] = S[nt][2] = S[nt][3] = 0.f;
            #pragma unroll
            for (int ks = 0; ks < 8; ks++){
                uint32_t b0 = Ks[(nt*8 + qr)*QPAD + ks*8 + qc];
                uint32_t b1 = Ks[(nt*8 + qr)*QPAD + ks*8 + 4 + qc];
                mma_tf32(S[nt], aQ[ks], b0, b1);
            }
        }

        // online softmax
        float mx0 = -INFINITY, mx1 = -INFINITY;
        #pragma unroll
        for (int nt = 0; nt < 16; nt++){
            mx0 = fmaxf(mx0, fmaxf(S[nt][0], S[nt][1]));
            mx1 = fmaxf(mx1, fmaxf(S[nt][2], S[nt][3]));
        }
        mx0 = fmaxf(mx0, __shfl_xor_sync(0xFFFFFFFFu, mx0, 1));
        mx0 = fmaxf(mx0, __shfl_xor_sync(0xFFFFFFFFu, mx0, 2));
        mx1 = fmaxf(mx1, __shfl_xor_sync(0xFFFFFFFFu, mx1, 1));
        mx1 = fmaxf(mx1, __shfl_xor_sync(0xFFFFFFFFu, mx1, 2));
        float nm0 = fmaxf(m0, mx0), nm1 = fmaxf(m1, mx1);
        float sc0 = __expf(m0 - nm0), sc1 = __expf(m1 - nm1);
        m0 = nm0; m1 = nm1;
        float rs0 = 0.f, rs1 = 0.f;
        #pragma unroll
        for (int nt = 0; nt < 16; nt++){
            float p0 = __expf(S[nt][0] - nm0);
            float p1 = __expf(S[nt][1] - nm0);
            float p2 = __expf(S[nt][2] - nm1);
            float p3 = __expf(S[nt][3] - nm1);
            S[nt][0] = p0; S[nt][1] = p1; S[nt][2] = p2; S[nt][3] = p3;
            rs0 += p0 + p1; rs1 += p2 + p3;
        }
        rs0 += __shfl_xor_sync(0xFFFFFFFFu, rs0, 1);
        rs0 += __shfl_xor_sync(0xFFFFFFFFu, rs0, 2);
        rs1 += __shfl_xor_sync(0xFFFFFFFFu, rs1, 1);
        rs1 += __shfl_xor_sync(0xFFFFFFFFu, rs1, 2);
        l0 = l0 * sc0 + rs0;
        l1 = l1 * sc1 + rs1;
        #pragma unroll
        for (int nt = 0; nt < 8; nt++){
            Oacc[nt][0] *= sc0; Oacc[nt][1] *= sc0;
            Oacc[nt][2] *= sc1; Oacc[nt][3] *= sc1;
        }

        // write P tiles to smem (tf32)
        {
            int r0 = w*16 + qr, r1 = w*16 + 8 + qr;
            #pragma unroll
            for (int nt = 0; nt < 16; nt++){
                uint2 u0 = make_uint2(f2tf32(S[nt][0]), f2tf32(S[nt][1]));
                uint2 u1 = make_uint2(f2tf32(S[nt][2]), f2tf32(S[nt][3]));
                *(uint2*)(Ps + r0*VPAD + nt*8 + 2*qc) = u0;
                *(uint2*)(Ps + r1*VPAD + nt*8 + 2*qc) = u1;
            }
        }
        __syncthreads();

        // O += P V
        #pragma unroll
        for (int ks = 0; ks < 16; ks++){
            uint32_t aP[4];
            int r0 = w*16 + qr, r1 = w*16 + 8 + qr;
            aP[0] = Ps[r0*VPAD + ks*8 + qc];
            aP[1] = Ps[r1*VPAD + ks*8 + qc];
            aP[2] = Ps[r0*VPAD + ks*8 + 4 + qc];
            aP[3] = Ps[r1*VPAD + ks*8 + 4 + qc];
            #pragma unroll
            for (int nt = 0; nt < 8; nt++){
                uint32_t b0 = Vt[(nt*8 + qr)*VPAD + ks*8 + qc];
                uint32_t b1 = Vt[(nt*8 + qr)*VPAD + ks*8 + 4 + qc];
                mma_tf32(Oacc[nt], aP, b0, b1);
            }
        }
    }

    // epilogue
    float il0 = 1.f / l0, il1 = 1.f / l1;
    int row0 = i0 + w*16 + qr, row1 = row0 + 8;
    #pragma unroll
    for (int nt = 0; nt < 8; nt++){
        int col = h*HDm + nt*8 + 2*qc;
        *(float2*)(O + ((size_t)(b*SEQ) + row0)*DIM + col) =
            make_float2(Oacc[nt][0]*il0, Oacc[nt][1]*il0);
        *(float2*)(O + ((size_t)(b*SEQ) + row1)*DIM + col) =
            make_float2(Oacc[nt][2]*il1, Oacc[nt][3]*il1);
    }
}

// ---------------- gated GELU ----------------
__global__ void glu_kernel(const float* __restrict__ Hh, float* __restrict__ Hg){
    size_t i = (size_t)blockIdx.x * 256 + threadIdx.x;
    size_t m = i / FFm, f = i % FFm;
    float hx = Hh[m*(2*FFm) + f];
    float g  = Hh[m*(2*FFm) + FFm + f];
    float ge = 0.5f * g * (1.f + erff(g * 0.70710678118654752f));
    Hg[i] = hx * ge;
}

// ---------------- launch ----------------
extern "C" void kernel_launch(void* const* d_in, const int* in_sizes, int n_in,
                              void* d_out, int out_size){
    const float* x       = (const float*)d_in[0];
    const float* theta   = (const float*)d_in[1];
    const float* fmaps   = (const float*)d_in[2];
    const float* coords  = (const float*)d_in[3];
    const float* w_corr  = (const float*)d_in[4];
    const float* norm1   = (const float*)d_in[5];
    const float* sq      = (const float*)d_in[6];
    const float* sk      = (const float*)d_in[7];
    const float* w_qkv   = (const float*)d_in[8];
    const float* w_out   = (const float*)d_in[9];
    const float* norm2   = (const float*)d_in[10];
    const float* w_ff1   = (const float*)d_in[11];
    const float* b_ff1   = (const float*)d_in[12];
    const float* w_ff2   = (const float*)d_in[13];
    float* out = (float*)d_out;

    float *p_feats, *p_x, *p_xn, *p_qkv, *p_o, *p_x2, *p_xn2, *p_h, *p_hg;
    cudaGetSymbolAddress((void**)&p_feats, g_feats);
    cudaGetSymbolAddress((void**)&p_x,     g_x);
    cudaGetSymbolAddress((void**)&p_xn,    g_xn);
    cudaGetSymbolAddress((void**)&p_qkv,   g_qkv);
    cudaGetSymbolAddress((void**)&p_o,     g_o);
    cudaGetSymbolAddress((void**)&p_x2,    g_x2);
    cudaGetSymbolAddress((void**)&p_xn2,   g_xn2);
    cudaGetSymbolAddress((void**)&p_h,     g_h);
    cudaGetSymbolAddress((void**)&p_hg,    g_hg);

    static bool cfg = false;
    if (!cfg){
        cudaFuncSetAttribute(fattn_kernel, cudaFuncAttributeMaxDynamicSharedMemorySize,
                             ATTN_SMEM);
        cudaFuncSetAttribute(gemm_mma, cudaFuncAttributeMaxDynamicSharedMemorySize,
                             GEMM_SMEM);
        cfg = true;
    }

    const int M = Bsz * SEQ;   // 8192

    bilinear_kernel<<<M, C2m>>>(fmaps, coords);
    gemm_mma<<<dim3(DIM/128, M/128), 256, GEMM_SMEM>>>(p_feats, w_corr, nullptr, x, p_x, M, DIM, C2m);
    rmsnorm_kernel<<<M, 128>>>(p_x, norm1, p_xn);
    gemm_mma<<<dim3(3*DIM/128, M/128), 256, GEMM_SMEM>>>(p_xn, w_qkv, nullptr, nullptr, p_qkv, M, 3*DIM, DIM);
    qkprep_kernel<<<M*NH*2, 32>>>(p_qkv, theta, sq, sk);
    fattn_kernel<<<Bsz*NH*(SEQ/128), 256, ATTN_SMEM>>>(p_qkv, p_o);
    gemm_mma<<<dim3(DIM/128, M/128), 256, GEMM_SMEM>>>(p_o, w_out, nullptr, p_x, p_x2, M, DIM, DIM);
    rmsnorm_kernel<<<M, 128>>>(p_x2, norm2, p_xn2);
    gemm_mma<<<dim3(2*FFm/128, M/128), 256, GEMM_SMEM>>>(p_xn2, w_ff1, b_ff1, nullptr, p_h, M, 2*FFm, DIM);
    glu_kernel<<<(Bsz*SEQ*FFm)/256, 256>>>(p_h, p_hg);
    gemm_mma<<<dim3(DIM/128, M/128), 256, GEMM_SMEM>>>(p_hg, w_ff2, nullptr, p_x2, out, M, DIM, FFm);
}

// round 10
// speedup vs baseline: 6.5523x; 1.2891x over previous
#include <cuda_runtime.h>
#include <cuda_fp16.h>
#include <math.h>
#include <stdint.h>

#define Bsz 4
#define SEQ 2048
#define DIM 512
#define NH  8
#define HDm 64
#define FFm 1024
#define C2m 128
#define HFm 64
#define WFm 64
#define EPSf 1e-6f

// ---------------- static scratch ----------------
__device__ float g_feats[Bsz*SEQ*C2m];
__device__ float g_x   [Bsz*SEQ*DIM];
__device__ float g_xn  [Bsz*SEQ*DIM];
__device__ float g_qkv [Bsz*SEQ*3*DIM];
__device__ float g_o   [Bsz*SEQ*DIM];
__device__ float g_x2  [Bsz*SEQ*DIM];
__device__ float g_xn2 [Bsz*SEQ*DIM];
__device__ float g_h   [Bsz*SEQ*2*FFm];
__device__ float g_hg  [Bsz*SEQ*FFm];

__device__ __forceinline__ float warpSum(float v){
    #pragma unroll
    for (int o = 16; o > 0; o >>= 1) v += __shfl_xor_sync(0xFFFFFFFFu, v, o);
    return v;
}
__device__ __forceinline__ uint32_t pkh2(float x, float y){
    __half2 h = __floats2half2_rn(x, y);
    return *reinterpret_cast<uint32_t*>(&h);
}
__device__ __forceinline__ void mma_f16(float* c, const uint32_t* a, uint32_t b0, uint32_t b1){
    asm volatile(
        "mma.sync.aligned.m16n8k16.row.col.f32.f16.f16.f32 "
        "{%0,%1,%2,%3}, {%4,%5,%6,%7}, {%8,%9}, {%0,%1,%2,%3};"
        : "+f"(c[0]), "+f"(c[1]), "+f"(c[2]), "+f"(c[3])
        : "r"(a[0]), "r"(a[1]), "r"(a[2]), "r"(a[3]), "r"(b0), "r"(b1));
}

// ---------------- bilinear ----------------
__global__ void bilinear_kernel(const float* __restrict__ fmaps,
                                const float* __restrict__ coords){
    int bn = blockIdx.x;
    int b  = bn / SEQ;
    int c  = threadIdx.x;
    float xc = coords[(size_t)bn*2 + 0];
    float yc = coords[(size_t)bn*2 + 1];
    xc = fminf(fmaxf(xc, 0.f), (float)(WFm-1));
    yc = fminf(fmaxf(yc, 0.f), (float)(HFm-1));
    float x0 = floorf(xc), y0 = floorf(yc);
    float wx = xc - x0,    wy = yc - y0;
    int x0i = (int)x0, y0i = (int)y0;
    int x1i = min(x0i+1, WFm-1), y1i = min(y0i+1, HFm-1);
    const float* img = fmaps + ((size_t)(b*C2m + c))*HFm*WFm;
    float f00 = img[y0i*WFm + x0i];
    float f01 = img[y0i*WFm + x1i];
    float f10 = img[y1i*WFm + x0i];
    float f11 = img[y1i*WFm + x1i];
    float top = f00*(1.f-wx) + f01*wx;
    float bot = f10*(1.f-wx) + f11*wx;
    g_feats[(size_t)bn*C2m + c] = top*(1.f-wy) + bot*wy;
}

// ---------------- f16 mma.sync GEMM: C = A @ W^T (+bias)(+resid) ----------------
// 128x128 tile, BK=32 panel (2 k-steps of 16), 256 thr = 8 warps (4m x 2n).
// SMEM rows: 40 halfs (20 u32) -> fragment LDS banks 4*qr+qc pattern, conflict-free.
#define BK 32
#define HSTR 20
#define HBUF (128*HSTR)
#define GEMM_SMEM (4*HBUF*4)

__global__ __launch_bounds__(256)
void gemm_mma(const float* __restrict__ A, const float* __restrict__ W,
              const float* __restrict__ bias, const float* __restrict__ resid,
              float* __restrict__ C, int M, int Nout, int K){
    extern __shared__ uint32_t smu[];
    int tid = threadIdx.x;
    int wid = tid >> 5, lane = tid & 31;
    int qr = lane >> 2, qc = lane & 3;
    int warp_m = wid & 3, warp_n = wid >> 2;
    int m0 = blockIdx.y * 128, n0 = blockIdx.x * 128;

    const float* Abase = A + (size_t)m0 * K;
    const float* Wbase = W + (size_t)n0 * K;

    float4 ra[4], rb[4];
    int ldr = tid >> 1;
    int ldc = (tid & 1) * 16;

    #pragma unroll
    for (int i = 0; i < 4; i++){
        ra[i] = *(const float4*)(Abase + (size_t)ldr*K + ldc + i*4);
        rb[i] = *(const float4*)(Wbase + (size_t)ldr*K + ldc + i*4);
    }
    {
        uint32_t* As = smu;
        uint32_t* Bs = smu + HBUF;
        uint4 ua0 = make_uint4(pkh2(ra[0].x,ra[0].y), pkh2(ra[0].z,ra[0].w),
                               pkh2(ra[1].x,ra[1].y), pkh2(ra[1].z,ra[1].w));
        uint4 ua1 = make_uint4(pkh2(ra[2].x,ra[2].y), pkh2(ra[2].z,ra[2].w),
                               pkh2(ra[3].x,ra[3].y), pkh2(ra[3].z,ra[3].w));
        uint4 ub0 = make_uint4(pkh2(rb[0].x,rb[0].y), pkh2(rb[0].z,rb[0].w),
                               pkh2(rb[1].x,rb[1].y), pkh2(rb[1].z,rb[1].w));
        uint4 ub1 = make_uint4(pkh2(rb[2].x,rb[2].y), pkh2(rb[2].z,rb[2].w),
                               pkh2(rb[3].x,rb[3].y), pkh2(rb[3].z,rb[3].w));
        *(uint4*)(As + ldr*HSTR + (ldc>>1)    ) = ua0;
        *(uint4*)(As + ldr*HSTR + (ldc>>1) + 4) = ua1;
        *(uint4*)(Bs + ldr*HSTR + (ldc>>1)    ) = ub0;
        *(uint4*)(Bs + ldr*HSTR + (ldc>>1) + 4) = ub1;
    }
    __syncthreads();

    float acc[2][8][4];
    #pragma unroll
    for (int mt = 0; mt < 2; mt++)
        #pragma unroll
        for (int nt = 0; nt < 8; nt++)
            #pragma unroll
            for (int i = 0; i < 4; i++) acc[mt][nt][i] = 0.f;

    int T = K / BK;
    for (int t = 0; t < T; t++){
        int buf = t & 1;
        if (t + 1 < T){
            int k0 = (t+1) * BK;
            #pragma unroll
            for (int i = 0; i < 4; i++){
                ra[i] = *(const float4*)(Abase + (size_t)ldr*K + k0 + ldc + i*4);
                rb[i] = *(const float4*)(Wbase + (size_t)ldr*K + k0 + ldc + i*4);
            }
        }
        const uint32_t* As = smu + buf*2*HBUF;
        const uint32_t* Bs = smu + buf*2*HBUF + HBUF;
        #pragma unroll
        for (int ks = 0; ks < 2; ks++){
            int k8 = ks * 8;
            uint32_t af[2][4];
            #pragma unroll
            for (int mt = 0; mt < 2; mt++){
                int r0 = warp_m*32 + mt*16 + qr;
                af[mt][0] = As[ r0     *HSTR + k8 + qc];
                af[mt][1] = As[(r0 + 8)*HSTR + k8 + qc];
                af[mt][2] = As[ r0     *HSTR + k8 + 4 + qc];
                af[mt][3] = As[(r0 + 8)*HSTR + k8 + 4 + qc];
            }
            #pragma unroll
            for (int nt = 0; nt < 8; nt++){
                int cb = warp_n*64 + nt*8 + qr;
                uint32_t b0 = Bs[cb*HSTR + k8 + qc];
                uint32_t b1 = Bs[cb*HSTR + k8 + 4 + qc];
                mma_f16(acc[0][nt], af[0], b0, b1);
                mma_f16(acc[1][nt], af[1], b0, b1);
            }
        }
        __syncthreads();
        if (t + 1 < T){
            int nbuf = (t+1) & 1;
            uint32_t* Aw = smu + nbuf*2*HBUF;
            uint32_t* Bw = smu + nbuf*2*HBUF + HBUF;
            uint4 ua0 = make_uint4(pkh2(ra[0].x,ra[0].y), pkh2(ra[0].z,ra[0].w),
                                   pkh2(ra[1].x,ra[1].y), pkh2(ra[1].z,ra[1].w));
            uint4 ua1 = make_uint4(pkh2(ra[2].x,ra[2].y), pkh2(ra[2].z,ra[2].w),
                                   pkh2(ra[3].x,ra[3].y), pkh2(ra[3].z,ra[3].w));
            uint4 ub0 = make_uint4(pkh2(rb[0].x,rb[0].y), pkh2(rb[0].z,rb[0].w),
                                   pkh2(rb[1].x,rb[1].y), pkh2(rb[1].z,rb[1].w));
            uint4 ub1 = make_uint4(pkh2(rb[2].x,rb[2].y), pkh2(rb[2].z,rb[2].w),
                                   pkh2(rb[3].x,rb[3].y), pkh2(rb[3].z,rb[3].w));
            *(uint4*)(Aw + ldr*HSTR + (ldc>>1)    ) = ua0;
            *(uint4*)(Aw + ldr*HSTR + (ldc>>1) + 4) = ua1;
            *(uint4*)(Bw + ldr*HSTR + (ldc>>1)    ) = ub0;
            *(uint4*)(Bw + ldr*HSTR + (ldc>>1) + 4) = ub1;
            __syncthreads();
        }
    }

    #pragma unroll
    for (int mt = 0; mt < 2; mt++){
        #pragma unroll
        for (int nt = 0; nt < 8; nt++){
            int row = m0 + warp_m*32 + mt*16 + qr;
            int col = n0 + warp_n*64 + nt*8 + qc*2;
            float2 v0 = make_float2(acc[mt][nt][0], acc[mt][nt][1]);
            float2 v1 = make_float2(acc[mt][nt][2], acc[mt][nt][3]);
            if (bias){
                float2 bb = *(const float2*)(bias + col);
                v0.x += bb.x; v0.y += bb.y;
                v1.x += bb.x; v1.y += bb.y;
            }
            size_t off0 = (size_t)row * Nout + col;
            size_t off1 = (size_t)(row + 8) * Nout + col;
            if (resid){
                float2 r0 = *(const float2*)(resid + off0);
                float2 r1 = *(const float2*)(resid + off1);
                v0.x += r0.x; v0.y += r0.y;
                v1.x += r1.x; v1.y += r1.y;
            }
            *(float2*)(C + off0) = v0;
            *(float2*)(C + off1) = v1;
        }
    }
}

// ---------------- RMSNorm over DIM=512 ----------------
__global__ void rmsnorm_kernel(const float* __restrict__ X,
                               const float* __restrict__ scale,
                               float* __restrict__ Y){
    int row = blockIdx.x;
    int t   = threadIdx.x;  // 128
    const float4* x4 = (const float4*)(X + (size_t)row*DIM);
    float4 v = x4[t];
    float ss = v.x*v.x + v.y*v.y + v.z*v.z + v.w*v.w;
    ss = warpSum(ss);
    __shared__ float red[4];
    if ((t & 31) == 0) red[t >> 5] = ss;
    __syncthreads();
    if (t == 0) red[0] = red[0] + red[1] + red[2] + red[3];
    __syncthreads();
    float inv = rsqrtf(red[0] / (float)DIM + EPSf);
    float4 s = ((const float4*)scale)[t];
    float4 o;
    o.x = v.x * s.x * inv; o.y = v.y * s.y * inv;
    o.z = v.z * s.z * inv; o.w = v.w * s.w * inv;
    ((float4*)(Y + (size_t)row*DIM))[t] = o;
}

// ---------------- per-head RMSNorm + rotary (8 units / 256-thr block) ----------------
__global__ __launch_bounds__(256)
void qkprep_kernel(float* __restrict__ qkv, const float* __restrict__ theta,
                   const float* __restrict__ sq, const float* __restrict__ sk){
    int t = blockIdx.x * 8 + (threadIdx.x >> 5);
    int isK = t & 1; int rest = t >> 1;
    int h = rest % NH; rest /= NH;
    int n = rest % SEQ; int b = rest / SEQ;
    int lane = threadIdx.x & 31;
    float* p = qkv + ((size_t)(b*SEQ + n))*(3*DIM) + isK*DIM + h*HDm;
    float v0 = p[lane], v1 = p[lane + 32];
    float ss = warpSum(v0*v0 + v1*v1);
    float inv = rsqrtf(ss / (float)HDm + EPSf);
    const float* sc = isK ? sk : sq;
    v0 = v0 * sc[lane]      * inv;
    v1 = v1 * sc[lane + 32] * inv;
    float th = theta[(((size_t)(b*NH + h))*SEQ + n)*(HDm/2) + lane];
    float cs = cosf(th), sn = sinf(th);
    float y0 = v0*cs - v1*sn;
    float y1 = v1*cs + v0*sn;
    p[lane]      = y0;
    p[lane + 32] = y1;
}

// ---------------- flash attention, f16 mma.sync ----------------
// CTA: 128 queries of one (b,h); 256 thr = 8 warps, warp owns 16 rows.
// u32-unit smem: Qs[128][QSTR], Ks[128][QSTR] (QSTR=36: 64 halfs data + pad,
// banks 36*qr mod 32 = 4*qr -> conflict-free), Ps[128][68], Vt[64][68] (xor swizzle).
#define QSTR 36
#define FQ_OFF 0
#define FK_OFF (128*QSTR)
#define FP_OFF (2*128*QSTR)
#define FV_OFF (2*128*QSTR + 128*68)
#define ATTN_SMEM ((2*128*QSTR + 128*68 + 64*68)*4)

__global__ __launch_bounds__(256)
void fattn_kernel(const float* __restrict__ qkv, float* __restrict__ O){
    extern __shared__ uint32_t smu[];
    uint32_t* Qs = smu + FQ_OFF;
    uint32_t* Ks = smu + FK_OFF;
    uint32_t* Ps = smu + FP_OFF;
    uint32_t* Vt = smu + FV_OFF;

    int tid = threadIdx.x;
    int w = tid >> 5, lane = tid & 31;
    int qr = lane >> 2, qc = lane & 3;
    int bh = blockIdx.x >> 4;
    int qt = blockIdx.x & 15;
    int b = bh >> 3, h = bh & 7;
    int i0 = qt * 128;

    int ldr = tid >> 1;
    int ldc = (tid & 1) * 32;

    // load Q tile (f16)
    {
        const float* src = qkv + ((size_t)(b*SEQ + i0 + ldr))*(3*DIM) + h*HDm + ldc;
        float4 q0 = *(const float4*)(src + 0);
        float4 q1 = *(const float4*)(src + 4);
        float4 q2 = *(const float4*)(src + 8);
        float4 q3 = *(const float4*)(src + 12);
        float4 q4 = *(const float4*)(src + 16);
        float4 q5 = *(const float4*)(src + 20);
        float4 q6 = *(const float4*)(src + 24);
        float4 q7 = *(const float4*)(src + 28);
        uint32_t* dst = Qs + ldr*QSTR + (ldc>>1);
        *(uint4*)(dst+ 0) = make_uint4(pkh2(q0.x,q0.y),pkh2(q0.z,q0.w),pkh2(q1.x,q1.y),pkh2(q1.z,q1.w));
        *(uint4*)(dst+ 4) = make_uint4(pkh2(q2.x,q2.y),pkh2(q2.z,q2.w),pkh2(q3.x,q3.y),pkh2(q3.z,q3.w));
        *(uint4*)(dst+ 8) = make_uint4(pkh2(q4.x,q4.y),pkh2(q4.z,q4.w),pkh2(q5.x,q5.y),pkh2(q5.z,q5.w));
        *(uint4*)(dst+12) = make_uint4(pkh2(q6.x,q6.y),pkh2(q6.z,q6.w),pkh2(q7.x,q7.y),pkh2(q7.z,q7.w));
    }
    __syncthreads();

    // preload Q fragments (HDm=64 halfs = 4 ksteps of 16)
    uint32_t aQ[4][4];
    #pragma unroll
    for (int ks = 0; ks < 4; ks++){
        int r0 = w*16 + qr;
        aQ[ks][0] = Qs[ r0     *QSTR + ks*8 + qc];
        aQ[ks][1] = Qs[(r0 + 8)*QSTR + ks*8 + qc];
        aQ[ks][2] = Qs[ r0     *QSTR + ks*8 + 4 + qc];
        aQ[ks][3] = Qs[(r0 + 8)*QSTR + ks*8 + 4 + qc];
    }

    float Oacc[8][4];
    #pragma unroll
    for (int nt = 0; nt < 8; nt++)
        #pragma unroll
        for (int i = 0; i < 4; i++) Oacc[nt][i] = 0.f;
    float m0 = -INFINITY, m1 = -INFINITY, l0 = 0.f, l1 = 0.f;

    int jp = tid >> 2;                 // 0..63 j-pair for V transpose
    int dg = (tid & 3) * 16;           // d base

    for (int t = 0; t < SEQ/128; t++){
        int j0 = t * 128;
        __syncthreads();
        // load K tile
        {
            const float* src = qkv + ((size_t)(b*SEQ + j0 + ldr))*(3*DIM) + DIM + h*HDm + ldc;
            float4 k0 = *(const float4*)(src + 0);
            float4 k1 = *(const float4*)(src + 4);
            float4 k2 = *(const float4*)(src + 8);
            float4 k3 = *(const float4*)(src + 12);
            float4 k4 = *(const float4*)(src + 16);
            float4 k5 = *(const float4*)(src + 20);
            float4 k6 = *(const float4*)(src + 24);
            float4 k7 = *(const float4*)(src + 28);
            uint32_t* dst = Ks + ldr*QSTR + (ldc>>1);
            *(uint4*)(dst+ 0) = make_uint4(pkh2(k0.x,k0.y),pkh2(k0.z,k0.w),pkh2(k1.x,k1.y),pkh2(k1.z,k1.w));
            *(uint4*)(dst+ 4) = make_uint4(pkh2(k2.x,k2.y),pkh2(k2.z,k2.w),pkh2(k3.x,k3.y),pkh2(k3.z,k3.w));
            *(uint4*)(dst+ 8) = make_uint4(pkh2(k4.x,k4.y),pkh2(k4.z,k4.w),pkh2(k5.x,k5.y),pkh2(k5.z,k5.w));
            *(uint4*)(dst+12) = make_uint4(pkh2(k6.x,k6.y),pkh2(k6.z,k6.w),pkh2(k7.x,k7.y),pkh2(k7.z,k7.w));
        }
        // load V tile transposed: Vt[d][jpair] = half2(V[2jp][d], V[2jp+1][d]), xor swizzle
        {
            const float* vp = qkv + ((size_t)(b*SEQ + j0 + 2*jp))*(3*DIM) + 2*DIM + h*HDm + dg;
            #pragma unroll
            for (int i = 0; i < 4; i++){
                float4 va = *(const float4*)(vp + i*4);
                float4 vb = *(const float4*)(vp + 3*DIM + i*4);
                int d0 = dg + i*4;
                Vt[(d0+0)*68 + (jp ^ ((((d0+0)>>4)&3)<<3))] = pkh2(va.x, vb.x);
                Vt[(d0+1)*68 + (jp ^ ((((d0+1)>>4)&3)<<3))] = pkh2(va.y, vb.y);
                Vt[(d0+2)*68 + (jp ^ ((((d0+2)>>4)&3)<<3))] = pkh2(va.z, vb.z);
                Vt[(d0+3)*68 + (jp ^ ((((d0+3)>>4)&3)<<3))] = pkh2(va.w, vb.w);
            }
        }
        __syncthreads();

        // S = Q K^T : warp computes 16 rows x 128 cols
        float S[16][4];
        #pragma unroll
        for (int nt = 0; nt < 16; nt++){
            S[nt][0] = S[nt][1] = S[nt][2] = S[nt][3] = 0.f;
            #pragma unroll
            for (int ks = 0; ks < 4; ks++){
                int cb = nt*8 + qr;
                uint32_t b0 = Ks[cb*QSTR + ks*8 + qc];
                uint32_t b1 = Ks[cb*QSTR + ks*8 + 4 + qc];
                mma_f16(S[nt], aQ[ks], b0, b1);
            }
        }

        // online softmax
        float mx0 = -INFINITY, mx1 = -INFINITY;
        #pragma unroll
        for (int nt = 0; nt < 16; nt++){
            mx0 = fmaxf(mx0, fmaxf(S[nt][0], S[nt][1]));
            mx1 = fmaxf(mx1, fmaxf(S[nt][2], S[nt][3]));
        }
        mx0 = fmaxf(mx0, __shfl_xor_sync(0xFFFFFFFFu, mx0, 1));
        mx0 = fmaxf(mx0, __shfl_xor_sync(0xFFFFFFFFu, mx0, 2));
        mx1 = fmaxf(mx1, __shfl_xor_sync(0xFFFFFFFFu, mx1, 1));
        mx1 = fmaxf(mx1, __shfl_xor_sync(0xFFFFFFFFu, mx1, 2));
        float nm0 = fmaxf(m0, mx0), nm1 = fmaxf(m1, mx1);
        float sc0 = __expf(m0 - nm0), sc1 = __expf(m1 - nm1);
        m0 = nm0; m1 = nm1;
        float rs0 = 0.f, rs1 = 0.f;
        #pragma unroll
        for (int nt = 0; nt < 16; nt++){
            float p0 = __expf(S[nt][0] - nm0);
            float p1 = __expf(S[nt][1] - nm0);
            float p2 = __expf(S[nt][2] - nm1);
            float p3 = __expf(S[nt][3] - nm1);
            S[nt][0] = p0; S[nt][1] = p1; S[nt][2] = p2; S[nt][3] = p3;
            rs0 += p0 + p1; rs1 += p2 + p3;
        }
        rs0 += __shfl_xor_sync(0xFFFFFFFFu, rs0, 1);
        rs0 += __shfl_xor_sync(0xFFFFFFFFu, rs0, 2);
        rs1 += __shfl_xor_sync(0xFFFFFFFFu, rs1, 1);
        rs1 += __shfl_xor_sync(0xFFFFFFFFu, rs1, 2);
        l0 = l0 * sc0 + rs0;
        l1 = l1 * sc1 + rs1;
        #pragma unroll
        for (int nt = 0; nt < 8; nt++){
            Oacc[nt][0] *= sc0; Oacc[nt][1] *= sc0;
            Oacc[nt][2] *= sc1; Oacc[nt][3] *= sc1;
        }

        // write P tiles to smem (f16)
        {
            int r0 = w*16 + qr, r1 = r0 + 8;
            #pragma unroll
            for (int nt = 0; nt < 16; nt++){
                Ps[r0*68 + nt*4 + qc] = pkh2(S[nt][0], S[nt][1]);
                Ps[r1*68 + nt*4 + qc] = pkh2(S[nt][2], S[nt][3]);
            }
        }
        __syncthreads();

        // O += P V  (128 keys = 8 ksteps of 16)
        #pragma unroll
        for (int ks = 0; ks < 8; ks++){
            uint32_t aP[4];
            int r0 = w*16 + qr, r1 = r0 + 8;
            aP[0] = Ps[r0*68 + ks*8 + qc];
            aP[1] = Ps[r1*68 + ks*8 + qc];
            aP[2] = Ps[r0*68 + ks*8 + 4 + qc];
            aP[3] = Ps[r1*68 + ks*8 + 4 + qc];
            #pragma unroll
            for (int nt = 0; nt < 8; nt++){
                int drow = nt*8 + qr;
                int swz = (nt >> 1) << 3;
                uint32_t b0 = Vt[drow*68 + ((ks*8 + qc) ^ swz)];
                uint32_t b1 = Vt[drow*68 + ((ks*8 + 4 + qc) ^ swz)];
                mma_f16(Oacc[nt], aP, b0, b1);
            }
        }
    }

    // epilogue
    float il0 = 1.f / l0, il1 = 1.f / l1;
    int row0 = i0 + w*16 + qr, row1 = row0 + 8;
    #pragma unroll
    for (int nt = 0; nt < 8; nt++){
        int col = h*HDm + nt*8 + 2*qc;
        *(float2*)(O + ((size_t)(b*SEQ) + row0)*DIM + col) =
            make_float2(Oacc[nt][0]*il0, Oacc[nt][1]*il0);
        *(float2*)(O + ((size_t)(b*SEQ) + row1)*DIM + col) =
            make_float2(Oacc[nt][2]*il1, Oacc[nt][3]*il1);
    }
}

// ---------------- gated GELU (float4) ----------------
__global__ void glu_kernel(const float* __restrict__ Hh, float* __restrict__ Hg){
    size_t i4 = ((size_t)blockIdx.x * 256 + threadIdx.x) * 4;
    size_t m = i4 / FFm, f = i4 % FFm;
    float4 hx = *(const float4*)(Hh + m*(2*FFm) + f);
    float4 g  = *(const float4*)(Hh + m*(2*FFm) + FFm + f);
    float4 o;
    o.x = hx.x * 0.5f * g.x * (1.f + erff(g.x * 0.70710678118654752f));
    o.y = hx.y * 0.5f * g.y * (1.f + erff(g.y * 0.70710678118654752f));
    o.z = hx.z * 0.5f * g.z * (1.f + erff(g.z * 0.70710678118654752f));
    o.w = hx.w * 0.5f * g.w * (1.f + erff(g.w * 0.70710678118654752f));
    *(float4*)(Hg + i4) = o;
}

// ---------------- launch ----------------
extern "C" void kernel_launch(void* const* d_in, const int* in_sizes, int n_in,
                              void* d_out, int out_size){
    const float* x       = (const float*)d_in[0];
    const float* theta   = (const float*)d_in[1];
    const float* fmaps   = (const float*)d_in[2];
    const float* coords  = (const float*)d_in[3];
    const float* w_corr  = (const float*)d_in[4];
    const float* norm1   = (const float*)d_in[5];
    const float* sq      = (const float*)d_in[6];
    const float* sk      = (const float*)d_in[7];
    const float* w_qkv   = (const float*)d_in[8];
    const float* w_out   = (const float*)d_in[9];
    const float* norm2   = (const float*)d_in[10];
    const float* w_ff1   = (const float*)d_in[11];
    const float* b_ff1   = (const float*)d_in[12];
    const float* w_ff2   = (const float*)d_in[13];
    float* out = (float*)d_out;

    float *p_feats, *p_x, *p_xn, *p_qkv, *p_o, *p_x2, *p_xn2, *p_h, *p_hg;
    cudaGetSymbolAddress((void**)&p_feats, g_feats);
    cudaGetSymbolAddress((void**)&p_x,     g_x);
    cudaGetSymbolAddress((void**)&p_xn,    g_xn);
    cudaGetSymbolAddress((void**)&p_qkv,   g_qkv);
    cudaGetSymbolAddress((void**)&p_o,     g_o);
    cudaGetSymbolAddress((void**)&p_x2,    g_x2);
    cudaGetSymbolAddress((void**)&p_xn2,   g_xn2);
    cudaGetSymbolAddress((void**)&p_h,     g_h);
    cudaGetSymbolAddress((void**)&p_hg,    g_hg);

    static bool cfg = false;
    if (!cfg){
        cudaFuncSetAttribute(fattn_kernel, cudaFuncAttributeMaxDynamicSharedMemorySize,
                             ATTN_SMEM);
        cudaFuncSetAttribute(gemm_mma, cudaFuncAttributeMaxDynamicSharedMemorySize,
                             GEMM_SMEM);
        cfg = true;
    }

    const int M = Bsz * SEQ;   // 8192

    bilinear_kernel<<<M, C2m>>>(fmaps, coords);
    gemm_mma<<<dim3(DIM/128, M/128), 256, GEMM_SMEM>>>(p_feats, w_corr, nullptr, x, p_x, M, DIM, C2m);
    rmsnorm_kernel<<<M, 128>>>(p_x, norm1, p_xn);
    gemm_mma<<<dim3(3*DIM/128, M/128), 256, GEMM_SMEM>>>(p_xn, w_qkv, nullptr, nullptr, p_qkv, M, 3*DIM, DIM);
    qkprep_kernel<<<M*NH*2/8, 256>>>(p_qkv, theta, sq, sk);
    fattn_kernel<<<Bsz*NH*(SEQ/128), 256, ATTN_SMEM>>>(p_qkv, p_o);
    gemm_mma<<<dim3(DIM/128, M/128), 256, GEMM_SMEM>>>(p_o, w_out, nullptr, p_x, p_x2, M, DIM, DIM);
    rmsnorm_kernel<<<M, 128>>>(p_x2, norm2, p_xn2);
    gemm_mma<<<dim3(2*FFm/128, M/128), 256, GEMM_SMEM>>>(p_xn2, w_ff1, b_ff1, nullptr, p_h, M, 2*FFm, DIM);
    glu_kernel<<<(Bsz*SEQ*FFm)/1024, 256>>>(p_h, p_hg);
    gemm_mma<<<dim3(DIM/128, M/128), 256, GEMM_SMEM>>>(p_hg, w_ff2, nullptr, p_x2, out, M, DIM, FFm);
}

// round 11
// speedup vs baseline: 7.2231x; 1.1024x over previous
#include <cuda_runtime.h>
#include <cuda_fp16.h>
#include <math.h>
#include <stdint.h>

#define Bsz 4
#define SEQ 2048
#define DIM 512
#define NH  8
#define HDm 64
#define FFm 1024
#define C2m 128
#define HFm 64
#define WFm 64
#define EPSf 1e-6f

// ---------------- static scratch ----------------
__device__ float g_feats[Bsz*SEQ*C2m];
__device__ float g_x   [Bsz*SEQ*DIM];
__device__ float g_xn  [Bsz*SEQ*DIM];
__device__ float g_qkv [Bsz*SEQ*3*DIM];
__device__ float g_o   [Bsz*SEQ*DIM];
__device__ float g_x2  [Bsz*SEQ*DIM];
__device__ float g_xn2 [Bsz*SEQ*DIM];
__device__ float g_h   [Bsz*SEQ*2*FFm];

__device__ __forceinline__ float warpSum(float v){
    #pragma unroll
    for (int o = 16; o > 0; o >>= 1) v += __shfl_xor_sync(0xFFFFFFFFu, v, o);
    return v;
}
__device__ __forceinline__ uint32_t pkh2(float x, float y){
    __half2 h = __floats2half2_rn(x, y);
    return *reinterpret_cast<uint32_t*>(&h);
}
__device__ __forceinline__ float geluf(float g){
    return 0.5f * g * (1.f + erff(g * 0.70710678118654752f));
}
__device__ __forceinline__ void mma_f16(float* c, const uint32_t* a, uint32_t b0, uint32_t b1){
    asm volatile(
        "mma.sync.aligned.m16n8k16.row.col.f32.f16.f16.f32 "
        "{%0,%1,%2,%3}, {%4,%5,%6,%7}, {%8,%9}, {%0,%1,%2,%3};"
        : "+f"(c[0]), "+f"(c[1]), "+f"(c[2]), "+f"(c[3])
        : "r"(a[0]), "r"(a[1]), "r"(a[2]), "r"(a[3]), "r"(b0), "r"(b1));
}

// ---------------- bilinear ----------------
__global__ void bilinear_kernel(const float* __restrict__ fmaps,
                                const float* __restrict__ coords){
    int bn = blockIdx.x;
    int b  = bn / SEQ;
    int c  = threadIdx.x;
    float xc = coords[(size_t)bn*2 + 0];
    float yc = coords[(size_t)bn*2 + 1];
    xc = fminf(fmaxf(xc, 0.f), (float)(WFm-1));
    yc = fminf(fmaxf(yc, 0.f), (float)(HFm-1));
    float x0 = floorf(xc), y0 = floorf(yc);
    float wx = xc - x0,    wy = yc - y0;
    int x0i = (int)x0, y0i = (int)y0;
    int x1i = min(x0i+1, WFm-1), y1i = min(y0i+1, HFm-1);
    const float* img = fmaps + ((size_t)(b*C2m + c))*HFm*WFm;
    float f00 = img[y0i*WFm + x0i];
    float f01 = img[y0i*WFm + x1i];
    float f10 = img[y1i*WFm + x0i];
    float f11 = img[y1i*WFm + x1i];
    float top = f00*(1.f-wx) + f01*wx;
    float bot = f10*(1.f-wx) + f11*wx;
    g_feats[(size_t)bn*C2m + c] = top*(1.f-wy) + bot*wy;
}

// ---------------- f16 mma.sync GEMM: C = A @ W^T (+bias)(+resid) ----------------
#define BK 32
#define HSTR 20
#define HBUF (128*HSTR)
#define GEMM_SMEM (4*HBUF*4)

__global__ __launch_bounds__(256, 2)
void gemm_mma(const float* __restrict__ A, const float* __restrict__ W,
              const float* __restrict__ bias, const float* __restrict__ resid,
              float* __restrict__ C, int M, int Nout, int K){
    extern __shared__ uint32_t smu[];
    int tid = threadIdx.x;
    int wid = tid >> 5, lane = tid & 31;
    int qr = lane >> 2, qc = lane & 3;
    int warp_m = wid & 3, warp_n = wid >> 2;
    int m0 = blockIdx.y * 128, n0 = blockIdx.x * 128;

    const float* Abase = A + (size_t)m0 * K;
    const float* Wbase = W + (size_t)n0 * K;

    float4 ra[4], rb[4];
    int ldr = tid >> 1;
    int ldc = (tid & 1) * 16;

    #pragma unroll
    for (int i = 0; i < 4; i++){
        ra[i] = *(const float4*)(Abase + (size_t)ldr*K + ldc + i*4);
        rb[i] = *(const float4*)(Wbase + (size_t)ldr*K + ldc + i*4);
    }
    {
        uint32_t* As = smu;
        uint32_t* Bs = smu + HBUF;
        *(uint4*)(As + ldr*HSTR + (ldc>>1)    ) = make_uint4(pkh2(ra[0].x,ra[0].y), pkh2(ra[0].z,ra[0].w),
                                                             pkh2(ra[1].x,ra[1].y), pkh2(ra[1].z,ra[1].w));
        *(uint4*)(As + ldr*HSTR + (ldc>>1) + 4) = make_uint4(pkh2(ra[2].x,ra[2].y), pkh2(ra[2].z,ra[2].w),
                                                             pkh2(ra[3].x,ra[3].y), pkh2(ra[3].z,ra[3].w));
        *(uint4*)(Bs + ldr*HSTR + (ldc>>1)    ) = make_uint4(pkh2(rb[0].x,rb[0].y), pkh2(rb[0].z,rb[0].w),
                                                             pkh2(rb[1].x,rb[1].y), pkh2(rb[1].z,rb[1].w));
        *(uint4*)(Bs + ldr*HSTR + (ldc>>1) + 4) = make_uint4(pkh2(rb[2].x,rb[2].y), pkh2(rb[2].z,rb[2].w),
                                                             pkh2(rb[3].x,rb[3].y), pkh2(rb[3].z,rb[3].w));
    }
    __syncthreads();

    float acc[2][8][4];
    #pragma unroll
    for (int mt = 0; mt < 2; mt++)
        #pragma unroll
        for (int nt = 0; nt < 8; nt++)
            #pragma unroll
            for (int i = 0; i < 4; i++) acc[mt][nt][i] = 0.f;

    int T = K / BK;
    for (int t = 0; t < T; t++){
        int buf = t & 1;
        if (t + 1 < T){
            int k0 = (t+1) * BK;
            #pragma unroll
            for (int i = 0; i < 4; i++){
                ra[i] = *(const float4*)(Abase + (size_t)ldr*K + k0 + ldc + i*4);
                rb[i] = *(const float4*)(Wbase + (size_t)ldr*K + k0 + ldc + i*4);
            }
        }
        const uint32_t* As = smu + buf*2*HBUF;
        const uint32_t* Bs = smu + buf*2*HBUF + HBUF;
        #pragma unroll
        for (int ks = 0; ks < 2; ks++){
            int k8 = ks * 8;
            uint32_t af[2][4];
            #pragma unroll
            for (int mt = 0; mt < 2; mt++){
                int r0 = warp_m*32 + mt*16 + qr;
                af[mt][0] = As[ r0     *HSTR + k8 + qc];
                af[mt][1] = As[(r0 + 8)*HSTR + k8 + qc];
                af[mt][2] = As[ r0     *HSTR + k8 + 4 + qc];
                af[mt][3] = As[(r0 + 8)*HSTR + k8 + 4 + qc];
            }
            #pragma unroll
            for (int nt = 0; nt < 8; nt++){
                int cb = warp_n*64 + nt*8 + qr;
                uint32_t b0 = Bs[cb*HSTR + k8 + qc];
                uint32_t b1 = Bs[cb*HSTR + k8 + 4 + qc];
                mma_f16(acc[0][nt], af[0], b0, b1);
                mma_f16(acc[1][nt], af[1], b0, b1);
            }
        }
        __syncthreads();
        if (t + 1 < T){
            int nbuf = (t+1) & 1;
            uint32_t* Aw = smu + nbuf*2*HBUF;
            uint32_t* Bw = smu + nbuf*2*HBUF + HBUF;
            *(uint4*)(Aw + ldr*HSTR + (ldc>>1)    ) = make_uint4(pkh2(ra[0].x,ra[0].y), pkh2(ra[0].z,ra[0].w),
                                                                 pkh2(ra[1].x,ra[1].y), pkh2(ra[1].z,ra[1].w));
            *(uint4*)(Aw + ldr*HSTR + (ldc>>1) + 4) = make_uint4(pkh2(ra[2].x,ra[2].y), pkh2(ra[2].z,ra[2].w),
                                                                 pkh2(ra[3].x,ra[3].y), pkh2(ra[3].z,ra[3].w));
            *(uint4*)(Bw + ldr*HSTR + (ldc>>1)    ) = make_uint4(pkh2(rb[0].x,rb[0].y), pkh2(rb[0].z,rb[0].w),
                                                                 pkh2(rb[1].x,rb[1].y), pkh2(rb[1].z,rb[1].w));
            *(uint4*)(Bw + ldr*HSTR + (ldc>>1) + 4) = make_uint4(pkh2(rb[2].x,rb[2].y), pkh2(rb[2].z,rb[2].w),
                                                                 pkh2(rb[3].x,rb[3].y), pkh2(rb[3].z,rb[3].w));
            __syncthreads();
        }
    }

    #pragma unroll
    for (int mt = 0; mt < 2; mt++){
        #pragma unroll
        for (int nt = 0; nt < 8; nt++){
            int row = m0 + warp_m*32 + mt*16 + qr;
            int col = n0 + warp_n*64 + nt*8 + qc*2;
            float2 v0 = make_float2(acc[mt][nt][0], acc[mt][nt][1]);
            float2 v1 = make_float2(acc[mt][nt][2], acc[mt][nt][3]);
            if (bias){
                float2 bb = *(const float2*)(bias + col);
                v0.x += bb.x; v0.y += bb.y;
                v1.x += bb.x; v1.y += bb.y;
            }
            size_t off0 = (size_t)row * Nout + col;
            size_t off1 = (size_t)(row + 8) * Nout + col;
            if (resid){
                float2 r0 = *(const float2*)(resid + off0);
                float2 r1 = *(const float2*)(resid + off1);
                v0.x += r0.x; v0.y += r0.y;
                v1.x += r1.x; v1.y += r1.y;
            }
            *(float2*)(C + off0) = v0;
            *(float2*)(C + off1) = v1;
        }
    }
}

// ---------------- ff2 GEMM with fused gated GELU on A ----------------
// A[m, k] = hx[m,k] * gelu(gate[m,k]) where hx = H[m, k], gate = H[m, FFm+k],
// H row stride 2*FFm. C = A @ W^T + resid.
__global__ __launch_bounds__(256, 2)
void gemm_mma_glu(const float* __restrict__ H, const float* __restrict__ W,
                  const float* __restrict__ resid,
                  float* __restrict__ C, int M, int Nout, int K){
    extern __shared__ uint32_t smu[];
    int tid = threadIdx.x;
    int wid = tid >> 5, lane = tid & 31;
    int qr = lane >> 2, qc = lane & 3;
    int warp_m = wid & 3, warp_n = wid >> 2;
    int m0 = blockIdx.y * 128, n0 = blockIdx.x * 128;

    const float* Hbase = H + (size_t)m0 * (2*FFm);
    const float* Wbase = W + (size_t)n0 * K;

    float4 ra[4], rg[4], rb[4];
    int ldr = tid >> 1;
    int ldc = (tid & 1) * 16;

    #pragma unroll
    for (int i = 0; i < 4; i++){
        ra[i] = *(const float4*)(Hbase + (size_t)ldr*(2*FFm) + ldc + i*4);
        rg[i] = *(const float4*)(Hbase + (size_t)ldr*(2*FFm) + FFm + ldc + i*4);
        rb[i] = *(const float4*)(Wbase + (size_t)ldr*K + ldc + i*4);
    }
    #pragma unroll
    for (int i = 0; i < 4; i++){
        ra[i].x *= geluf(rg[i].x); ra[i].y *= geluf(rg[i].y);
        ra[i].z *= geluf(rg[i].z); ra[i].w *= geluf(rg[i].w);
    }
    {
        uint32_t* As = smu;
        uint32_t* Bs = smu + HBUF;
        *(uint4*)(As + ldr*HSTR + (ldc>>1)    ) = make_uint4(pkh2(ra[0].x,ra[0].y), pkh2(ra[0].z,ra[0].w),
                                                             pkh2(ra[1].x,ra[1].y), pkh2(ra[1].z,ra[1].w));
        *(uint4*)(As + ldr*HSTR + (ldc>>1) + 4) = make_uint4(pkh2(ra[2].x,ra[2].y), pkh2(ra[2].z,ra[2].w),
                                                             pkh2(ra[3].x,ra[3].y), pkh2(ra[3].z,ra[3].w));
        *(uint4*)(Bs + ldr*HSTR + (ldc>>1)    ) = make_uint4(pkh2(rb[0].x,rb[0].y), pkh2(rb[0].z,rb[0].w),
                                                             pkh2(rb[1].x,rb[1].y), pkh2(rb[1].z,rb[1].w));
        *(uint4*)(Bs + ldr*HSTR + (ldc>>1) + 4) = make_uint4(pkh2(rb[2].x,rb[2].y), pkh2(rb[2].z,rb[2].w),
                                                             pkh2(rb[3].x,rb[3].y), pkh2(rb[3].z,rb[3].w));
    }
    __syncthreads();

    float acc[2][8][4];
    #pragma unroll
    for (int mt = 0; mt < 2; mt++)
        #pragma unroll
        for (int nt = 0; nt < 8; nt++)
            #pragma unroll
            for (int i = 0; i < 4; i++) acc[mt][nt][i] = 0.f;

    int T = K / BK;
    for (int t = 0; t < T; t++){
        int buf = t & 1;
        if (t + 1 < T){
            int k0 = (t+1) * BK;
            #pragma unroll
            for (int i = 0; i < 4; i++){
                ra[i] = *(const float4*)(Hbase + (size_t)ldr*(2*FFm) + k0 + ldc + i*4);
                rg[i] = *(const float4*)(Hbase + (size_t)ldr*(2*FFm) + FFm + k0 + ldc + i*4);
                rb[i] = *(const float4*)(Wbase + (size_t)ldr*K + k0 + ldc + i*4);
            }
        }
        const uint32_t* As = smu + buf*2*HBUF;
        const uint32_t* Bs = smu + buf*2*HBUF + HBUF;
        #pragma unroll
        for (int ks = 0; ks < 2; ks++){
            int k8 = ks * 8;
            uint32_t af[2][4];
            #pragma unroll
            for (int mt = 0; mt < 2; mt++){
                int r0 = warp_m*32 + mt*16 + qr;
                af[mt][0] = As[ r0     *HSTR + k8 + qc];
                af[mt][1] = As[(r0 + 8)*HSTR + k8 + qc];
                af[mt][2] = As[ r0     *HSTR + k8 + 4 + qc];
                af[mt][3] = As[(r0 + 8)*HSTR + k8 + 4 + qc];
            }
            #pragma unroll
            for (int nt = 0; nt < 8; nt++){
                int cb = warp_n*64 + nt*8 + qr;
                uint32_t b0 = Bs[cb*HSTR + k8 + qc];
                uint32_t b1 = Bs[cb*HSTR + k8 + 4 + qc];
                mma_f16(acc[0][nt], af[0], b0, b1);
                mma_f16(acc[1][nt], af[1], b0, b1);
            }
        }
        __syncthreads();
        if (t + 1 < T){
            #pragma unroll
            for (int i = 0; i < 4; i++){
                ra[i].x *= geluf(rg[i].x); ra[i].y *= geluf(rg[i].y);
                ra[i].z *= geluf(rg[i].z); ra[i].w *= geluf(rg[i].w);
            }
            int nbuf = (t+1) & 1;
            uint32_t* Aw = smu + nbuf*2*HBUF;
            uint32_t* Bw = smu + nbuf*2*HBUF + HBUF;
            *(uint4*)(Aw + ldr*HSTR + (ldc>>1)    ) = make_uint4(pkh2(ra[0].x,ra[0].y), pkh2(ra[0].z,ra[0].w),
                                                                 pkh2(ra[1].x,ra[1].y), pkh2(ra[1].z,ra[1].w));
            *(uint4*)(Aw + ldr*HSTR + (ldc>>1) + 4) = make_uint4(pkh2(ra[2].x,ra[2].y), pkh2(ra[2].z,ra[2].w),
                                                                 pkh2(ra[3].x,ra[3].y), pkh2(ra[3].z,ra[3].w));
            *(uint4*)(Bw + ldr*HSTR + (ldc>>1)    ) = make_uint4(pkh2(rb[0].x,rb[0].y), pkh2(rb[0].z,rb[0].w),
                                                                 pkh2(rb[1].x,rb[1].y), pkh2(rb[1].z,rb[1].w));
            *(uint4*)(Bw + ldr*HSTR + (ldc>>1) + 4) = make_uint4(pkh2(rb[2].x,rb[2].y), pkh2(rb[2].z,rb[2].w),
                                                                 pkh2(rb[3].x,rb[3].y), pkh2(rb[3].z,rb[3].w));
            __syncthreads();
        }
    }

    #pragma unroll
    for (int mt = 0; mt < 2; mt++){
        #pragma unroll
        for (int nt = 0; nt < 8; nt++){
            int row = m0 + warp_m*32 + mt*16 + qr;
            int col = n0 + warp_n*64 + nt*8 + qc*2;
            size_t off0 = (size_t)row * Nout + col;
            size_t off1 = (size_t)(row + 8) * Nout + col;
            float2 r0 = *(const float2*)(resid + off0);
            float2 r1 = *(const float2*)(resid + off1);
            *(float2*)(C + off0) = make_float2(acc[mt][nt][0] + r0.x, acc[mt][nt][1] + r0.y);
            *(float2*)(C + off1) = make_float2(acc[mt][nt][2] + r1.x, acc[mt][nt][3] + r1.y);
        }
    }
}

// ---------------- RMSNorm over DIM=512 ----------------
__global__ void rmsnorm_kernel(const float* __restrict__ X,
                               const float* __restrict__ scale,
                               float* __restrict__ Y){
    int row = blockIdx.x;
    int t   = threadIdx.x;  // 128
    const float4* x4 = (const float4*)(X + (size_t)row*DIM);
    float4 v = x4[t];
    float ss = v.x*v.x + v.y*v.y + v.z*v.z + v.w*v.w;
    ss = warpSum(ss);
    __shared__ float red[4];
    if ((t & 31) == 0) red[t >> 5] = ss;
    __syncthreads();
    if (t == 0) red[0] = red[0] + red[1] + red[2] + red[3];
    __syncthreads();
    float inv = rsqrtf(red[0] / (float)DIM + EPSf);
    float4 s = ((const float4*)scale)[t];
    float4 o;
    o.x = v.x * s.x * inv; o.y = v.y * s.y * inv;
    o.z = v.z * s.z * inv; o.w = v.w * s.w * inv;
    ((float4*)(Y + (size_t)row*DIM))[t] = o;
}

// ---------------- per-head RMSNorm + rotary (8 units / 256-thr block) ----------------
__global__ __launch_bounds__(256)
void qkprep_kernel(float* __restrict__ qkv, const float* __restrict__ theta,
                   const float* __restrict__ sq, const float* __restrict__ sk){
    int t = blockIdx.x * 8 + (threadIdx.x >> 5);
    int isK = t & 1; int rest = t >> 1;
    int h = rest % NH; rest /= NH;
    int n = rest % SEQ; int b = rest / SEQ;
    int lane = threadIdx.x & 31;
    float* p = qkv + ((size_t)(b*SEQ + n))*(3*DIM) + isK*DIM + h*HDm;
    float v0 = p[lane], v1 = p[lane + 32];
    float ss = warpSum(v0*v0 + v1*v1);
    float inv = rsqrtf(ss / (float)HDm + EPSf);
    const float* sc = isK ? sk : sq;
    v0 = v0 * sc[lane]      * inv;
    v1 = v1 * sc[lane + 32] * inv;
    float th = theta[(((size_t)(b*NH + h))*SEQ + n)*(HDm/2) + lane];
    float cs = cosf(th), sn = sinf(th);
    float y0 = v0*cs - v1*sn;
    float y1 = v1*cs + v0*sn;
    p[lane]      = y0;
    p[lane + 32] = y1;
}

// ---------------- flash attention, f16 mma.sync ----------------
#define QSTR 36
#define FQ_OFF 0
#define FK_OFF (128*QSTR)
#define FP_OFF (2*128*QSTR)
#define FV_OFF (2*128*QSTR + 128*68)
#define ATTN_SMEM ((2*128*QSTR + 128*68 + 64*68)*4)

__global__ __launch_bounds__(256)
void fattn_kernel(const float* __restrict__ qkv, float* __restrict__ O){
    extern __shared__ uint32_t smu[];
    uint32_t* Qs = smu + FQ_OFF;
    uint32_t* Ks = smu + FK_OFF;
    uint32_t* Ps = smu + FP_OFF;
    uint32_t* Vt = smu + FV_OFF;

    int tid = threadIdx.x;
    int w = tid >> 5, lane = tid & 31;
    int qr = lane >> 2, qc = lane & 3;
    int bh = blockIdx.x >> 4;
    int qt = blockIdx.x & 15;
    int b = bh >> 3, h = bh & 7;
    int i0 = qt * 128;

    int ldr = tid >> 1;
    int ldc = (tid & 1) * 32;

    // load Q tile (f16)
    {
        const float* src = qkv + ((size_t)(b*SEQ + i0 + ldr))*(3*DIM) + h*HDm + ldc;
        float4 q0 = *(const float4*)(src + 0);
        float4 q1 = *(const float4*)(src + 4);
        float4 q2 = *(const float4*)(src + 8);
        float4 q3 = *(const float4*)(src + 12);
        float4 q4 = *(const float4*)(src + 16);
        float4 q5 = *(const float4*)(src + 20);
        float4 q6 = *(const float4*)(src + 24);
        float4 q7 = *(const float4*)(src + 28);
        uint32_t* dst = Qs + ldr*QSTR + (ldc>>1);
        *(uint4*)(dst+ 0) = make_uint4(pkh2(q0.x,q0.y),pkh2(q0.z,q0.w),pkh2(q1.x,q1.y),pkh2(q1.z,q1.w));
        *(uint4*)(dst+ 4) = make_uint4(pkh2(q2.x,q2.y),pkh2(q2.z,q2.w),pkh2(q3.x,q3.y),pkh2(q3.z,q3.w));
        *(uint4*)(dst+ 8) = make_uint4(pkh2(q4.x,q4.y),pkh2(q4.z,q4.w),pkh2(q5.x,q5.y),pkh2(q5.z,q5.w));
        *(uint4*)(dst+12) = make_uint4(pkh2(q6.x,q6.y),pkh2(q6.z,q6.w),pkh2(q7.x,q7.y),pkh2(q7.z,q7.w));
    }
    __syncthreads();

    uint32_t aQ[4][4];
    #pragma unroll
    for (int ks = 0; ks < 4; ks++){
        int r0 = w*16 + qr;
        aQ[ks][0] = Qs[ r0     *QSTR + ks*8 + qc];
        aQ[ks][1] = Qs[(r0 + 8)*QSTR + ks*8 + qc];
        aQ[ks][2] = Qs[ r0     *QSTR + ks*8 + 4 + qc];
        aQ[ks][3] = Qs[(r0 + 8)*QSTR + ks*8 + 4 + qc];
    }

    float Oacc[8][4];
    #pragma unroll
    for (int nt = 0; nt < 8; nt++)
        #pragma unroll
        for (int i = 0; i < 4; i++) Oacc[nt][i] = 0.f;
    float m0 = -INFINITY, m1 = -INFINITY, l0 = 0.f, l1 = 0.f;

    int jp = tid >> 2;
    int dg = (tid & 3) * 16;

    for (int t = 0; t < SEQ/128; t++){
        int j0 = t * 128;
        __syncthreads();
        // load K tile
        {
            const float* src = qkv + ((size_t)(b*SEQ + j0 + ldr))*(3*DIM) + DIM + h*HDm + ldc;
            float4 k0 = *(const float4*)(src + 0);
            float4 k1 = *(const float4*)(src + 4);
            float4 k2 = *(const float4*)(src + 8);
            float4 k3 = *(const float4*)(src + 12);
            float4 k4 = *(const float4*)(src + 16);
            float4 k5 = *(const float4*)(src + 20);
            float4 k6 = *(const float4*)(src + 24);
            float4 k7 = *(const float4*)(src + 28);
            uint32_t* dst = Ks + ldr*QSTR + (ldc>>1);
            *(uint4*)(dst+ 0) = make_uint4(pkh2(k0.x,k0.y),pkh2(k0.z,k0.w),pkh2(k1.x,k1.y),pkh2(k1.z,k1.w));
            *(uint4*)(dst+ 4) = make_uint4(pkh2(k2.x,k2.y),pkh2(k2.z,k2.w),pkh2(k3.x,k3.y),pkh2(k3.z,k3.w));
            *(uint4*)(dst+ 8) = make_uint4(pkh2(k4.x,k4.y),pkh2(k4.z,k4.w),pkh2(k5.x,k5.y),pkh2(k5.z,k5.w));
            *(uint4*)(dst+12) = make_uint4(pkh2(k6.x,k6.y),pkh2(k6.z,k6.w),pkh2(k7.x,k7.y),pkh2(k7.z,k7.w));
        }
        // load V tile transposed (xor swizzle)
        {
            const float* vp = qkv + ((size_t)(b*SEQ + j0 + 2*jp))*(3*DIM) + 2*DIM + h*HDm + dg;
            #pragma unroll
            for (int i = 0; i < 4; i++){
                float4 va = *(const float4*)(vp + i*4);
                float4 vb = *(const float4*)(vp + 3*DIM + i*4);
                int d0 = dg + i*4;
                Vt[(d0+0)*68 + (jp ^ ((((d0+0)>>4)&3)<<3))] = pkh2(va.x, vb.x);
                Vt[(d0+1)*68 + (jp ^ ((((d0+1)>>4)&3)<<3))] = pkh2(va.y, vb.y);
                Vt[(d0+2)*68 + (jp ^ ((((d0+2)>>4)&3)<<3))] = pkh2(va.z, vb.z);
                Vt[(d0+3)*68 + (jp ^ ((((d0+3)>>4)&3)<<3))] = pkh2(va.w, vb.w);
            }
        }
        __syncthreads();

        // S = Q K^T
        float S[16][4];
        #pragma unroll
        for (int nt = 0; nt < 16; nt++){
            S[nt][0] = S[nt][1] = S[nt][2] = S[nt][3] = 0.f;
            #pragma unroll
            for (int ks = 0; ks < 4; ks++){
                int cb = nt*8 + qr;
                uint32_t b0 = Ks[cb*QSTR + ks*8 + qc];
                uint32_t b1 = Ks[cb*QSTR + ks*8 + 4 + qc];
                mma_f16(S[nt], aQ[ks], b0, b1);
            }
        }

        // online softmax
        float mx0 = -INFINITY, mx1 = -INFINITY;
        #pragma unroll
        for (int nt = 0; nt < 16; nt++){
            mx0 = fmaxf(mx0, fmaxf(S[nt][0], S[nt][1]));
            mx1 = fmaxf(mx1, fmaxf(S[nt][2], S[nt][3]));
        }
        mx0 = fmaxf(mx0, __shfl_xor_sync(0xFFFFFFFFu, mx0, 1));
        mx0 = fmaxf(mx0, __shfl_xor_sync(0xFFFFFFFFu, mx0, 2));
        mx1 = fmaxf(mx1, __shfl_xor_sync(0xFFFFFFFFu, mx1, 1));
        mx1 = fmaxf(mx1, __shfl_xor_sync(0xFFFFFFFFu, mx1, 2));
        float nm0 = fmaxf(m0, mx0), nm1 = fmaxf(m1, mx1);
        float sc0 = __expf(m0 - nm0), sc1 = __expf(m1 - nm1);
        m0 = nm0; m1 = nm1;
        float rs0 = 0.f, rs1 = 0.f;
        #pragma unroll
        for (int nt = 0; nt < 16; nt++){
            float p0 = __expf(S[nt][0] - nm0);
            float p1 = __expf(S[nt][1] - nm0);
            float p2 = __expf(S[nt][2] - nm1);
            float p3 = __expf(S[nt][3] - nm1);
            S[nt][0] = p0; S[nt][1] = p1; S[nt][2] = p2; S[nt][3] = p3;
            rs0 += p0 + p1; rs1 += p2 + p3;
        }
        rs0 += __shfl_xor_sync(0xFFFFFFFFu, rs0, 1);
        rs0 += __shfl_xor_sync(0xFFFFFFFFu, rs0, 2);
        rs1 += __shfl_xor_sync(0xFFFFFFFFu, rs1, 1);
        rs1 += __shfl_xor_sync(0xFFFFFFFFu, rs1, 2);
        l0 = l0 * sc0 + rs0;
        l1 = l1 * sc1 + rs1;
        #pragma unroll
        for (int nt = 0; nt < 8; nt++){
            Oacc[nt][0] *= sc0; Oacc[nt][1] *= sc0;
            Oacc[nt][2] *= sc1; Oacc[nt][3] *= sc1;
        }

        // write P tiles to smem (f16)
        {
            int r0 = w*16 + qr, r1 = r0 + 8;
            #pragma unroll
            for (int nt = 0; nt < 16; nt++){
                Ps[r0*68 + nt*4 + qc] = pkh2(S[nt][0], S[nt][1]);
                Ps[r1*68 + nt*4 + qc] = pkh2(S[nt][2], S[nt][3]);
            }
        }
        __syncthreads();

        // O += P V
        #pragma unroll
        for (int ks = 0; ks < 8; ks++){
            uint32_t aP[4];
            int r0 = w*16 + qr, r1 = r0 + 8;
            aP[0] = Ps[r0*68 + ks*8 + qc];
            aP[1] = Ps[r1*68 + ks*8 + qc];
            aP[2] = Ps[r0*68 + ks*8 + 4 + qc];
            aP[3] = Ps[r1*68 + ks*8 + 4 + qc];
            #pragma unroll
            for (int nt = 0; nt < 8; nt++){
                int drow = nt*8 + qr;
                int swz = (nt >> 1) << 3;
                uint32_t b0 = Vt[drow*68 + ((ks*8 + qc) ^ swz)];
                uint32_t b1 = Vt[drow*68 + ((ks*8 + 4 + qc) ^ swz)];
                mma_f16(Oacc[nt], aP, b0, b1);
            }
        }
    }

    float il0 = 1.f / l0, il1 = 1.f / l1;
    int row0 = i0 + w*16 + qr, row1 = row0 + 8;
    #pragma unroll
    for (int nt = 0; nt < 8; nt++){
        int col = h*HDm + nt*8 + 2*qc;
        *(float2*)(O + ((size_t)(b*SEQ) + row0)*DIM + col) =
            make_float2(Oacc[nt][0]*il0, Oacc[nt][1]*il0);
        *(float2*)(O + ((size_t)(b*SEQ) + row1)*DIM + col) =
            make_float2(Oacc[nt][2]*il1, Oacc[nt][3]*il1);
    }
}

// ---------------- launch ----------------
extern "C" void kernel_launch(void* const* d_in, const int* in_sizes, int n_in,
                              void* d_out, int out_size){
    const float* x       = (const float*)d_in[0];
    const float* theta   = (const float*)d_in[1];
    const float* fmaps   = (const float*)d_in[2];
    const float* coords  = (const float*)d_in[3];
    const float* w_corr  = (const float*)d_in[4];
    const float* norm1   = (const float*)d_in[5];
    const float* sq      = (const float*)d_in[6];
    const float* sk      = (const float*)d_in[7];
    const float* w_qkv   = (const float*)d_in[8];
    const float* w_out   = (const float*)d_in[9];
    const float* norm2   = (const float*)d_in[10];
    const float* w_ff1   = (const float*)d_in[11];
    const float* b_ff1   = (const float*)d_in[12];
    const float* w_ff2   = (const float*)d_in[13];
    float* out = (float*)d_out;

    float *p_feats, *p_x, *p_xn, *p_qkv, *p_o, *p_x2, *p_xn2, *p_h;
    cudaGetSymbolAddress((void**)&p_feats, g_feats);
    cudaGetSymbolAddress((void**)&p_x,     g_x);
    cudaGetSymbolAddress((void**)&p_xn,    g_xn);
    cudaGetSymbolAddress((void**)&p_qkv,   g_qkv);
    cudaGetSymbolAddress((void**)&p_o,     g_o);
    cudaGetSymbolAddress((void**)&p_x2,    g_x2);
    cudaGetSymbolAddress((void**)&p_xn2,   g_xn2);
    cudaGetSymbolAddress((void**)&p_h,     g_h);

    static bool cfg = false;
    if (!cfg){
        cudaFuncSetAttribute(fattn_kernel, cudaFuncAttributeMaxDynamicSharedMemorySize,
                             ATTN_SMEM);
        cudaFuncSetAttribute(gemm_mma, cudaFuncAttributeMaxDynamicSharedMemorySize,
                             GEMM_SMEM);
        cudaFuncSetAttribute(gemm_mma_glu, cudaFuncAttributeMaxDynamicSharedMemorySize,
                             GEMM_SMEM);
        cfg = true;
    }

    const int M = Bsz * SEQ;   // 8192

    bilinear_kernel<<<M, C2m>>>(fmaps, coords);
    gemm_mma<<<dim3(DIM/128, M/128), 256, GEMM_SMEM>>>(p_feats, w_corr, nullptr, x, p_x, M, DIM, C2m);
    rmsnorm_kernel<<<M, 128>>>(p_x, norm1, p_xn);
    gemm_mma<<<dim3(3*DIM/128, M/128), 256, GEMM_SMEM>>>(p_xn, w_qkv, nullptr, nullptr, p_qkv, M, 3*DIM, DIM);
    qkprep_kernel<<<M*NH*2/8, 256>>>(p_qkv, theta, sq, sk);
    fattn_kernel<<<Bsz*NH*(SEQ/128), 256, ATTN_SMEM>>>(p_qkv, p_o);
    gemm_mma<<<dim3(DIM/128, M/128), 256, GEMM_SMEM>>>(p_o, w_out, nullptr, p_x, p_x2, M, DIM, DIM);
    rmsnorm_kernel<<<M, 128>>>(p_x2, norm2, p_xn2);
    gemm_mma<<<dim3(2*FFm/128, M/128), 256, GEMM_SMEM>>>(p_xn2, w_ff1, b_ff1, nullptr, p_h, M, 2*FFm, DIM);
    gemm_mma_glu<<<dim3(DIM/128, M/128), 256, GEMM_SMEM>>>(p_h, w_ff2, p_x2, out, M, DIM, FFm);
}

// round 12
// speedup vs baseline: 9.1031x; 1.2603x over previous
#include <cuda_runtime.h>
#include <cuda_fp16.h>
#include <math.h>
#include <stdint.h>

#define Bsz 4
#define SEQ 2048
#define DIM 512
#define NH  8
#define HDm 64
#define FFm 1024
#define C2m 128
#define HFm 64
#define WFm 64
#define EPSf 1e-6f

// ---------------- static scratch ----------------
// f32
__device__ float g_x   [Bsz*SEQ*DIM];
__device__ float g_qkv [Bsz*SEQ*3*DIM];
__device__ float g_x2  [Bsz*SEQ*DIM];
__device__ float g_h   [Bsz*SEQ*2*FFm];
// f16 activations
__device__ __half g_feats_h[Bsz*SEQ*C2m];
__device__ __half g_xn_h  [Bsz*SEQ*DIM];
__device__ __half g_o_h   [Bsz*SEQ*DIM];
__device__ __half g_xn2_h [Bsz*SEQ*DIM];
__device__ __half g_hg_h  [Bsz*SEQ*FFm];
// f16 weights
__device__ __half g_wcorr_h[DIM*C2m];
__device__ __half g_wqkv_h [3*DIM*DIM];
__device__ __half g_wout_h [DIM*DIM];
__device__ __half g_wff1_h [2*FFm*DIM];
__device__ __half g_wff2_h [DIM*FFm];

__device__ __forceinline__ float warpSum(float v){
    #pragma unroll
    for (int o = 16; o > 0; o >>= 1) v += __shfl_xor_sync(0xFFFFFFFFu, v, o);
    return v;
}
__device__ __forceinline__ uint32_t pkh2(float x, float y){
    __half2 h = __floats2half2_rn(x, y);
    return *reinterpret_cast<uint32_t*>(&h);
}
__device__ __forceinline__ float geluf(float g){
    return 0.5f * g * (1.f + erff(g * 0.70710678118654752f));
}
__device__ __forceinline__ void mma_f16(float* c, const uint32_t* a, uint32_t b0, uint32_t b1){
    asm volatile(
        "mma.sync.aligned.m16n8k16.row.col.f32.f16.f16.f32 "
        "{%0,%1,%2,%3}, {%4,%5,%6,%7}, {%8,%9}, {%0,%1,%2,%3};"
        : "+f"(c[0]), "+f"(c[1]), "+f"(c[2]), "+f"(c[3])
        : "r"(a[0]), "r"(a[1]), "r"(a[2]), "r"(a[3]), "r"(b0), "r"(b1));
}
__device__ __forceinline__ void cp16(uint32_t smaddr, const void* g){
    asm volatile("cp.async.cg.shared.global [%0], [%1], 16;" :: "r"(smaddr), "l"(g));
}
#define CP_COMMIT() asm volatile("cp.async.commit_group;" ::: "memory")
#define CP_WAIT2()  asm volatile("cp.async.wait_group 2;" ::: "memory")

// ---------------- f32 -> f16 convert ----------------
__global__ void f2h_kernel(const float* __restrict__ src, __half* __restrict__ dst){
    int i = blockIdx.x * 256 + threadIdx.x;
    float4 v = ((const float4*)src)[i];
    ((uint2*)dst)[i] = make_uint2(pkh2(v.x, v.y), pkh2(v.z, v.w));
}

// ---------------- bilinear (writes f16 feats) ----------------
__global__ void bilinear_kernel(const float* __restrict__ fmaps,
                                const float* __restrict__ coords){
    int bn = blockIdx.x;
    int b  = bn / SEQ;
    int c  = threadIdx.x;
    float xc = coords[(size_t)bn*2 + 0];
    float yc = coords[(size_t)bn*2 + 1];
    xc = fminf(fmaxf(xc, 0.f), (float)(WFm-1));
    yc = fminf(fmaxf(yc, 0.f), (float)(HFm-1));
    float x0 = floorf(xc), y0 = floorf(yc);
    float wx = xc - x0,    wy = yc - y0;
    int x0i = (int)x0, y0i = (int)y0;
    int x1i = min(x0i+1, WFm-1), y1i = min(y0i+1, HFm-1);
    const float* img = fmaps + ((size_t)(b*C2m + c))*HFm*WFm;
    float f00 = img[y0i*WFm + x0i];
    float f01 = img[y0i*WFm + x1i];
    float f10 = img[y1i*WFm + x0i];
    float f11 = img[y1i*WFm + x1i];
    float top = f00*(1.f-wx) + f01*wx;
    float bot = f10*(1.f-wx) + f11*wx;
    g_feats_h[(size_t)bn*C2m + c] = __float2half(top*(1.f-wy) + bot*wy);
}

// ---------------- f16 GEMM with cp.async 4-stage pipeline ----------------
// C[M,Nout] = A[M,K](f16) @ W[Nout,K](f16)^T (+bias f32)(+resid f32), C f32.
// 128x128 tile, BK=32 panel. One __syncthreads per panel.
#define BK 32
#define HSTR 20                         // u32 row stride (40 halfs: 32 data + pad)
#define PANEL_U32 (128*HSTR)            // 2560 u32 = 10240 B
#define STAGE_U32 (2*PANEL_U32)
#define GEMM_SMEM (4*STAGE_U32*4)       // 81920 B

__global__ __launch_bounds__(256, 2)
void gemm_f16(const __half* __restrict__ A, const __half* __restrict__ W,
              const float* __restrict__ bias, const float* __restrict__ resid,
              float* __restrict__ C, int M, int Nout, int K){
    extern __shared__ uint32_t smu[];
    uint32_t smbase = (uint32_t)__cvta_generic_to_shared(smu);
    int tid = threadIdx.x;
    int wid = tid >> 5, lane = tid & 31;
    int qr = lane >> 2, qc = lane & 3;
    int warp_m = wid & 3, warp_n = wid >> 2;
    int m0 = blockIdx.y * 128, n0 = blockIdx.x * 128;

    const __half* Ab = A + (size_t)m0 * K;
    const __half* Wb = W + (size_t)n0 * K;
    int crow = tid >> 1;            // 0..127
    int ccol = (tid & 1) * 2;       // chunk col {0,2}

    int T = K / BK;

    // prologue: issue up to 3 panels
    #pragma unroll
    for (int s = 0; s < 3; s++){
        if (s < T){
            int k0 = s * BK;
            uint32_t base = smbase + (s & 3) * (STAGE_U32*4);
            const __half* as = Ab + (size_t)crow*K + k0 + ccol*8;
            const __half* ws = Wb + (size_t)crow*K + k0 + ccol*8;
            uint32_t da = base + crow*80 + ccol*16;
            uint32_t db = base + PANEL_U32*4 + crow*80 + ccol*16;
            cp16(da, as);      cp16(da + 16, as + 8);
            cp16(db, ws);      cp16(db + 16, ws + 8);
        }
        CP_COMMIT();
    }

    float acc[2][8][4];
    #pragma unroll
    for (int mt = 0; mt < 2; mt++)
        #pragma unroll
        for (int nt = 0; nt < 8; nt++)
            #pragma unroll
            for (int i = 0; i < 4; i++) acc[mt][nt][i] = 0.f;

    for (int t = 0; t < T; t++){
        CP_WAIT2();
        __syncthreads();
        // issue panel t+3 into buf (t+3)&3 (safe: its last readers finished before this barrier)
        if (t + 3 < T){
            int k0 = (t+3) * BK;
            uint32_t base = smbase + ((t+3) & 3) * (STAGE_U32*4);
            const __half* as = Ab + (size_t)crow*K + k0 + ccol*8;
            const __half* ws = Wb + (size_t)crow*K + k0 + ccol*8;
            uint32_t da = base + crow*80 + ccol*16;
            uint32_t db = base + PANEL_U32*4 + crow*80 + ccol*16;
            cp16(da, as);      cp16(da + 16, as + 8);
            cp16(db, ws);      cp16(db + 16, ws + 8);
        }
        CP_COMMIT();

        const uint32_t* As = smu + (t & 3) * STAGE_U32;
        const uint32_t* Bs = As + PANEL_U32;
        #pragma unroll
        for (int ks = 0; ks < 2; ks++){
            int k8 = ks * 8;
            uint32_t af[2][4];
            #pragma unroll
            for (int mt = 0; mt < 2; mt++){
                int r0 = warp_m*32 + mt*16 + qr;
                af[mt][0] = As[ r0     *HSTR + k8 + qc];
                af[mt][1] = As[(r0 + 8)*HSTR + k8 + qc];
                af[mt][2] = As[ r0     *HSTR + k8 + 4 + qc];
                af[mt][3] = As[(r0 + 8)*HSTR + k8 + 4 + qc];
            }
            #pragma unroll
            for (int nt = 0; nt < 8; nt++){
                int cb = warp_n*64 + nt*8 + qr;
                uint32_t b0 = Bs[cb*HSTR + k8 + qc];
                uint32_t b1 = Bs[cb*HSTR + k8 + 4 + qc];
                mma_f16(acc[0][nt], af[0], b0, b1);
                mma_f16(acc[1][nt], af[1], b0, b1);
            }
        }
    }

    #pragma unroll
    for (int mt = 0; mt < 2; mt++){
        #pragma unroll
        for (int nt = 0; nt < 8; nt++){
            int row = m0 + warp_m*32 + mt*16 + qr;
            int col = n0 + warp_n*64 + nt*8 + qc*2;
            float2 v0 = make_float2(acc[mt][nt][0], acc[mt][nt][1]);
            float2 v1 = make_float2(acc[mt][nt][2], acc[mt][nt][3]);
            if (bias){
                float2 bb = *(const float2*)(bias + col);
                v0.x += bb.x; v0.y += bb.y;
                v1.x += bb.x; v1.y += bb.y;
            }
            size_t off0 = (size_t)row * Nout + col;
            size_t off1 = (size_t)(row + 8) * Nout + col;
            if (resid){
                float2 r0 = *(const float2*)(resid + off0);
                float2 r1 = *(const float2*)(resid + off1);
                v0.x += r0.x; v0.y += r0.y;
                v1.x += r1.x; v1.y += r1.y;
            }
            *(float2*)(C + off0) = v0;
            *(float2*)(C + off1) = v1;
        }
    }
}

// ---------------- RMSNorm over DIM=512 (f32 in, f16 out) ----------------
__global__ void rmsnorm_kernel(const float* __restrict__ X,
                               const float* __restrict__ scale,
                               __half* __restrict__ Y){
    int row = blockIdx.x;
    int t   = threadIdx.x;  // 128
    const float4* x4 = (const float4*)(X + (size_t)row*DIM);
    float4 v = x4[t];
    float ss = v.x*v.x + v.y*v.y + v.z*v.z + v.w*v.w;
    ss = warpSum(ss);
    __shared__ float red[4];
    if ((t & 31) == 0) red[t >> 5] = ss;
    __syncthreads();
    if (t == 0) red[0] = red[0] + red[1] + red[2] + red[3];
    __syncthreads();
    float inv = rsqrtf(red[0] / (float)DIM + EPSf);
    float4 s = ((const float4*)scale)[t];
    ((uint2*)(Y + (size_t)row*DIM))[t] =
        make_uint2(pkh2(v.x*s.x*inv, v.y*s.y*inv), pkh2(v.z*s.z*inv, v.w*s.w*inv));
}

// ---------------- per-head RMSNorm + rotary (f32 qkv in-place) ----------------
__global__ __launch_bounds__(256)
void qkprep_kernel(float* __restrict__ qkv, const float* __restrict__ theta,
                   const float* __restrict__ sq, const float* __restrict__ sk){
    int t = blockIdx.x * 8 + (threadIdx.x >> 5);
    int isK = t & 1; int rest = t >> 1;
    int h = rest % NH; rest /= NH;
    int n = rest % SEQ; int b = rest / SEQ;
    int lane = threadIdx.x & 31;
    float* p = qkv + ((size_t)(b*SEQ + n))*(3*DIM) + isK*DIM + h*HDm;
    float v0 = p[lane], v1 = p[lane + 32];
    float ss = warpSum(v0*v0 + v1*v1);
    float inv = rsqrtf(ss / (float)HDm + EPSf);
    const float* sc = isK ? sk : sq;
    v0 = v0 * sc[lane]      * inv;
    v1 = v1 * sc[lane + 32] * inv;
    float th = theta[(((size_t)(b*NH + h))*SEQ + n)*(HDm/2) + lane];
    float cs = cosf(th), sn = sinf(th);
    float y0 = v0*cs - v1*sn;
    float y1 = v1*cs + v0*sn;
    p[lane]      = y0;
    p[lane + 32] = y1;
}

// ---------------- flash attention, f16 mma.sync (O out as f16) ----------------
#define QSTR 36
#define FQ_OFF 0
#define FK_OFF (128*QSTR)
#define FP_OFF (2*128*QSTR)
#define FV_OFF (2*128*QSTR + 128*68)
#define ATTN_SMEM ((2*128*QSTR + 128*68 + 64*68)*4)

__global__ __launch_bounds__(256)
void fattn_kernel(const float* __restrict__ qkv, __half* __restrict__ O){
    extern __shared__ uint32_t smu[];
    uint32_t* Qs = smu + FQ_OFF;
    uint32_t* Ks = smu + FK_OFF;
    uint32_t* Ps = smu + FP_OFF;
    uint32_t* Vt = smu + FV_OFF;

    int tid = threadIdx.x;
    int w = tid >> 5, lane = tid & 31;
    int qr = lane >> 2, qc = lane & 3;
    int bh = blockIdx.x >> 4;
    int qt = blockIdx.x & 15;
    int b = bh >> 3, h = bh & 7;
    int i0 = qt * 128;

    int ldr = tid >> 1;
    int ldc = (tid & 1) * 32;

    // load Q tile (f16)
    {
        const float* src = qkv + ((size_t)(b*SEQ + i0 + ldr))*(3*DIM) + h*HDm + ldc;
        float4 q0 = *(const float4*)(src + 0);
        float4 q1 = *(const float4*)(src + 4);
        float4 q2 = *(const float4*)(src + 8);
        float4 q3 = *(const float4*)(src + 12);
        float4 q4 = *(const float4*)(src + 16);
        float4 q5 = *(const float4*)(src + 20);
        float4 q6 = *(const float4*)(src + 24);
        float4 q7 = *(const float4*)(src + 28);
        uint32_t* dst = Qs + ldr*QSTR + (ldc>>1);
        *(uint4*)(dst+ 0) = make_uint4(pkh2(q0.x,q0.y),pkh2(q0.z,q0.w),pkh2(q1.x,q1.y),pkh2(q1.z,q1.w));
        *(uint4*)(dst+ 4) = make_uint4(pkh2(q2.x,q2.y),pkh2(q2.z,q2.w),pkh2(q3.x,q3.y),pkh2(q3.z,q3.w));
        *(uint4*)(dst+ 8) = make_uint4(pkh2(q4.x,q4.y),pkh2(q4.z,q4.w),pkh2(q5.x,q5.y),pkh2(q5.z,q5.w));
        *(uint4*)(dst+12) = make_uint4(pkh2(q6.x,q6.y),pkh2(q6.z,q6.w),pkh2(q7.x,q7.y),pkh2(q7.z,q7.w));
    }
    __syncthreads();

    uint32_t aQ[4][4];
    #pragma unroll
    for (int ks = 0; ks < 4; ks++){
        int r0 = w*16 + qr;
        aQ[ks][0] = Qs[ r0     *QSTR + ks*8 + qc];
        aQ[ks][1] = Qs[(r0 + 8)*QSTR + ks*8 + qc];
        aQ[ks][2] = Qs[ r0     *QSTR + ks*8 + 4 + qc];
        aQ[ks][3] = Qs[(r0 + 8)*QSTR + ks*8 + 4 + qc];
    }

    float Oacc[8][4];
    #pragma unroll
    for (int nt = 0; nt < 8; nt++)
        #pragma unroll
        for (int i = 0; i < 4; i++) Oacc[nt][i] = 0.f;
    float m0 = -INFINITY, m1 = -INFINITY, l0 = 0.f, l1 = 0.f;

    int jp = tid >> 2;
    int dg = (tid & 3) * 16;

    for (int t = 0; t < SEQ/128; t++){
        int j0 = t * 128;
        __syncthreads();
        // load K tile
        {
            const float* src = qkv + ((size_t)(b*SEQ + j0 + ldr))*(3*DIM) + DIM + h*HDm + ldc;
            float4 k0 = *(const float4*)(src + 0);
            float4 k1 = *(const float4*)(src + 4);
            float4 k2 = *(const float4*)(src + 8);
            float4 k3 = *(const float4*)(src + 12);
            float4 k4 = *(const float4*)(src + 16);
            float4 k5 = *(const float4*)(src + 20);
            float4 k6 = *(const float4*)(src + 24);
            float4 k7 = *(const float4*)(src + 28);
            uint32_t* dst = Ks + ldr*QSTR + (ldc>>1);
            *(uint4*)(dst+ 0) = make_uint4(pkh2(k0.x,k0.y),pkh2(k0.z,k0.w),pkh2(k1.x,k1.y),pkh2(k1.z,k1.w));
            *(uint4*)(dst+ 4) = make_uint4(pkh2(k2.x,k2.y),pkh2(k2.z,k2.w),pkh2(k3.x,k3.y),pkh2(k3.z,k3.w));
            *(uint4*)(dst+ 8) = make_uint4(pkh2(k4.x,k4.y),pkh2(k4.z,k4.w),pkh2(k5.x,k5.y),pkh2(k5.z,k5.w));
            *(uint4*)(dst+12) = make_uint4(pkh2(k6.x,k6.y),pkh2(k6.z,k6.w),pkh2(k7.x,k7.y),pkh2(k7.z,k7.w));
        }
        // load V tile transposed (xor swizzle)
        {
            const float* vp = qkv + ((size_t)(b*SEQ + j0 + 2*jp))*(3*DIM) + 2*DIM + h*HDm + dg;
            #pragma unroll
            for (int i = 0; i < 4; i++){
                float4 va = *(const float4*)(vp + i*4);
                float4 vb = *(const float4*)(vp + 3*DIM + i*4);
                int d0 = dg + i*4;
                Vt[(d0+0)*68 + (jp ^ ((((d0+0)>>4)&3)<<3))] = pkh2(va.x, vb.x);
                Vt[(d0+1)*68 + (jp ^ ((((d0+1)>>4)&3)<<3))] = pkh2(va.y, vb.y);
                Vt[(d0+2)*68 + (jp ^ ((((d0+2)>>4)&3)<<3))] = pkh2(va.z, vb.z);
                Vt[(d0+3)*68 + (jp ^ ((((d0+3)>>4)&3)<<3))] = pkh2(va.w, vb.w);
            }
        }
        __syncthreads();

        // S = Q K^T
        float S[16][4];
        #pragma unroll
        for (int nt = 0; nt < 16; nt++){
            S[nt][0] = S[nt][1] = S[nt][2] = S[nt][3] = 0.f;
            #pragma unroll
            for (int ks = 0; ks < 4; ks++){
                int cb = nt*8 + qr;
                uint32_t b0 = Ks[cb*QSTR + ks*8 + qc];
                uint32_t b1 = Ks[cb*QSTR + ks*8 + 4 + qc];
                mma_f16(S[nt], aQ[ks], b0, b1);
            }
        }

        // online softmax
        float mx0 = -INFINITY, mx1 = -INFINITY;
        #pragma unroll
        for (int nt = 0; nt < 16; nt++){
            mx0 = fmaxf(mx0, fmaxf(S[nt][0], S[nt][1]));
            mx1 = fmaxf(mx1, fmaxf(S[nt][2], S[nt][3]));
        }
        mx0 = fmaxf(mx0, __shfl_xor_sync(0xFFFFFFFFu, mx0, 1));
        mx0 = fmaxf(mx0, __shfl_xor_sync(0xFFFFFFFFu, mx0, 2));
        mx1 = fmaxf(mx1, __shfl_xor_sync(0xFFFFFFFFu, mx1, 1));
        mx1 = fmaxf(mx1, __shfl_xor_sync(0xFFFFFFFFu, mx1, 2));
        float nm0 = fmaxf(m0, mx0), nm1 = fmaxf(m1, mx1);
        float sc0 = __expf(m0 - nm0), sc1 = __expf(m1 - nm1);
        m0 = nm0; m1 = nm1;
        float rs0 = 0.f, rs1 = 0.f;
        #pragma unroll
        for (int nt = 0; nt < 16; nt++){
            float p0 = __expf(S[nt][0] - nm0);
            float p1 = __expf(S[nt][1] - nm0);
            float p2 = __expf(S[nt][2] - nm1);
            float p3 = __expf(S[nt][3] - nm1);
            S[nt][0] = p0; S[nt][1] = p1; S[nt][2] = p2; S[nt][3] = p3;
            rs0 += p0 + p1; rs1 += p2 + p3;
        }
        rs0 += __shfl_xor_sync(0xFFFFFFFFu, rs0, 1);
        rs0 += __shfl_xor_sync(0xFFFFFFFFu, rs0, 2);
        rs1 += __shfl_xor_sync(0xFFFFFFFFu, rs1, 1);
        rs1 += __shfl_xor_sync(0xFFFFFFFFu, rs1, 2);
        l0 = l0 * sc0 + rs0;
        l1 = l1 * sc1 + rs1;
        #pragma unroll
        for (int nt = 0; nt < 8; nt++){
            Oacc[nt][0] *= sc0; Oacc[nt][1] *= sc0;
            Oacc[nt][2] *= sc1; Oacc[nt][3] *= sc1;
        }

        // write P tiles to smem (f16)
        {
            int r0 = w*16 + qr, r1 = r0 + 8;
            #pragma unroll
            for (int nt = 0; nt < 16; nt++){
                Ps[r0*68 + nt*4 + qc] = pkh2(S[nt][0], S[nt][1]);
                Ps[r1*68 + nt*4 + qc] = pkh2(S[nt][2], S[nt][3]);
            }
        }
        __syncthreads();

        // O += P V
        #pragma unroll
        for (int ks = 0; ks < 8; ks++){
            uint32_t aP[4];
            int r0 = w*16 + qr, r1 = r0 + 8;
            aP[0] = Ps[r0*68 + ks*8 + qc];
            aP[1] = Ps[r1*68 + ks*8 + qc];
            aP[2] = Ps[r0*68 + ks*8 + 4 + qc];
            aP[3] = Ps[r1*68 + ks*8 + 4 + qc];
            #pragma unroll
            for (int nt = 0; nt < 8; nt++){
                int drow = nt*8 + qr;
                int swz = (nt >> 1) << 3;
                uint32_t b0 = Vt[drow*68 + ((ks*8 + qc) ^ swz)];
                uint32_t b1 = Vt[drow*68 + ((ks*8 + 4 + qc) ^ swz)];
                mma_f16(Oacc[nt], aP, b0, b1);
            }
        }
    }

    // epilogue: write f16 O
    float il0 = 1.f / l0, il1 = 1.f / l1;
    int row0 = i0 + w*16 + qr, row1 = row0 + 8;
    #pragma unroll
    for (int nt = 0; nt < 8; nt++){
        int col = h*HDm + nt*8 + 2*qc;
        *(uint32_t*)(O + ((size_t)(b*SEQ) + row0)*DIM + col) =
            pkh2(Oacc[nt][0]*il0, Oacc[nt][1]*il0);
        *(uint32_t*)(O + ((size_t)(b*SEQ) + row1)*DIM + col) =
            pkh2(Oacc[nt][2]*il1, Oacc[nt][3]*il1);
    }
}

// ---------------- gated GELU (f32 in, f16 out) ----------------
__global__ void glu_kernel(const float* __restrict__ Hh, __half* __restrict__ Hg){
    size_t i4 = ((size_t)blockIdx.x * 256 + threadIdx.x) * 4;
    size_t m = i4 / FFm, f = i4 % FFm;
    float4 hx = *(const float4*)(Hh + m*(2*FFm) + f);
    float4 g  = *(const float4*)(Hh + m*(2*FFm) + FFm + f);
    *(uint2*)(Hg + i4) = make_uint2(
        pkh2(hx.x * geluf(g.x), hx.y * geluf(g.y)),
        pkh2(hx.z * geluf(g.z), hx.w * geluf(g.w)));
}

// ---------------- launch ----------------
extern "C" void kernel_launch(void* const* d_in, const int* in_sizes, int n_in,
                              void* d_out, int out_size){
    const float* x       = (const float*)d_in[0];
    const float* theta   = (const float*)d_in[1];
    const float* fmaps   = (const float*)d_in[2];
    const float* coords  = (const float*)d_in[3];
    const float* w_corr  = (const float*)d_in[4];
    const float* norm1   = (const float*)d_in[5];
    const float* sq      = (const float*)d_in[6];
    const float* sk      = (const float*)d_in[7];
    const float* w_qkv   = (const float*)d_in[8];
    const float* w_out   = (const float*)d_in[9];
    const float* norm2   = (const float*)d_in[10];
    const float* w_ff1   = (const float*)d_in[11];
    const float* b_ff1   = (const float*)d_in[12];
    const float* w_ff2   = (const float*)d_in[13];
    float* out = (float*)d_out;

    float *p_x, *p_qkv, *p_x2, *p_h;
    __half *p_feats, *p_xn, *p_o, *p_xn2, *p_hg;
    __half *p_wc, *p_wq, *p_wo, *p_w1, *p_w2;
    cudaGetSymbolAddress((void**)&p_x,     g_x);
    cudaGetSymbolAddress((void**)&p_qkv,   g_qkv);
    cudaGetSymbolAddress((void**)&p_x2,    g_x2);
    cudaGetSymbolAddress((void**)&p_h,     g_h);
    cudaGetSymbolAddress((void**)&p_feats, g_feats_h);
    cudaGetSymbolAddress((void**)&p_xn,    g_xn_h);
    cudaGetSymbolAddress((void**)&p_o,     g_o_h);
    cudaGetSymbolAddress((void**)&p_xn2,   g_xn2_h);
    cudaGetSymbolAddress((void**)&p_hg,    g_hg_h);
    cudaGetSymbolAddress((void**)&p_wc,    g_wcorr_h);
    cudaGetSymbolAddress((void**)&p_wq,    g_wqkv_h);
    cudaGetSymbolAddress((void**)&p_wo,    g_wout_h);
    cudaGetSymbolAddress((void**)&p_w1,    g_wff1_h);
    cudaGetSymbolAddress((void**)&p_w2,    g_wff2_h);

    static bool cfg = false;
    if (!cfg){
        cudaFuncSetAttribute(fattn_kernel, cudaFuncAttributeMaxDynamicSharedMemorySize,
                             ATTN_SMEM);
        cudaFuncSetAttribute(gemm_f16, cudaFuncAttributeMaxDynamicSharedMemorySize,
                             GEMM_SMEM);
        cfg = true;
    }

    const int M = Bsz * SEQ;   // 8192

    // weight conversions (independent of data pipeline start)
    f2h_kernel<<<(DIM*C2m)/1024, 256>>>(w_corr, p_wc);
    f2h_kernel<<<(3*DIM*DIM)/1024, 256>>>(w_qkv, p_wq);
    f2h_kernel<<<(DIM*DIM)/1024, 256>>>(w_out, p_wo);
    f2h_kernel<<<(2*FFm*DIM)/1024, 256>>>(w_ff1, p_w1);
    f2h_kernel<<<(DIM*FFm)/1024, 256>>>(w_ff2, p_w2);

    bilinear_kernel<<<M, C2m>>>(fmaps, coords);
    gemm_f16<<<dim3(DIM/128, M/128), 256, GEMM_SMEM>>>(p_feats, p_wc, nullptr, x, p_x, M, DIM, C2m);
    rmsnorm_kernel<<<M, 128>>>(p_x, norm1, p_xn);
    gemm_f16<<<dim3(3*DIM/128, M/128), 256, GEMM_SMEM>>>(p_xn, p_wq, nullptr, nullptr, p_qkv, M, 3*DIM, DIM);
    qkprep_kernel<<<M*NH*2/8, 256>>>(p_qkv, theta, sq, sk);
    fattn_kernel<<<Bsz*NH*(SEQ/128), 256, ATTN_SMEM>>>(p_qkv, p_o);
    gemm_f16<<<dim3(DIM/128, M/128), 256, GEMM_SMEM>>>(p_o, p_wo, nullptr, p_x, p_x2, M, DIM, DIM);
    rmsnorm_kernel<<<M, 128>>>(p_x2, norm2, p_xn2);
    gemm_f16<<<dim3(2*FFm/128, M/128), 256, GEMM_SMEM>>>(p_xn2, p_w1, b_ff1, nullptr, p_h, M, 2*FFm, DIM);
    glu_kernel<<<(Bsz*SEQ*FFm)/1024, 256>>>(p_h, p_hg);
    gemm_f16<<<dim3(DIM/128, M/128), 256, GEMM_SMEM>>>(p_hg, p_w2, nullptr, p_x2, out, M, DIM, FFm);
}

// round 13
// speedup vs baseline: 10.5885x; 1.1632x over previous
#include <cuda_runtime.h>
#include <cuda_fp16.h>
#include <math.h>
#include <stdint.h>

#define Bsz 4
#define SEQ 2048
#define DIM 512
#define NH  8
#define HDm 64
#define FFm 1024
#define C2m 128
#define HFm 64
#define WFm 64
#define EPSf 1e-6f

// ---------------- static scratch ----------------
// f32
__device__ float g_x   [Bsz*SEQ*DIM];
__device__ float g_x2  [Bsz*SEQ*DIM];
__device__ float g_h   [Bsz*SEQ*2*FFm];
// f16 activations
__device__ __half g_feats_h[Bsz*SEQ*C2m];
__device__ __half g_xn_h  [Bsz*SEQ*DIM];
__device__ __half g_qkv_h [Bsz*SEQ*3*DIM];
__device__ __half g_o_h   [Bsz*SEQ*DIM];
__device__ __half g_xn2_h [Bsz*SEQ*DIM];
__device__ __half g_hg_h  [Bsz*SEQ*FFm];
// f16 weights
__device__ __half g_wcorr_h[DIM*C2m];
__device__ __half g_wqkv_h [3*DIM*DIM];
__device__ __half g_wout_h [DIM*DIM];
__device__ __half g_wff1_h [2*FFm*DIM];
__device__ __half g_wff2_h [DIM*FFm];

__device__ __forceinline__ float warpSum(float v){
    #pragma unroll
    for (int o = 16; o > 0; o >>= 1) v += __shfl_xor_sync(0xFFFFFFFFu, v, o);
    return v;
}
__device__ __forceinline__ uint32_t pkh2(float x, float y){
    __half2 h = __floats2half2_rn(x, y);
    return *reinterpret_cast<uint32_t*>(&h);
}
__device__ __forceinline__ float geluf(float g){
    return 0.5f * g * (1.f + erff(g * 0.70710678118654752f));
}
__device__ __forceinline__ void mma_f16(float* c, const uint32_t* a, uint32_t b0, uint32_t b1){
    asm volatile(
        "mma.sync.aligned.m16n8k16.row.col.f32.f16.f16.f32 "
        "{%0,%1,%2,%3}, {%4,%5,%6,%7}, {%8,%9}, {%0,%1,%2,%3};"
        : "+f"(c[0]), "+f"(c[1]), "+f"(c[2]), "+f"(c[3])
        : "r"(a[0]), "r"(a[1]), "r"(a[2]), "r"(a[3]), "r"(b0), "r"(b1));
}
__device__ __forceinline__ void cp16(uint32_t smaddr, const void* g){
    asm volatile("cp.async.cg.shared.global [%0], [%1], 16;" :: "r"(smaddr), "l"(g));
}
#define CP_COMMIT() asm volatile("cp.async.commit_group;" ::: "memory")
#define CP_WAIT2()  asm volatile("cp.async.wait_group 2;" ::: "memory")

// ---------------- fused weight conversion (all 5 weights, one kernel) ----------------
#define WC_N0 ((DIM*C2m)/4)
#define WC_N1 ((3*DIM*DIM)/4)
#define WC_N2 ((DIM*DIM)/4)
#define WC_N3 ((2*FFm*DIM)/4)
#define WC_N4 ((DIM*FFm)/4)
#define WC_TOT (WC_N0+WC_N1+WC_N2+WC_N3+WC_N4)
__global__ void wconv_kernel(const float* __restrict__ s0, const float* __restrict__ s1,
                             const float* __restrict__ s2, const float* __restrict__ s3,
                             const float* __restrict__ s4){
    int i = blockIdx.x * 256 + threadIdx.x;
    if (i >= WC_TOT) return;
    const float* src; __half* dst;
    if (i < WC_N0){ src = s0; dst = g_wcorr_h; }
    else if ((i -= WC_N0) < WC_N1){ src = s1; dst = g_wqkv_h; }
    else if ((i -= WC_N1) < WC_N2){ src = s2; dst = g_wout_h; }
    else if ((i -= WC_N2) < WC_N3){ src = s3; dst = g_wff1_h; }
    else { i -= WC_N3; src = s4; dst = g_wff2_h; }
    float4 v = ((const float4*)src)[i];
    ((uint2*)dst)[i] = make_uint2(pkh2(v.x, v.y), pkh2(v.z, v.w));
}

// ---------------- bilinear (writes f16 feats) ----------------
__global__ void bilinear_kernel(const float* __restrict__ fmaps,
                                const float* __restrict__ coords){
    int bn = blockIdx.x;
    int b  = bn / SEQ;
    int c  = threadIdx.x;
    float xc = coords[(size_t)bn*2 + 0];
    float yc = coords[(size_t)bn*2 + 1];
    xc = fminf(fmaxf(xc, 0.f), (float)(WFm-1));
    yc = fminf(fmaxf(yc, 0.f), (float)(HFm-1));
    float x0 = floorf(xc), y0 = floorf(yc);
    float wx = xc - x0,    wy = yc - y0;
    int x0i = (int)x0, y0i = (int)y0;
    int x1i = min(x0i+1, WFm-1), y1i = min(y0i+1, HFm-1);
    const float* img = fmaps + ((size_t)(b*C2m + c))*HFm*WFm;
    float f00 = img[y0i*WFm + x0i];
    float f01 = img[y0i*WFm + x1i];
    float f10 = img[y1i*WFm + x0i];
    float f11 = img[y1i*WFm + x1i];
    float top = f00*(1.f-wx) + f01*wx;
    float bot = f10*(1.f-wx) + f11*wx;
    g_feats_h[(size_t)bn*C2m + c] = __float2half(top*(1.f-wy) + bot*wy);
}

// ---------------- f16 GEMM with cp.async 4-stage pipeline (f32 out) ----------------
#define BK 32
#define HSTR 20
#define PANEL_U32 (128*HSTR)
#define STAGE_U32 (2*PANEL_U32)
#define GEMM_SMEM (4*STAGE_U32*4)

// shared mainloop body via macro to keep both epilogue variants in sync
#define GEMM_BODY(EPILOGUE)                                                     \
    extern __shared__ uint32_t smu[];                                           \
    uint32_t smbase = (uint32_t)__cvta_generic_to_shared(smu);                  \
    int tid = threadIdx.x;                                                      \
    int wid = tid >> 5, lane = tid & 31;                                        \
    int qr = lane >> 2, qc = lane & 3;                                          \
    int warp_m = wid & 3, warp_n = wid >> 2;                                    \
    int m0 = blockIdx.y * 128, n0 = blockIdx.x * 128;                           \
    const __half* Ab = A + (size_t)m0 * K;                                      \
    const __half* Wb = W + (size_t)n0 * K;                                      \
    int crow = tid >> 1;                                                        \
    int ccol = (tid & 1) * 2;                                                   \
    int T = K / BK;                                                             \
    _Pragma("unroll")                                                           \
    for (int s = 0; s < 3; s++){                                                \
        if (s < T){                                                             \
            int k0 = s * BK;                                                    \
            uint32_t base = smbase + (s & 3) * (STAGE_U32*4);                   \
            const __half* as = Ab + (size_t)crow*K + k0 + ccol*8;               \
            const __half* ws = Wb + (size_t)crow*K + k0 + ccol*8;               \
            uint32_t da = base + crow*80 + ccol*16;                             \
            uint32_t db = base + PANEL_U32*4 + crow*80 + ccol*16;               \
            cp16(da, as);      cp16(da + 16, as + 8);                           \
            cp16(db, ws);      cp16(db + 16, ws + 8);                           \
        }                                                                       \
        CP_COMMIT();                                                            \
    }                                                                           \
    float acc[2][8][4];                                                         \
    _Pragma("unroll")                                                           \
    for (int mt = 0; mt < 2; mt++)                                              \
        _Pragma("unroll")                                                       \
        for (int nt = 0; nt < 8; nt++)                                          \
            _Pragma("unroll")                                                   \
            for (int i = 0; i < 4; i++) acc[mt][nt][i] = 0.f;                   \
    for (int t = 0; t < T; t++){                                                \
        CP_WAIT2();                                                             \
        __syncthreads();                                                        \
        if (t + 3 < T){                                                         \
            int k0 = (t+3) * BK;                                                \
            uint32_t base = smbase + ((t+3) & 3) * (STAGE_U32*4);               \
            const __half* as = Ab + (size_t)crow*K + k0 + ccol*8;               \
            const __half* ws = Wb + (size_t)crow*K + k0 + ccol*8;               \
            uint32_t da = base + crow*80 + ccol*16;                             \
            uint32_t db = base + PANEL_U32*4 + crow*80 + ccol*16;               \
            cp16(da, as);      cp16(da + 16, as + 8);                           \
            cp16(db, ws);      cp16(db + 16, ws + 8);                           \
        }                                                                       \
        CP_COMMIT();                                                            \
        const uint32_t* As = smu + (t & 3) * STAGE_U32;                         \
        const uint32_t* Bs = As + PANEL_U32;                                    \
        _Pragma("unroll")                                                       \
        for (int ks = 0; ks < 2; ks++){                                         \
            int k8 = ks * 8;                                                    \
            uint32_t af[2][4];                                                  \
            _Pragma("unroll")                                                   \
            for (int mt = 0; mt < 2; mt++){                                     \
                int r0 = warp_m*32 + mt*16 + qr;                                \
                af[mt][0] = As[ r0     *HSTR + k8 + qc];                        \
                af[mt][1] = As[(r0 + 8)*HSTR + k8 + qc];                        \
                af[mt][2] = As[ r0     *HSTR + k8 + 4 + qc];                    \
                af[mt][3] = As[(r0 + 8)*HSTR + k8 + 4 + qc];                    \
            }                                                                   \
            _Pragma("unroll")                                                   \
            for (int nt = 0; nt < 8; nt++){                                     \
                int cb = warp_n*64 + nt*8 + qr;                                 \
                uint32_t b0 = Bs[cb*HSTR + k8 + qc];                            \
                uint32_t b1 = Bs[cb*HSTR + k8 + 4 + qc];                        \
                mma_f16(acc[0][nt], af[0], b0, b1);                             \
                mma_f16(acc[1][nt], af[1], b0, b1);                             \
            }                                                                   \
        }                                                                       \
    }                                                                           \
    EPILOGUE

__global__ __launch_bounds__(256, 2)
void gemm_f16(const __half* __restrict__ A, const __half* __restrict__ W,
              const float* __restrict__ bias, const float* __restrict__ resid,
              float* __restrict__ C, int M, int Nout, int K){
    GEMM_BODY({
        _Pragma("unroll")
        for (int mt = 0; mt < 2; mt++){
            _Pragma("unroll")
            for (int nt = 0; nt < 8; nt++){
                int row = m0 + warp_m*32 + mt*16 + qr;
                int col = n0 + warp_n*64 + nt*8 + qc*2;
                float2 v0 = make_float2(acc[mt][nt][0], acc[mt][nt][1]);
                float2 v1 = make_float2(acc[mt][nt][2], acc[mt][nt][3]);
                if (bias){
                    float2 bb = *(const float2*)(bias + col);
                    v0.x += bb.x; v0.y += bb.y;
                    v1.x += bb.x; v1.y += bb.y;
                }
                size_t off0 = (size_t)row * Nout + col;
                size_t off1 = (size_t)(row + 8) * Nout + col;
                if (resid){
                    float2 r0 = *(const float2*)(resid + off0);
                    float2 r1 = *(const float2*)(resid + off1);
                    v0.x += r0.x; v0.y += r0.y;
                    v1.x += r1.x; v1.y += r1.y;
                }
                *(float2*)(C + off0) = v0;
                *(float2*)(C + off1) = v1;
            }
        }
    })
}

// f16-out variant (no bias/resid) — used for qkv
__global__ __launch_bounds__(256, 2)
void gemm_f16_hout(const __half* __restrict__ A, const __half* __restrict__ W,
                   __half* __restrict__ C, int M, int Nout, int K){
    GEMM_BODY({
        _Pragma("unroll")
        for (int mt = 0; mt < 2; mt++){
            _Pragma("unroll")
            for (int nt = 0; nt < 8; nt++){
                int row = m0 + warp_m*32 + mt*16 + qr;
                int col = n0 + warp_n*64 + nt*8 + qc*2;
                size_t off0 = (size_t)row * Nout + col;
                size_t off1 = (size_t)(row + 8) * Nout + col;
                *(uint32_t*)(C + off0) = pkh2(acc[mt][nt][0], acc[mt][nt][1]);
                *(uint32_t*)(C + off1) = pkh2(acc[mt][nt][2], acc[mt][nt][3]);
            }
        }
    })
}

// ---------------- RMSNorm over DIM=512 (f32 in, f16 out) ----------------
__global__ void rmsnorm_kernel(const float* __restrict__ X,
                               const float* __restrict__ scale,
                               __half* __restrict__ Y){
    int row = blockIdx.x;
    int t   = threadIdx.x;  // 128
    const float4* x4 = (const float4*)(X + (size_t)row*DIM);
    float4 v = x4[t];
    float ss = v.x*v.x + v.y*v.y + v.z*v.z + v.w*v.w;
    ss = warpSum(ss);
    __shared__ float red[4];
    if ((t & 31) == 0) red[t >> 5] = ss;
    __syncthreads();
    if (t == 0) red[0] = red[0] + red[1] + red[2] + red[3];
    __syncthreads();
    float inv = rsqrtf(red[0] / (float)DIM + EPSf);
    float4 s = ((const float4*)scale)[t];
    ((uint2*)(Y + (size_t)row*DIM))[t] =
        make_uint2(pkh2(v.x*s.x*inv, v.y*s.y*inv), pkh2(v.z*s.z*inv, v.w*s.w*inv));
}

// ---------------- per-head RMSNorm + rotary on f16 qkv (fp32 math) ----------------
__global__ __launch_bounds__(256)
void qkprep_kernel(__half* __restrict__ qkv, const float* __restrict__ theta,
                   const float* __restrict__ sq, const float* __restrict__ sk){
    int t = blockIdx.x * 8 + (threadIdx.x >> 5);
    int isK = t & 1; int rest = t >> 1;
    int h = rest % NH; rest /= NH;
    int n = rest % SEQ; int b = rest / SEQ;
    int lane = threadIdx.x & 31;
    __half* p = qkv + ((size_t)(b*SEQ + n))*(3*DIM) + isK*DIM + h*HDm;
    float v0 = __half2float(p[lane]);
    float v1 = __half2float(p[lane + 32]);
    float ss = warpSum(v0*v0 + v1*v1);
    float inv = rsqrtf(ss / (float)HDm + EPSf);
    const float* sc = isK ? sk : sq;
    v0 = v0 * sc[lane]      * inv;
    v1 = v1 * sc[lane + 32] * inv;
    float th = theta[(((size_t)(b*NH + h))*SEQ + n)*(HDm/2) + lane];
    float cs = cosf(th), sn = sinf(th);
    p[lane]      = __float2half(v0*cs - v1*sn);
    p[lane + 32] = __float2half(v1*cs + v0*sn);
}

// ---------------- flash attention, f16 in / f16 out ----------------
#define QSTR 36
#define FQ_OFF 0
#define FK_OFF (128*QSTR)
#define FP_OFF (2*128*QSTR)
#define FV_OFF (2*128*QSTR + 128*68)
#define ATTN_SMEM ((2*128*QSTR + 128*68 + 64*68)*4)

__global__ __launch_bounds__(256)
void fattn_kernel(const __half* __restrict__ qkv, __half* __restrict__ O){
    extern __shared__ uint32_t smu[];
    uint32_t* Qs = smu + FQ_OFF;
    uint32_t* Ks = smu + FK_OFF;
    uint32_t* Ps = smu + FP_OFF;
    uint32_t* Vt = smu + FV_OFF;

    int tid = threadIdx.x;
    int w = tid >> 5, lane = tid & 31;
    int qr = lane >> 2, qc = lane & 3;
    int bh = blockIdx.x >> 4;
    int qt = blockIdx.x & 15;
    int b = bh >> 3, h = bh & 7;
    int i0 = qt * 128;

    int ldr = tid >> 1;              // row 0..127
    int ldc = (tid & 1) * 32;        // half offset 0/32

    // load Q tile: straight 16B copies
    {
        const __half* src = qkv + ((size_t)(b*SEQ + i0 + ldr))*(3*DIM) + h*HDm + ldc;
        uint32_t* dst = Qs + ldr*QSTR + (ldc>>1);
        *(uint4*)(dst + 0) = *(const uint4*)(src + 0);
        *(uint4*)(dst + 4) = *(const uint4*)(src + 8);
        *(uint4*)(dst + 8) = *(const uint4*)(src + 16);
        *(uint4*)(dst +12) = *(const uint4*)(src + 24);
    }
    __syncthreads();

    uint32_t aQ[4][4];
    #pragma unroll
    for (int ks = 0; ks < 4; ks++){
        int r0 = w*16 + qr;
        aQ[ks][0] = Qs[ r0     *QSTR + ks*8 + qc];
        aQ[ks][1] = Qs[(r0 + 8)*QSTR + ks*8 + qc];
        aQ[ks][2] = Qs[ r0     *QSTR + ks*8 + 4 + qc];
        aQ[ks][3] = Qs[(r0 + 8)*QSTR + ks*8 + 4 + qc];
    }

    float Oacc[8][4];
    #pragma unroll
    for (int nt = 0; nt < 8; nt++)
        #pragma unroll
        for (int i = 0; i < 4; i++) Oacc[nt][i] = 0.f;
    float m0 = -INFINITY, m1 = -INFINITY, l0 = 0.f, l1 = 0.f;

    int jp = tid >> 2;               // 0..63 j-pair
    int dg = (tid & 3) * 16;         // d base

    for (int t = 0; t < SEQ/128; t++){
        int j0 = t * 128;
        __syncthreads();
        // load K tile (straight copy)
        {
            const __half* src = qkv + ((size_t)(b*SEQ + j0 + ldr))*(3*DIM) + DIM + h*HDm + ldc;
            uint32_t* dst = Ks + ldr*QSTR + (ldc>>1);
            *(uint4*)(dst + 0) = *(const uint4*)(src + 0);
            *(uint4*)(dst + 4) = *(const uint4*)(src + 8);
            *(uint4*)(dst + 8) = *(const uint4*)(src + 16);
            *(uint4*)(dst +12) = *(const uint4*)(src + 24);
        }
        // load V tile transposed via byte_perm pair-interleave
        {
            const __half* vp = qkv + ((size_t)(b*SEQ + j0 + 2*jp))*(3*DIM) + 2*DIM + h*HDm + dg;
            uint4 a0 = *(const uint4*)(vp);
            uint4 a1 = *(const uint4*)(vp + 8);
            uint4 b0v = *(const uint4*)(vp + 3*DIM);
            uint4 b1v = *(const uint4*)(vp + 3*DIM + 8);
            uint32_t av[8] = {a0.x,a0.y,a0.z,a0.w,a1.x,a1.y,a1.z,a1.w};
            uint32_t bv[8] = {b0v.x,b0v.y,b0v.z,b0v.w,b1v.x,b1v.y,b1v.z,b1v.w};
            #pragma unroll
            for (int i = 0; i < 8; i++){
                int d0 = dg + 2*i;
                int s0 = jp ^ ((((d0  )>>4)&3)<<3);
                int s1 = jp ^ ((((d0+1)>>4)&3)<<3);
                Vt[(d0  )*68 + s0] = __byte_perm(av[i], bv[i], 0x5410);
                Vt[(d0+1)*68 + s1] = __byte_perm(av[i], bv[i], 0x7632);
            }
        }
        __syncthreads();

        // S = Q K^T
        float S[16][4];
        #pragma unroll
        for (int nt = 0; nt < 16; nt++){
            S[nt][0] = S[nt][1] = S[nt][2] = S[nt][3] = 0.f;
            #pragma unroll
            for (int ks = 0; ks < 4; ks++){
                int cb = nt*8 + qr;
                uint32_t b0 = Ks[cb*QSTR + ks*8 + qc];
                uint32_t b1 = Ks[cb*QSTR + ks*8 + 4 + qc];
                mma_f16(S[nt], aQ[ks], b0, b1);
            }
        }

        // online softmax
        float mx0 = -INFINITY, mx1 = -INFINITY;
        #pragma unroll
        for (int nt = 0; nt < 16; nt++){
            mx0 = fmaxf(mx0, fmaxf(S[nt][0], S[nt][1]));
            mx1 = fmaxf(mx1, fmaxf(S[nt][2], S[nt][3]));
        }
        mx0 = fmaxf(mx0, __shfl_xor_sync(0xFFFFFFFFu, mx0, 1));
        mx0 = fmaxf(mx0, __shfl_xor_sync(0xFFFFFFFFu, mx0, 2));
        mx1 = fmaxf(mx1, __shfl_xor_sync(0xFFFFFFFFu, mx1, 1));
        mx1 = fmaxf(mx1, __shfl_xor_sync(0xFFFFFFFFu, mx1, 2));
        float nm0 = fmaxf(m0, mx0), nm1 = fmaxf(m1, mx1);
        float sc0 = __expf(m0 - nm0), sc1 = __expf(m1 - nm1);
        m0 = nm0; m1 = nm1;
        float rs0 = 0.f, rs1 = 0.f;
        #pragma unroll
        for (int nt = 0; nt < 16; nt++){
            float p0 = __expf(S[nt][0] - nm0);
            float p1 = __expf(S[nt][1] - nm0);
            float p2 = __expf(S[nt][2] - nm1);
            float p3 = __expf(S[nt][3] - nm1);
            S[nt][0] = p0; S[nt][1] = p1; S[nt][2] = p2; S[nt][3] = p3;
            rs0 += p0 + p1; rs1 += p2 + p3;
        }
        rs0 += __shfl_xor_sync(0xFFFFFFFFu, rs0, 1);
        rs0 += __shfl_xor_sync(0xFFFFFFFFu, rs0, 2);
        rs1 += __shfl_xor_sync(0xFFFFFFFFu, rs1, 1);
        rs1 += __shfl_xor_sync(0xFFFFFFFFu, rs1, 2);
        l0 = l0 * sc0 + rs0;
        l1 = l1 * sc1 + rs1;
        #pragma unroll
        for (int nt = 0; nt < 8; nt++){
            Oacc[nt][0] *= sc0; Oacc[nt][1] *= sc0;
            Oacc[nt][2] *= sc1; Oacc[nt][3] *= sc1;
        }

        // write P tiles to smem (f16)
        {
            int r0 = w*16 + qr, r1 = r0 + 8;
            #pragma unroll
            for (int nt = 0; nt < 16; nt++){
                Ps[r0*68 + nt*4 + qc] = pkh2(S[nt][0], S[nt][1]);
                Ps[r1*68 + nt*4 + qc] = pkh2(S[nt][2], S[nt][3]);
            }
        }
        __syncthreads();

        // O += P V
        #pragma unroll
        for (int ks = 0; ks < 8; ks++){
            uint32_t aP[4];
            int r0 = w*16 + qr, r1 = r0 + 8;
            aP[0] = Ps[r0*68 + ks*8 + qc];
            aP[1] = Ps[r1*68 + ks*8 + qc];
            aP[2] = Ps[r0*68 + ks*8 + 4 + qc];
            aP[3] = Ps[r1*68 + ks*8 + 4 + qc];
            #pragma unroll
            for (int nt = 0; nt < 8; nt++){
                int drow = nt*8 + qr;
                int swz = (nt >> 1) << 3;
                uint32_t b0 = Vt[drow*68 + ((ks*8 + qc) ^ swz)];
                uint32_t b1 = Vt[drow*68 + ((ks*8 + 4 + qc) ^ swz)];
                mma_f16(Oacc[nt], aP, b0, b1);
            }
        }
    }

    float il0 = 1.f / l0, il1 = 1.f / l1;
    int row0 = i0 + w*16 + qr, row1 = row0 + 8;
    #pragma unroll
    for (int nt = 0; nt < 8; nt++){
        int col = h*HDm + nt*8 + 2*qc;
        *(uint32_t*)(O + ((size_t)(b*SEQ) + row0)*DIM + col) =
            pkh2(Oacc[nt][0]*il0, Oacc[nt][1]*il0);
        *(uint32_t*)(O + ((size_t)(b*SEQ) + row1)*DIM + col) =
            pkh2(Oacc[nt][2]*il1, Oacc[nt][3]*il1);
    }
}

// ---------------- gated GELU (f32 in, f16 out) ----------------
__global__ void glu_kernel(const float* __restrict__ Hh, __half* __restrict__ Hg){
    size_t i4 = ((size_t)blockIdx.x * 256 + threadIdx.x) * 4;
    size_t m = i4 / FFm, f = i4 % FFm;
    float4 hx = *(const float4*)(Hh + m*(2*FFm) + f);
    float4 g  = *(const float4*)(Hh + m*(2*FFm) + FFm + f);
    *(uint2*)(Hg + i4) = make_uint2(
        pkh2(hx.x * geluf(g.x), hx.y * geluf(g.y)),
        pkh2(hx.z * geluf(g.z), hx.w * geluf(g.w)));
}

// ---------------- launch ----------------
extern "C" void kernel_launch(void* const* d_in, const int* in_sizes, int n_in,
                              void* d_out, int out_size){
    const float* x       = (const float*)d_in[0];
    const float* theta   = (const float*)d_in[1];
    const float* fmaps   = (const float*)d_in[2];
    const float* coords  = (const float*)d_in[3];
    const float* w_corr  = (const float*)d_in[4];
    const float* norm1   = (const float*)d_in[5];
    const float* sq      = (const float*)d_in[6];
    const float* sk      = (const float*)d_in[7];
    const float* w_qkv   = (const float*)d_in[8];
    const float* w_out   = (const float*)d_in[9];
    const float* norm2   = (const float*)d_in[10];
    const float* w_ff1   = (const float*)d_in[11];
    const float* b_ff1   = (const float*)d_in[12];
    const float* w_ff2   = (const float*)d_in[13];
    float* out = (float*)d_out;

    float *p_x, *p_x2, *p_h;
    __half *p_feats, *p_xn, *p_qkvh, *p_o, *p_xn2, *p_hg;
    __half *p_wc, *p_wq, *p_wo, *p_w1, *p_w2;
    cudaGetSymbolAddress((void**)&p_x,     g_x);
    cudaGetSymbolAddress((void**)&p_x2,    g_x2);
    cudaGetSymbolAddress((void**)&p_h,     g_h);
    cudaGetSymbolAddress((void**)&p_feats, g_feats_h);
    cudaGetSymbolAddress((void**)&p_xn,    g_xn_h);
    cudaGetSymbolAddress((void**)&p_qkvh,  g_qkv_h);
    cudaGetSymbolAddress((void**)&p_o,     g_o_h);
    cudaGetSymbolAddress((void**)&p_xn2,   g_xn2_h);
    cudaGetSymbolAddress((void**)&p_hg,    g_hg_h);
    cudaGetSymbolAddress((void**)&p_wc,    g_wcorr_h);
    cudaGetSymbolAddress((void**)&p_wq,    g_wqkv_h);
    cudaGetSymbolAddress((void**)&p_wo,    g_wout_h);
    cudaGetSymbolAddress((void**)&p_w1,    g_wff1_h);
    cudaGetSymbolAddress((void**)&p_w2,    g_wff2_h);

    static bool cfg = false;
    if (!cfg){
        cudaFuncSetAttribute(fattn_kernel, cudaFuncAttributeMaxDynamicSharedMemorySize,
                             ATTN_SMEM);
        cudaFuncSetAttribute(gemm_f16, cudaFuncAttributeMaxDynamicSharedMemorySize,
                             GEMM_SMEM);
        cudaFuncSetAttribute(gemm_f16_hout, cudaFuncAttributeMaxDynamicSharedMemorySize,
                             GEMM_SMEM);
        cfg = true;
    }

    const int M = Bsz * SEQ;   // 8192

    wconv_kernel<<<(WC_TOT + 255)/256, 256>>>(w_corr, w_qkv, w_out, w_ff1, w_ff2);
    bilinear_kernel<<<M, C2m>>>(fmaps, coords);
    gemm_f16<<<dim3(DIM/128, M/128), 256, GEMM_SMEM>>>(p_feats, p_wc, nullptr, x, p_x, M, DIM, C2m);
    rmsnorm_kernel<<<M, 128>>>(p_x, norm1, p_xn);
    gemm_f16_hout<<<dim3(3*DIM/128, M/128), 256, GEMM_SMEM>>>(p_xn, p_wq, p_qkvh, M, 3*DIM, DIM);
    qkprep_kernel<<<M*NH*2/8, 256>>>(p_qkvh, theta, sq, sk);
    fattn_kernel<<<Bsz*NH*(SEQ/128), 256, ATTN_SMEM>>>(p_qkvh, p_o);
    gemm_f16<<<dim3(DIM/128, M/128), 256, GEMM_SMEM>>>(p_o, p_wo, nullptr, p_x, p_x2, M, DIM, DIM);
    rmsnorm_kernel<<<M, 128>>>(p_x2, norm2, p_xn2);
    gemm_f16<<<dim3(2*FFm/128, M/128), 256, GEMM_SMEM>>>(p_xn2, p_w1, b_ff1, nullptr, p_h, M, 2*FFm, DIM);
    glu_kernel<<<(Bsz*SEQ*FFm)/1024, 256>>>(p_h, p_hg);
    gemm_f16<<<dim3(DIM/128, M/128), 256, GEMM_SMEM>>>(p_hg, p_w2, nullptr, p_x2, out, M, DIM, FFm);
}

// round 14
// speedup vs baseline: 10.5912x; 1.0003x over previous
#include <cuda_runtime.h>
#include <cuda_fp16.h>
#include <math.h>
#include <stdint.h>

#define Bsz 4
#define SEQ 2048
#define DIM 512
#define NH  8
#define HDm 64
#define FFm 1024
#define C2m 128
#define HFm 64
#define WFm 64
#define EPSf 1e-6f

// ---------------- static scratch ----------------
// f32
__device__ float g_x   [Bsz*SEQ*DIM];
__device__ float g_x2  [Bsz*SEQ*DIM];
// f16 activations
__device__ __half g_feats_h[Bsz*SEQ*C2m];
__device__ __half g_xn_h  [Bsz*SEQ*DIM];
__device__ __half g_qkv_h [Bsz*SEQ*3*DIM];
__device__ __half g_o_h   [Bsz*SEQ*DIM];
__device__ __half g_xn2_h [Bsz*SEQ*DIM];
__device__ __half g_hh    [Bsz*SEQ*2*FFm];
__device__ __half g_hg_h  [Bsz*SEQ*FFm];
// f16 weights
__device__ __half g_wcorr_h[DIM*C2m];
__device__ __half g_wqkv_h [3*DIM*DIM];
__device__ __half g_wout_h [DIM*DIM];
__device__ __half g_wff1_h [2*FFm*DIM];
__device__ __half g_wff2_h [DIM*FFm];

__device__ __forceinline__ float warpSum(float v){
    #pragma unroll
    for (int o = 16; o > 0; o >>= 1) v += __shfl_xor_sync(0xFFFFFFFFu, v, o);
    return v;
}
__device__ __forceinline__ uint32_t pkh2(float x, float y){
    __half2 h = __floats2half2_rn(x, y);
    return *reinterpret_cast<uint32_t*>(&h);
}
__device__ __forceinline__ float geluf(float g){
    return 0.5f * g * (1.f + erff(g * 0.70710678118654752f));
}
__device__ __forceinline__ void mma_f16(float* c, const uint32_t* a, uint32_t b0, uint32_t b1){
    asm volatile(
        "mma.sync.aligned.m16n8k16.row.col.f32.f16.f16.f32 "
        "{%0,%1,%2,%3}, {%4,%5,%6,%7}, {%8,%9}, {%0,%1,%2,%3};"
        : "+f"(c[0]), "+f"(c[1]), "+f"(c[2]), "+f"(c[3])
        : "r"(a[0]), "r"(a[1]), "r"(a[2]), "r"(a[3]), "r"(b0), "r"(b1));
}
__device__ __forceinline__ void cp16(uint32_t smaddr, const void* g){
    asm volatile("cp.async.cg.shared.global [%0], [%1], 16;" :: "r"(smaddr), "l"(g));
}
#define CP_COMMIT() asm volatile("cp.async.commit_group;" ::: "memory")
#define CP_WAIT2()  asm volatile("cp.async.wait_group 2;" ::: "memory")
#define CP_WAIT0()  asm volatile("cp.async.wait_group 0;" ::: "memory")

// ---------------- fused weight conversion ----------------
#define WC_N0 ((DIM*C2m)/4)
#define WC_N1 ((3*DIM*DIM)/4)
#define WC_N2 ((DIM*DIM)/4)
#define WC_N3 ((2*FFm*DIM)/4)
#define WC_N4 ((DIM*FFm)/4)
#define WC_TOT (WC_N0+WC_N1+WC_N2+WC_N3+WC_N4)
__global__ void wconv_kernel(const float* __restrict__ s0, const float* __restrict__ s1,
                             const float* __restrict__ s2, const float* __restrict__ s3,
                             const float* __restrict__ s4){
    int i = blockIdx.x * 256 + threadIdx.x;
    if (i >= WC_TOT) return;
    const float* src; __half* dst;
    if (i < WC_N0){ src = s0; dst = g_wcorr_h; }
    else if ((i -= WC_N0) < WC_N1){ src = s1; dst = g_wqkv_h; }
    else if ((i -= WC_N1) < WC_N2){ src = s2; dst = g_wout_h; }
    else if ((i -= WC_N2) < WC_N3){ src = s3; dst = g_wff1_h; }
    else { i -= WC_N3; src = s4; dst = g_wff2_h; }
    float4 v = ((const float4*)src)[i];
    ((uint2*)dst)[i] = make_uint2(pkh2(v.x, v.y), pkh2(v.z, v.w));
}

// ---------------- bilinear (writes f16 feats) ----------------
__global__ void bilinear_kernel(const float* __restrict__ fmaps,
                                const float* __restrict__ coords){
    int bn = blockIdx.x;
    int b  = bn / SEQ;
    int c  = threadIdx.x;
    float xc = coords[(size_t)bn*2 + 0];
    float yc = coords[(size_t)bn*2 + 1];
    xc = fminf(fmaxf(xc, 0.f), (float)(WFm-1));
    yc = fminf(fmaxf(yc, 0.f), (float)(HFm-1));
    float x0 = floorf(xc), y0 = floorf(yc);
    float wx = xc - x0,    wy = yc - y0;
    int x0i = (int)x0, y0i = (int)y0;
    int x1i = min(x0i+1, WFm-1), y1i = min(y0i+1, HFm-1);
    const float* img = fmaps + ((size_t)(b*C2m + c))*HFm*WFm;
    float f00 = img[y0i*WFm + x0i];
    float f01 = img[y0i*WFm + x1i];
    float f10 = img[y1i*WFm + x0i];
    float f11 = img[y1i*WFm + x1i];
    float top = f00*(1.f-wx) + f01*wx;
    float bot = f10*(1.f-wx) + f11*wx;
    g_feats_h[(size_t)bn*C2m + c] = __float2half(top*(1.f-wy) + bot*wy);
}

// ---------------- f16 GEMM with cp.async 4-stage pipeline ----------------
#define BK 32
#define HSTR 20
#define PANEL_U32 (128*HSTR)
#define STAGE_U32 (2*PANEL_U32)
#define GEMM_SMEM (4*STAGE_U32*4)

#define GEMM_BODY(EPILOGUE)                                                     \
    extern __shared__ uint32_t smu[];                                           \
    uint32_t smbase = (uint32_t)__cvta_generic_to_shared(smu);                  \
    int tid = threadIdx.x;                                                      \
    int wid = tid >> 5, lane = tid & 31;                                        \
    int qr = lane >> 2, qc = lane & 3;                                          \
    int warp_m = wid & 3, warp_n = wid >> 2;                                    \
    int m0 = blockIdx.y * 128, n0 = blockIdx.x * 128;                           \
    const __half* Ab = A + (size_t)m0 * K;                                      \
    const __half* Wb = W + (size_t)n0 * K;                                      \
    int crow = tid >> 1;                                                        \
    int ccol = (tid & 1) * 2;                                                   \
    int T = K / BK;                                                             \
    _Pragma("unroll")                                                           \
    for (int s = 0; s < 3; s++){                                                \
        if (s < T){                                                             \
            int k0 = s * BK;                                                    \
            uint32_t base = smbase + (s & 3) * (STAGE_U32*4);                   \
            const __half* as = Ab + (size_t)crow*K + k0 + ccol*8;               \
            const __half* ws = Wb + (size_t)crow*K + k0 + ccol*8;               \
            uint32_t da = base + crow*80 + ccol*16;                             \
            uint32_t db = base + PANEL_U32*4 + crow*80 + ccol*16;               \
            cp16(da, as);      cp16(da + 16, as + 8);                           \
            cp16(db, ws);      cp16(db + 16, ws + 8);                           \
        }                                                                       \
        CP_COMMIT();                                                            \
    }                                                                           \
    float acc[2][8][4];                                                         \
    _Pragma("unroll")                                                           \
    for (int mt = 0; mt < 2; mt++)                                              \
        _Pragma("unroll")                                                       \
        for (int nt = 0; nt < 8; nt++)                                          \
            _Pragma("unroll")                                                   \
            for (int i = 0; i < 4; i++) acc[mt][nt][i] = 0.f;                   \
    for (int t = 0; t < T; t++){                                                \
        CP_WAIT2();                                                             \
        __syncthreads();                                                        \
        if (t + 3 < T){                                                         \
            int k0 = (t+3) * BK;                                                \
            uint32_t base = smbase + ((t+3) & 3) * (STAGE_U32*4);               \
            const __half* as = Ab + (size_t)crow*K + k0 + ccol*8;               \
            const __half* ws = Wb + (size_t)crow*K + k0 + ccol*8;               \
            uint32_t da = base + crow*80 + ccol*16;                             \
            uint32_t db = base + PANEL_U32*4 + crow*80 + ccol*16;               \
            cp16(da, as);      cp16(da + 16, as + 8);                           \
            cp16(db, ws);      cp16(db + 16, ws + 8);                           \
        }                                                                       \
        CP_COMMIT();                                                            \
        const uint32_t* As = smu + (t & 3) * STAGE_U32;                         \
        const uint32_t* Bs = As + PANEL_U32;                                    \
        _Pragma("unroll")                                                       \
        for (int ks = 0; ks < 2; ks++){                                         \
            int k8 = ks * 8;                                                    \
            uint32_t af[2][4];                                                  \
            _Pragma("unroll")                                                   \
            for (int mt = 0; mt < 2; mt++){                                     \
                int r0 = warp_m*32 + mt*16 + qr;                                \
                af[mt][0] = As[ r0     *HSTR + k8 + qc];                        \
                af[mt][1] = As[(r0 + 8)*HSTR + k8 + qc];                        \
                af[mt][2] = As[ r0     *HSTR + k8 + 4 + qc];                    \
                af[mt][3] = As[(r0 + 8)*HSTR + k8 + 4 + qc];                    \
            }                                                                   \
            _Pragma("unroll")                                                   \
            for (int nt = 0; nt < 8; nt++){                                     \
                int cb = warp_n*64 + nt*8 + qr;                                 \
                uint32_t b0 = Bs[cb*HSTR + k8 + qc];                            \
                uint32_t b1 = Bs[cb*HSTR + k8 + 4 + qc];                        \
                mma_f16(acc[0][nt], af[0], b0, b1);                             \
                mma_f16(acc[1][nt], af[1], b0, b1);                             \
            }                                                                   \
        }                                                                       \
    }                                                                           \
    EPILOGUE

__global__ __launch_bounds__(256, 2)
void gemm_f16(const __half* __restrict__ A, const __half* __restrict__ W,
              const float* __restrict__ bias, const float* __restrict__ resid,
              float* __restrict__ C, int M, int Nout, int K){
    GEMM_BODY({
        _Pragma("unroll")
        for (int mt = 0; mt < 2; mt++){
            _Pragma("unroll")
            for (int nt = 0; nt < 8; nt++){
                int row = m0 + warp_m*32 + mt*16 + qr;
                int col = n0 + warp_n*64 + nt*8 + qc*2;
                float2 v0 = make_float2(acc[mt][nt][0], acc[mt][nt][1]);
                float2 v1 = make_float2(acc[mt][nt][2], acc[mt][nt][3]);
                if (bias){
                    float2 bb = *(const float2*)(bias + col);
                    v0.x += bb.x; v0.y += bb.y;
                    v1.x += bb.x; v1.y += bb.y;
                }
                size_t off0 = (size_t)row * Nout + col;
                size_t off1 = (size_t)(row + 8) * Nout + col;
                if (resid){
                    float2 r0 = *(const float2*)(resid + off0);
                    float2 r1 = *(const float2*)(resid + off1);
                    v0.x += r0.x; v0.y += r0.y;
                    v1.x += r1.x; v1.y += r1.y;
                }
                *(float2*)(C + off0) = v0;
                *(float2*)(C + off1) = v1;
            }
        }
    })
}

// f16-out variant (optional bias) — used for qkv and ff1
__global__ __launch_bounds__(256, 2)
void gemm_f16_hout(const __half* __restrict__ A, const __half* __restrict__ W,
                   const float* __restrict__ bias,
                   __half* __restrict__ C, int M, int Nout, int K){
    GEMM_BODY({
        _Pragma("unroll")
        for (int mt = 0; mt < 2; mt++){
            _Pragma("unroll")
            for (int nt = 0; nt < 8; nt++){
                int row = m0 + warp_m*32 + mt*16 + qr;
                int col = n0 + warp_n*64 + nt*8 + qc*2;
                float2 v0 = make_float2(acc[mt][nt][0], acc[mt][nt][1]);
                float2 v1 = make_float2(acc[mt][nt][2], acc[mt][nt][3]);
                if (bias){
                    float2 bb = *(const float2*)(bias + col);
                    v0.x += bb.x; v0.y += bb.y;
                    v1.x += bb.x; v1.y += bb.y;
                }
                size_t off0 = (size_t)row * Nout + col;
                size_t off1 = (size_t)(row + 8) * Nout + col;
                *(uint32_t*)(C + off0) = pkh2(v0.x, v0.y);
                *(uint32_t*)(C + off1) = pkh2(v1.x, v1.y);
            }
        }
    })
}

// ---------------- RMSNorm over DIM=512 (f32 in, f16 out) ----------------
__global__ void rmsnorm_kernel(const float* __restrict__ X,
                               const float* __restrict__ scale,
                               __half* __restrict__ Y){
    int row = blockIdx.x;
    int t   = threadIdx.x;  // 128
    const float4* x4 = (const float4*)(X + (size_t)row*DIM);
    float4 v = x4[t];
    float ss = v.x*v.x + v.y*v.y + v.z*v.z + v.w*v.w;
    ss = warpSum(ss);
    __shared__ float red[4];
    if ((t & 31) == 0) red[t >> 5] = ss;
    __syncthreads();
    if (t == 0) red[0] = red[0] + red[1] + red[2] + red[3];
    __syncthreads();
    float inv = rsqrtf(red[0] / (float)DIM + EPSf);
    float4 s = ((const float4*)scale)[t];
    ((uint2*)(Y + (size_t)row*DIM))[t] =
        make_uint2(pkh2(v.x*s.x*inv, v.y*s.y*inv), pkh2(v.z*s.z*inv, v.w*s.w*inv));
}

// ---------------- per-head RMSNorm + rotary on f16 qkv ----------------
__global__ __launch_bounds__(256)
void qkprep_kernel(__half* __restrict__ qkv, const float* __restrict__ theta,
                   const float* __restrict__ sq, const float* __restrict__ sk){
    int t = blockIdx.x * 8 + (threadIdx.x >> 5);
    int isK = t & 1; int rest = t >> 1;
    int h = rest % NH; rest /= NH;
    int n = rest % SEQ; int b = rest / SEQ;
    int lane = threadIdx.x & 31;
    __half* p = qkv + ((size_t)(b*SEQ + n))*(3*DIM) + isK*DIM + h*HDm;
    float v0 = __half2float(p[lane]);
    float v1 = __half2float(p[lane + 32]);
    float ss = warpSum(v0*v0 + v1*v1);
    float inv = rsqrtf(ss / (float)HDm + EPSf);
    const float* sc = isK ? sk : sq;
    v0 = v0 * sc[lane]      * inv;
    v1 = v1 * sc[lane + 32] * inv;
    float th = theta[(((size_t)(b*NH + h))*SEQ + n)*(HDm/2) + lane];
    float cs = cosf(th), sn = sinf(th);
    p[lane]      = __float2half(v0*cs - v1*sn);
    p[lane + 32] = __float2half(v1*cs + v0*sn);
}

// ---------------- flash attention: K cp.async double-buffer + V reg prefetch ----------------
#define QSTR 36
#define FK0_OFF 0
#define FK1_OFF (128*QSTR)            // also Q staging region (dead after frag preload)
#define FP_OFF  (2*128*QSTR)
#define FVT_OFF (2*128*QSTR + 128*68) // Vt[b] = FVT_OFF + b*64*68
#define ATTN_SMEM ((2*128*QSTR + 128*68 + 2*64*68)*4)   // 106496 B

__global__ __launch_bounds__(256, 2)
void fattn_kernel(const __half* __restrict__ qkv, __half* __restrict__ O){
    extern __shared__ uint32_t smu[];
    uint32_t smbase = (uint32_t)__cvta_generic_to_shared(smu);
    uint32_t* Ps = smu + FP_OFF;

    int tid = threadIdx.x;
    int w = tid >> 5, lane = tid & 31;
    int qr = lane >> 2, qc = lane & 3;
    int bh = blockIdx.x >> 4;
    int qt = blockIdx.x & 15;
    int b = bh >> 3, h = bh & 7;
    int i0 = qt * 128;

    int ldr = tid >> 1;              // row 0..127
    int ldc = (tid & 1) * 32;        // half offset 0/32
    int jp = tid >> 2;               // 0..63 j-pair (V)
    int dg = (tid & 3) * 16;         // d base (V)

    const __half* kvbase = qkv + (size_t)b*SEQ*3*DIM;

    // issue cp.async K(0) -> K0
    {
        const __half* src = kvbase + (size_t)(0 + ldr)*(3*DIM) + DIM + h*HDm + ldc;
        uint32_t da = smbase + (FK0_OFF + ldr*QSTR + (ldc>>1))*4;
        cp16(da, src); cp16(da+16, src+8); cp16(da+32, src+16); cp16(da+48, src+24);
        CP_COMMIT();
    }
    // stage V(0) in regs
    uint32_t av[8], bv[8];
    {
        const __half* vp = kvbase + (size_t)(2*jp)*(3*DIM) + 2*DIM + h*HDm + dg;
        uint4 a0 = *(const uint4*)(vp);
        uint4 a1 = *(const uint4*)(vp + 8);
        uint4 b0v = *(const uint4*)(vp + 3*DIM);
        uint4 b1v = *(const uint4*)(vp + 3*DIM + 8);
        av[0]=a0.x; av[1]=a0.y; av[2]=a0.z; av[3]=a0.w;
        av[4]=a1.x; av[5]=a1.y; av[6]=a1.z; av[7]=a1.w;
        bv[0]=b0v.x; bv[1]=b0v.y; bv[2]=b0v.z; bv[3]=b0v.w;
        bv[4]=b1v.x; bv[5]=b1v.y; bv[6]=b1v.z; bv[7]=b1v.w;
    }
    // Q tile -> K1 region (sync)
    {
        const __half* src = kvbase + (size_t)(i0 + ldr)*(3*DIM) + h*HDm + ldc;
        uint32_t* dst = smu + FK1_OFF + ldr*QSTR + (ldc>>1);
        *(uint4*)(dst + 0) = *(const uint4*)(src + 0);
        *(uint4*)(dst + 4) = *(const uint4*)(src + 8);
        *(uint4*)(dst + 8) = *(const uint4*)(src + 16);
        *(uint4*)(dst +12) = *(const uint4*)(src + 24);
    }
    __syncthreads();

    uint32_t aQ[4][4];
    {
        const uint32_t* Qs = smu + FK1_OFF;
        #pragma unroll
        for (int ks = 0; ks < 4; ks++){
            int r0 = w*16 + qr;
            aQ[ks][0] = Qs[ r0     *QSTR + ks*8 + qc];
            aQ[ks][1] = Qs[(r0 + 8)*QSTR + ks*8 + qc];
            aQ[ks][2] = Qs[ r0     *QSTR + ks*8 + 4 + qc];
            aQ[ks][3] = Qs[(r0 + 8)*QSTR + ks*8 + 4 + qc];
        }
    }

    float Oacc[8][4];
    #pragma unroll
    for (int nt = 0; nt < 8; nt++)
        #pragma unroll
        for (int i = 0; i < 4; i++) Oacc[nt][i] = 0.f;
    float m0 = -INFINITY, m1 = -INFINITY, l0 = 0.f, l1 = 0.f;

    const int T = SEQ/128;
    for (int t = 0; t < T; t++){
        int buf = t & 1;
        uint32_t* Vt = smu + FVT_OFF + buf*(64*68);
        const uint32_t* Ks = smu + (buf ? FK1_OFF : FK0_OFF);

        // store staged V(t) into Vt[buf] (xor swizzle)
        #pragma unroll
        for (int i = 0; i < 8; i++){
            int d0 = dg + 2*i;
            int s0 = jp ^ ((((d0  )>>4)&3)<<3);
            int s1 = jp ^ ((((d0+1)>>4)&3)<<3);
            Vt[(d0  )*68 + s0] = __byte_perm(av[i], bv[i], 0x5410);
            Vt[(d0+1)*68 + s1] = __byte_perm(av[i], bv[i], 0x7632);
        }
        CP_WAIT0();          // K(t) arrived
        __syncthreads();     // A: K(t), V(t) visible; prior PV done

        // prefetch K(t+1) into the other K buffer
        if (t + 1 < T){
            int j1 = (t+1) * 128;
            uint32_t koff = (buf ? FK0_OFF : FK1_OFF);
            const __half* src = kvbase + (size_t)(j1 + ldr)*(3*DIM) + DIM + h*HDm + ldc;
            uint32_t da = smbase + (koff + ldr*QSTR + (ldc>>1))*4;
            cp16(da, src); cp16(da+16, src+8); cp16(da+32, src+16); cp16(da+48, src+24);
        }
        CP_COMMIT();

        // S = Q K^T
        float S[16][4];
        #pragma unroll
        for (int nt = 0; nt < 16; nt++){
            S[nt][0] = S[nt][1] = S[nt][2] = S[nt][3] = 0.f;
            #pragma unroll
            for (int ks = 0; ks < 4; ks++){
                int cb = nt*8 + qr;
                uint32_t b0 = Ks[cb*QSTR + ks*8 + qc];
                uint32_t b1 = Ks[cb*QSTR + ks*8 + 4 + qc];
                mma_f16(S[nt], aQ[ks], b0, b1);
            }
        }

        // online softmax
        float mx0 = -INFINITY, mx1 = -INFINITY;
        #pragma unroll
        for (int nt = 0; nt < 16; nt++){
            mx0 = fmaxf(mx0, fmaxf(S[nt][0], S[nt][1]));
            mx1 = fmaxf(mx1, fmaxf(S[nt][2], S[nt][3]));
        }
        mx0 = fmaxf(mx0, __shfl_xor_sync(0xFFFFFFFFu, mx0, 1));
        mx0 = fmaxf(mx0, __shfl_xor_sync(0xFFFFFFFFu, mx0, 2));
        mx1 = fmaxf(mx1, __shfl_xor_sync(0xFFFFFFFFu, mx1, 1));
        mx1 = fmaxf(mx1, __shfl_xor_sync(0xFFFFFFFFu, mx1, 2));
        float nm0 = fmaxf(m0, mx0), nm1 = fmaxf(m1, mx1);
        float sc0 = __expf(m0 - nm0), sc1 = __expf(m1 - nm1);
        m0 = nm0; m1 = nm1;
        float rs0 = 0.f, rs1 = 0.f;
        #pragma unroll
        for (int nt = 0; nt < 16; nt++){
            float p0 = __expf(S[nt][0] - nm0);
            float p1 = __expf(S[nt][1] - nm0);
            float p2 = __expf(S[nt][2] - nm1);
            float p3 = __expf(S[nt][3] - nm1);
            S[nt][0] = p0; S[nt][1] = p1; S[nt][2] = p2; S[nt][3] = p3;
            rs0 += p0 + p1; rs1 += p2 + p3;
        }
        rs0 += __shfl_xor_sync(0xFFFFFFFFu, rs0, 1);
        rs0 += __shfl_xor_sync(0xFFFFFFFFu, rs0, 2);
        rs1 += __shfl_xor_sync(0xFFFFFFFFu, rs1, 1);
        rs1 += __shfl_xor_sync(0xFFFFFFFFu, rs1, 2);
        l0 = l0 * sc0 + rs0;
        l1 = l1 * sc1 + rs1;
        #pragma unroll
        for (int nt = 0; nt < 8; nt++){
            Oacc[nt][0] *= sc0; Oacc[nt][1] *= sc0;
            Oacc[nt][2] *= sc1; Oacc[nt][3] *= sc1;
        }

        // prefetch V(t+1) into regs (S dead; latency hidden by P write + barrier + PV)
        if (t + 1 < T){
            const __half* vp = kvbase + (size_t)((t+1)*128 + 2*jp)*(3*DIM) + 2*DIM + h*HDm + dg;
            uint4 a0 = *(const uint4*)(vp);
            uint4 a1 = *(const uint4*)(vp + 8);
            uint4 b0v = *(const uint4*)(vp + 3*DIM);
            uint4 b1v = *(const uint4*)(vp + 3*DIM + 8);
            av[0]=a0.x; av[1]=a0.y; av[2]=a0.z; av[3]=a0.w;
            av[4]=a1.x; av[5]=a1.y; av[6]=a1.z; av[7]=a1.w;
            bv[0]=b0v.x; bv[1]=b0v.y; bv[2]=b0v.z; bv[3]=b0v.w;
            bv[4]=b1v.x; bv[5]=b1v.y; bv[6]=b1v.z; bv[7]=b1v.w;
        }

        // write P tiles to smem (f16)
        {
            int r0 = w*16 + qr, r1 = r0 + 8;
            #pragma unroll
            for (int nt = 0; nt < 16; nt++){
                Ps[r0*68 + nt*4 + qc] = pkh2(S[nt][0], S[nt][1]);
                Ps[r1*68 + nt*4 + qc] = pkh2(S[nt][2], S[nt][3]);
            }
        }
        __syncthreads();     // B: P + Vt[buf] ready for all

        // O += P V
        #pragma unroll
        for (int ks = 0; ks < 8; ks++){
            uint32_t aP[4];
            int r0 = w*16 + qr, r1 = r0 + 8;
            aP[0] = Ps[r0*68 + ks*8 + qc];
            aP[1] = Ps[r1*68 + ks*8 + qc];
            aP[2] = Ps[r0*68 + ks*8 + 4 + qc];
            aP[3] = Ps[r1*68 + ks*8 + 4 + qc];
            #pragma unroll
            for (int nt = 0; nt < 8; nt++){
                int drow = nt*8 + qr;
                int swz = (nt >> 1) << 3;
                uint32_t b0 = Vt[drow*68 + ((ks*8 + qc) ^ swz)];
                uint32_t b1 = Vt[drow*68 + ((ks*8 + 4 + qc) ^ swz)];
                mma_f16(Oacc[nt], aP, b0, b1);
            }
        }
    }

    float il0 = 1.f / l0, il1 = 1.f / l1;
    int row0 = i0 + w*16 + qr, row1 = row0 + 8;
    #pragma unroll
    for (int nt = 0; nt < 8; nt++){
        int col = h*HDm + nt*8 + 2*qc;
        *(uint32_t*)(O + ((size_t)(b*SEQ) + row0)*DIM + col) =
            pkh2(Oacc[nt][0]*il0, Oacc[nt][1]*il0);
        *(uint32_t*)(O + ((size_t)(b*SEQ) + row1)*DIM + col) =
            pkh2(Oacc[nt][2]*il1, Oacc[nt][3]*il1);
    }
}

// ---------------- gated GELU (f16 in, f16 out) ----------------
__global__ void glu_kernel(const __half* __restrict__ Hh, __half* __restrict__ Hg){
    size_t i8 = ((size_t)blockIdx.x * 256 + threadIdx.x) * 8;
    size_t m = i8 / FFm, f = i8 % FFm;
    uint4 hx4 = *(const uint4*)(Hh + m*(2*FFm) + f);
    uint4 g4  = *(const uint4*)(Hh + m*(2*FFm) + FFm + f);
    const uint32_t* hxp = &hx4.x;
    const uint32_t* gp  = &g4.x;
    uint4 o;
    uint32_t* op = &o.x;
    #pragma unroll
    for (int i = 0; i < 4; i++){
        __half2 hh = *reinterpret_cast<const __half2*>(&hxp[i]);
        __half2 gg = *reinterpret_cast<const __half2*>(&gp[i]);
        float2 hf = __half22float2(hh);
        float2 gf = __half22float2(gg);
        op[i] = pkh2(hf.x * geluf(gf.x), hf.y * geluf(gf.y));
    }
    *(uint4*)(Hg + i8) = o;
}

// ---------------- launch ----------------
extern "C" void kernel_launch(void* const* d_in, const int* in_sizes, int n_in,
                              void* d_out, int out_size){
    const float* x       = (const float*)d_in[0];
    const float* theta   = (const float*)d_in[1];
    const float* fmaps   = (const float*)d_in[2];
    const float* coords  = (const float*)d_in[3];
    const float* w_corr  = (const float*)d_in[4];
    const float* norm1   = (const float*)d_in[5];
    const float* sq      = (const float*)d_in[6];
    const float* sk      = (const float*)d_in[7];
    const float* w_qkv   = (const float*)d_in[8];
    const float* w_out   = (const float*)d_in[9];
    const float* norm2   = (const float*)d_in[10];
    const float* w_ff1   = (const float*)d_in[11];
    const float* b_ff1   = (const float*)d_in[12];
    const float* w_ff2   = (const float*)d_in[13];
    float* out = (float*)d_out;

    float *p_x, *p_x2;
    __half *p_feats, *p_xn, *p_qkvh, *p_o, *p_xn2, *p_hh, *p_hg;
    __half *p_wc, *p_wq, *p_wo, *p_w1, *p_w2;
    cudaGetSymbolAddress((void**)&p_x,     g_x);
    cudaGetSymbolAddress((void**)&p_x2,    g_x2);
    cudaGetSymbolAddress((void**)&p_feats, g_feats_h);
    cudaGetSymbolAddress((void**)&p_xn,    g_xn_h);
    cudaGetSymbolAddress((void**)&p_qkvh,  g_qkv_h);
    cudaGetSymbolAddress((void**)&p_o,     g_o_h);
    cudaGetSymbolAddress((void**)&p_xn2,   g_xn2_h);
    cudaGetSymbolAddress((void**)&p_hh,    g_hh);
    cudaGetSymbolAddress((void**)&p_hg,    g_hg_h);
    cudaGetSymbolAddress((void**)&p_wc,    g_wcorr_h);
    cudaGetSymbolAddress((void**)&p_wq,    g_wqkv_h);
    cudaGetSymbolAddress((void**)&p_wo,    g_wout_h);
    cudaGetSymbolAddress((void**)&p_w1,    g_wff1_h);
    cudaGetSymbolAddress((void**)&p_w2,    g_wff2_h);

    static bool cfg = false;
    if (!cfg){
        cudaFuncSetAttribute(fattn_kernel, cudaFuncAttributeMaxDynamicSharedMemorySize,
                             ATTN_SMEM);
        cudaFuncSetAttribute(gemm_f16, cudaFuncAttributeMaxDynamicSharedMemorySize,
                             GEMM_SMEM);
        cudaFuncSetAttribute(gemm_f16_hout, cudaFuncAttributeMaxDynamicSharedMemorySize,
                             GEMM_SMEM);
        cfg = true;
    }

    const int M = Bsz * SEQ;   // 8192

    wconv_kernel<<<(WC_TOT + 255)/256, 256>>>(w_corr, w_qkv, w_out, w_ff1, w_ff2);
    bilinear_kernel<<<M, C2m>>>(fmaps, coords);
    gemm_f16<<<dim3(DIM/128, M/128), 256, GEMM_SMEM>>>(p_feats, p_wc, nullptr, x, p_x, M, DIM, C2m);
    rmsnorm_kernel<<<M, 128>>>(p_x, norm1, p_xn);
    gemm_f16_hout<<<dim3(3*DIM/128, M/128), 256, GEMM_SMEM>>>(p_xn, p_wq, nullptr, p_qkvh, M, 3*DIM, DIM);
    qkprep_kernel<<<M*NH*2/8, 256>>>(p_qkvh, theta, sq, sk);
    fattn_kernel<<<Bsz*NH*(SEQ/128), 256, ATTN_SMEM>>>(p_qkvh, p_o);
    gemm_f16<<<dim3(DIM/128, M/128), 256, GEMM_SMEM>>>(p_o, p_wo, nullptr, p_x, p_x2, M, DIM, DIM);
    rmsnorm_kernel<<<M, 128>>>(p_x2, norm2, p_xn2);
    gemm_f16_hout<<<dim3(2*FFm/128, M/128), 256, GEMM_SMEM>>>(p_xn2, p_w1, b_ff1, p_hh, M, 2*FFm, DIM);
    glu_kernel<<<(Bsz*SEQ*FFm)/2048, 256>>>(p_hh, p_hg);
    gemm_f16<<<dim3(DIM/128, M/128), 256, GEMM_SMEM>>>(p_hg, p_w2, nullptr, p_x2, out, M, DIM, FFm);
}

// round 15
// speedup vs baseline: 10.7654x; 1.0164x over previous
#include <cuda_runtime.h>
#include <cuda_fp16.h>
#include <math.h>
#include <stdint.h>

#define Bsz 4
#define SEQ 2048
#define DIM 512
#define NH  8
#define HDm 64
#define FFm 1024
#define C2m 128
#define HFm 64
#define WFm 64
#define EPSf 1e-6f

// ---------------- static scratch ----------------
__device__ float g_x   [Bsz*SEQ*DIM];
__device__ float g_x2  [Bsz*SEQ*DIM];
__device__ __half g_feats_h[Bsz*SEQ*C2m];
__device__ __half g_xn_h  [Bsz*SEQ*DIM];
__device__ __half g_qkv_h [Bsz*SEQ*3*DIM];
__device__ __half g_o_h   [Bsz*SEQ*DIM];
__device__ __half g_xn2_h [Bsz*SEQ*DIM];
__device__ __half g_hh    [Bsz*SEQ*2*FFm];
__device__ __half g_hg_h  [Bsz*SEQ*FFm];
__device__ __half g_wcorr_h[DIM*C2m];
__device__ __half g_wqkv_h [3*DIM*DIM];
__device__ __half g_wout_h [DIM*DIM];
__device__ __half g_wff1_h [2*FFm*DIM];
__device__ __half g_wff2_h [DIM*FFm];

__device__ __forceinline__ float warpSum(float v){
    #pragma unroll
    for (int o = 16; o > 0; o >>= 1) v += __shfl_xor_sync(0xFFFFFFFFu, v, o);
    return v;
}
__device__ __forceinline__ uint32_t pkh2(float x, float y){
    __half2 h = __floats2half2_rn(x, y);
    return *reinterpret_cast<uint32_t*>(&h);
}
__device__ __forceinline__ float geluf(float g){
    return 0.5f * g * (1.f + erff(g * 0.70710678118654752f));
}
__device__ __forceinline__ void mma_f16(float* c, const uint32_t* a, uint32_t b0, uint32_t b1){
    asm volatile(
        "mma.sync.aligned.m16n8k16.row.col.f32.f16.f16.f32 "
        "{%0,%1,%2,%3}, {%4,%5,%6,%7}, {%8,%9}, {%0,%1,%2,%3};"
        : "+f"(c[0]), "+f"(c[1]), "+f"(c[2]), "+f"(c[3])
        : "r"(a[0]), "r"(a[1]), "r"(a[2]), "r"(a[3]), "r"(b0), "r"(b1));
}
__device__ __forceinline__ void cp16(uint32_t smaddr, const void* g){
    asm volatile("cp.async.cg.shared.global [%0], [%1], 16;" :: "r"(smaddr), "l"(g));
}
#define CP_COMMIT() asm volatile("cp.async.commit_group;" ::: "memory")
#define CP_WAIT2()  asm volatile("cp.async.wait_group 2;" ::: "memory")
#define CP_WAIT0()  asm volatile("cp.async.wait_group 0;" ::: "memory")

// ---------------- fused weight conversion ----------------
#define WC_N0 ((DIM*C2m)/4)
#define WC_N1 ((3*DIM*DIM)/4)
#define WC_N2 ((DIM*DIM)/4)
#define WC_N3 ((2*FFm*DIM)/4)
#define WC_N4 ((DIM*FFm)/4)
#define WC_TOT (WC_N0+WC_N1+WC_N2+WC_N3+WC_N4)
__global__ void wconv_kernel(const float* __restrict__ s0, const float* __restrict__ s1,
                             const float* __restrict__ s2, const float* __restrict__ s3,
                             const float* __restrict__ s4){
    int i = blockIdx.x * 256 + threadIdx.x;
    if (i >= WC_TOT) return;
    const float* src; __half* dst;
    if (i < WC_N0){ src = s0; dst = g_wcorr_h; }
    else if ((i -= WC_N0) < WC_N1){ src = s1; dst = g_wqkv_h; }
    else if ((i -= WC_N1) < WC_N2){ src = s2; dst = g_wout_h; }
    else if ((i -= WC_N2) < WC_N3){ src = s3; dst = g_wff1_h; }
    else { i -= WC_N3; src = s4; dst = g_wff2_h; }
    float4 v = ((const float4*)src)[i];
    ((uint2*)dst)[i] = make_uint2(pkh2(v.x, v.y), pkh2(v.z, v.w));
}

// ---------------- bilinear (writes f16 feats) ----------------
__global__ void bilinear_kernel(const float* __restrict__ fmaps,
                                const float* __restrict__ coords){
    int bn = blockIdx.x;
    int b  = bn / SEQ;
    int c  = threadIdx.x;
    float xc = coords[(size_t)bn*2 + 0];
    float yc = coords[(size_t)bn*2 + 1];
    xc = fminf(fmaxf(xc, 0.f), (float)(WFm-1));
    yc = fminf(fmaxf(yc, 0.f), (float)(HFm-1));
    float x0 = floorf(xc), y0 = floorf(yc);
    float wx = xc - x0,    wy = yc - y0;
    int x0i = (int)x0, y0i = (int)y0;
    int x1i = min(x0i+1, WFm-1), y1i = min(y0i+1, HFm-1);
    const float* img = fmaps + ((size_t)(b*C2m + c))*HFm*WFm;
    float f00 = img[y0i*WFm + x0i];
    float f01 = img[y0i*WFm + x1i];
    float f10 = img[y1i*WFm + x0i];
    float f11 = img[y1i*WFm + x1i];
    float top = f00*(1.f-wx) + f01*wx;
    float bot = f10*(1.f-wx) + f11*wx;
    g_feats_h[(size_t)bn*C2m + c] = __float2half(top*(1.f-wy) + bot*wy);
}

// ---------------- f16 GEMM with cp.async 4-stage pipeline ----------------
#define BK 32
#define HSTR 20
#define PANEL_U32 (128*HSTR)
#define STAGE_U32 (2*PANEL_U32)
#define GEMM_SMEM (4*STAGE_U32*4)

#define GEMM_BODY(EPILOGUE)                                                     \
    extern __shared__ uint32_t smu[];                                           \
    uint32_t smbase = (uint32_t)__cvta_generic_to_shared(smu);                  \
    int tid = threadIdx.x;                                                      \
    int wid = tid >> 5, lane = tid & 31;                                        \
    int qr = lane >> 2, qc = lane & 3;                                          \
    int warp_m = wid & 3, warp_n = wid >> 2;                                    \
    int m0 = blockIdx.y * 128, n0 = blockIdx.x * 128;                           \
    const __half* Ab = A + (size_t)m0 * K;                                      \
    const __half* Wb = W + (size_t)n0 * K;                                      \
    int crow = tid >> 1;                                                        \
    int ccol = (tid & 1) * 2;                                                   \
    int T = K / BK;                                                             \
    _Pragma("unroll")                                                           \
    for (int s = 0; s < 3; s++){                                                \
        if (s < T){                                                             \
            int k0 = s * BK;                                                    \
            uint32_t base = smbase + (s & 3) * (STAGE_U32*4);                   \
            const __half* as = Ab + (size_t)crow*K + k0 + ccol*8;               \
            const __half* ws = Wb + (size_t)crow*K + k0 + ccol*8;               \
            uint32_t da = base + crow*80 + ccol*16;                             \
            uint32_t db = base + PANEL_U32*4 + crow*80 + ccol*16;               \
            cp16(da, as);      cp16(da + 16, as + 8);                           \
            cp16(db, ws);      cp16(db + 16, ws + 8);                           \
        }                                                                       \
        CP_COMMIT();                                                            \
    }                                                                           \
    float acc[2][8][4];                                                         \
    _Pragma("unroll")                                                           \
    for (int mt = 0; mt < 2; mt++)                                              \
        _Pragma("unroll")                                                       \
        for (int nt = 0; nt < 8; nt++)                                          \
            _Pragma("unroll")                                                   \
            for (int i = 0; i < 4; i++) acc[mt][nt][i] = 0.f;                   \
    for (int t = 0; t < T; t++){                                                \
        CP_WAIT2();                                                             \
        __syncthreads();                                                        \
        if (t + 3 < T){                                                         \
            int k0 = (t+3) * BK;                                                \
            uint32_t base = smbase + ((t+3) & 3) * (STAGE_U32*4);               \
            const __half* as = Ab + (size_t)crow*K + k0 + ccol*8;               \
            const __half* ws = Wb + (size_t)crow*K + k0 + ccol*8;               \
            uint32_t da = base + crow*80 + ccol*16;                             \
            uint32_t db = base + PANEL_U32*4 + crow*80 + ccol*16;               \
            cp16(da, as);      cp16(da + 16, as + 8);                           \
            cp16(db, ws);      cp16(db + 16, ws + 8);                           \
        }                                                                       \
        CP_COMMIT();                                                            \
        const uint32_t* As = smu + (t & 3) * STAGE_U32;                         \
        const uint32_t* Bs = As + PANEL_U32;                                    \
        _Pragma("unroll")                                                       \
        for (int ks = 0; ks < 2; ks++){                                         \
            int k8 = ks * 8;                                                    \
            uint32_t af[2][4];                                                  \
            _Pragma("unroll")                                                   \
            for (int mt = 0; mt < 2; mt++){                                     \
                int r0 = warp_m*32 + mt*16 + qr;                                \
                af[mt][0] = As[ r0     *HSTR + k8 + qc];                        \
                af[mt][1] = As[(r0 + 8)*HSTR + k8 + qc];                        \
                af[mt][2] = As[ r0     *HSTR + k8 + 4 + qc];                    \
                af[mt][3] = As[(r0 + 8)*HSTR + k8 + 4 + qc];                    \
            }                                                                   \
            _Pragma("unroll")                                                   \
            for (int nt = 0; nt < 8; nt++){                                     \
                int cb = warp_n*64 + nt*8 + qr;                                 \
                uint32_t b0 = Bs[cb*HSTR + k8 + qc];                            \
                uint32_t b1 = Bs[cb*HSTR + k8 + 4 + qc];                        \
                mma_f16(acc[0][nt], af[0], b0, b1);                             \
                mma_f16(acc[1][nt], af[1], b0, b1);                             \
            }                                                                   \
        }                                                                       \
    }                                                                           \
    EPILOGUE

__global__ __launch_bounds__(256, 2)
void gemm_f16(const __half* __restrict__ A, const __half* __restrict__ W,
              const float* __restrict__ bias, const float* __restrict__ resid,
              float* __restrict__ C, int M, int Nout, int K){
    GEMM_BODY({
        _Pragma("unroll")
        for (int mt = 0; mt < 2; mt++){
            _Pragma("unroll")
            for (int nt = 0; nt < 8; nt++){
                int row = m0 + warp_m*32 + mt*16 + qr;
                int col = n0 + warp_n*64 + nt*8 + qc*2;
                float2 v0 = make_float2(acc[mt][nt][0], acc[mt][nt][1]);
                float2 v1 = make_float2(acc[mt][nt][2], acc[mt][nt][3]);
                if (bias){
                    float2 bb = *(const float2*)(bias + col);
                    v0.x += bb.x; v0.y += bb.y;
                    v1.x += bb.x; v1.y += bb.y;
                }
                size_t off0 = (size_t)row * Nout + col;
                size_t off1 = (size_t)(row + 8) * Nout + col;
                if (resid){
                    float2 r0 = *(const float2*)(resid + off0);
                    float2 r1 = *(const float2*)(resid + off1);
                    v0.x += r0.x; v0.y += r0.y;
                    v1.x += r1.x; v1.y += r1.y;
                }
                *(float2*)(C + off0) = v0;
                *(float2*)(C + off1) = v1;
            }
        }
    })
}

__global__ __launch_bounds__(256, 2)
void gemm_f16_hout(const __half* __restrict__ A, const __half* __restrict__ W,
                   const float* __restrict__ bias,
                   __half* __restrict__ C, int M, int Nout, int K){
    GEMM_BODY({
        _Pragma("unroll")
        for (int mt = 0; mt < 2; mt++){
            _Pragma("unroll")
            for (int nt = 0; nt < 8; nt++){
                int row = m0 + warp_m*32 + mt*16 + qr;
                int col = n0 + warp_n*64 + nt*8 + qc*2;
                float2 v0 = make_float2(acc[mt][nt][0], acc[mt][nt][1]);
                float2 v1 = make_float2(acc[mt][nt][2], acc[mt][nt][3]);
                if (bias){
                    float2 bb = *(const float2*)(bias + col);
                    v0.x += bb.x; v0.y += bb.y;
                    v1.x += bb.x; v1.y += bb.y;
                }
                size_t off0 = (size_t)row * Nout + col;
                size_t off1 = (size_t)(row + 8) * Nout + col;
                *(uint32_t*)(C + off0) = pkh2(v0.x, v0.y);
                *(uint32_t*)(C + off1) = pkh2(v1.x, v1.y);
            }
        }
    })
}

// ---------------- RMSNorm over DIM=512 (f32 in, f16 out) ----------------
__global__ void rmsnorm_kernel(const float* __restrict__ X,
                               const float* __restrict__ scale,
                               __half* __restrict__ Y){
    int row = blockIdx.x;
    int t   = threadIdx.x;  // 128
    const float4* x4 = (const float4*)(X + (size_t)row*DIM);
    float4 v = x4[t];
    float ss = v.x*v.x + v.y*v.y + v.z*v.z + v.w*v.w;
    ss = warpSum(ss);
    __shared__ float red[4];
    if ((t & 31) == 0) red[t >> 5] = ss;
    __syncthreads();
    if (t == 0) red[0] = red[0] + red[1] + red[2] + red[3];
    __syncthreads();
    float inv = rsqrtf(red[0] / (float)DIM + EPSf);
    float4 s = ((const float4*)scale)[t];
    ((uint2*)(Y + (size_t)row*DIM))[t] =
        make_uint2(pkh2(v.x*s.x*inv, v.y*s.y*inv), pkh2(v.z*s.z*inv, v.w*s.w*inv));
}

// ---------------- per-head RMSNorm + rotary on f16 qkv ----------------
__global__ __launch_bounds__(256)
void qkprep_kernel(__half* __restrict__ qkv, const float* __restrict__ theta,
                   const float* __restrict__ sq, const float* __restrict__ sk){
    int t = blockIdx.x * 8 + (threadIdx.x >> 5);
    int isK = t & 1; int rest = t >> 1;
    int h = rest % NH; rest /= NH;
    int n = rest % SEQ; int b = rest / SEQ;
    int lane = threadIdx.x & 31;
    __half* p = qkv + ((size_t)(b*SEQ + n))*(3*DIM) + isK*DIM + h*HDm;
    float v0 = __half2float(p[lane]);
    float v1 = __half2float(p[lane + 32]);
    float ss = warpSum(v0*v0 + v1*v1);
    float inv = rsqrtf(ss / (float)HDm + EPSf);
    const float* sc = isK ? sk : sq;
    v0 = v0 * sc[lane]      * inv;
    v1 = v1 * sc[lane + 32] * inv;
    float th = theta[(((size_t)(b*NH + h))*SEQ + n)*(HDm/2) + lane];
    float cs = cosf(th), sn = sinf(th);
    p[lane]      = __float2half(v0*cs - v1*sn);
    p[lane + 32] = __float2half(v1*cs + v0*sn);
}

// ---------------- flash attention: K cp.async double-buffer + V reg prefetch ----------------
#define QSTR 36
#define FK0_OFF 0
#define FK1_OFF (128*QSTR)
#define FP_OFF  (2*128*QSTR)
#define FVT_OFF (2*128*QSTR + 128*68)
#define ATTN_SMEM ((2*128*QSTR + 128*68 + 2*64*68)*4)

__global__ __launch_bounds__(256, 2)
void fattn_kernel(const __half* __restrict__ qkv, __half* __restrict__ O){
    extern __shared__ uint32_t smu[];
    uint32_t smbase = (uint32_t)__cvta_generic_to_shared(smu);
    uint32_t* Ps = smu + FP_OFF;

    int tid = threadIdx.x;
    int w = tid >> 5, lane = tid & 31;
    int qr = lane >> 2, qc = lane & 3;
    int bh = blockIdx.x >> 4;
    int qt = blockIdx.x & 15;
    int b = bh >> 3, h = bh & 7;
    int i0 = qt * 128;

    int ldr = tid >> 1;
    int ldc = (tid & 1) * 32;
    int jp = tid >> 2;
    int dg = (tid & 3) * 16;

    const __half* kvbase = qkv + (size_t)b*SEQ*3*DIM;

    // issue cp.async K(0) -> K0
    {
        const __half* src = kvbase + (size_t)(0 + ldr)*(3*DIM) + DIM + h*HDm + ldc;
        uint32_t da = smbase + (FK0_OFF + ldr*QSTR + (ldc>>1))*4;
        cp16(da, src); cp16(da+16, src+8); cp16(da+32, src+16); cp16(da+48, src+24);
        CP_COMMIT();
    }
    // stage V(0) in regs
    uint32_t av[8], bv[8];
    {
        const __half* vp = kvbase + (size_t)(2*jp)*(3*DIM) + 2*DIM + h*HDm + dg;
        uint4 a0 = *(const uint4*)(vp);
        uint4 a1 = *(const uint4*)(vp + 8);
        uint4 b0v = *(const uint4*)(vp + 3*DIM);
        uint4 b1v = *(const uint4*)(vp + 3*DIM + 8);
        av[0]=a0.x; av[1]=a0.y; av[2]=a0.z; av[3]=a0.w;
        av[4]=a1.x; av[5]=a1.y; av[6]=a1.z; av[7]=a1.w;
        bv[0]=b0v.x; bv[1]=b0v.y; bv[2]=b0v.z; bv[3]=b0v.w;
        bv[4]=b1v.x; bv[5]=b1v.y; bv[6]=b1v.z; bv[7]=b1v.w;
    }
    // Q tile -> K1 region (sync)
    {
        const __half* src = kvbase + (size_t)(i0 + ldr)*(3*DIM) + h*HDm + ldc;
        uint32_t* dst = smu + FK1_OFF + ldr*QSTR + (ldc>>1);
        *(uint4*)(dst + 0) = *(const uint4*)(src + 0);
        *(uint4*)(dst + 4) = *(const uint4*)(src + 8);
        *(uint4*)(dst + 8) = *(const uint4*)(src + 16);
        *(uint4*)(dst +12) = *(const uint4*)(src + 24);
    }
    __syncthreads();

    uint32_t aQ[4][4];
    {
        const uint32_t* Qs = smu + FK1_OFF;
        #pragma unroll
        for (int ks = 0; ks < 4; ks++){
            int r0 = w*16 + qr;
            aQ[ks][0] = Qs[ r0     *QSTR + ks*8 + qc];
            aQ[ks][1] = Qs[(r0 + 8)*QSTR + ks*8 + qc];
            aQ[ks][2] = Qs[ r0     *QSTR + ks*8 + 4 + qc];
            aQ[ks][3] = Qs[(r0 + 8)*QSTR + ks*8 + 4 + qc];
        }
    }

    float Oacc[8][4];
    #pragma unroll
    for (int nt = 0; nt < 8; nt++)
        #pragma unroll
        for (int i = 0; i < 4; i++) Oacc[nt][i] = 0.f;
    float m0 = -INFINITY, m1 = -INFINITY, l0 = 0.f, l1 = 0.f;

    const int T = SEQ/128;
    for (int t = 0; t < T; t++){
        int buf = t & 1;
        uint32_t* Vt = smu + FVT_OFF + buf*(64*68);
        const uint32_t* Ks = smu + (buf ? FK1_OFF : FK0_OFF);

        // store staged V(t) into Vt[buf] (xor swizzle)
        #pragma unroll
        for (int i = 0; i < 8; i++){
            int d0 = dg + 2*i;
            int s0 = jp ^ ((((d0  )>>4)&3)<<3);
            int s1 = jp ^ ((((d0+1)>>4)&3)<<3);
            Vt[(d0  )*68 + s0] = __byte_perm(av[i], bv[i], 0x5410);
            Vt[(d0+1)*68 + s1] = __byte_perm(av[i], bv[i], 0x7632);
        }
        CP_WAIT0();          // K(t) arrived
        __syncthreads();     // A: K(t), V(t) visible; prior PV done

        // prefetch K(t+1) into the other K buffer
        if (t + 1 < T){
            int j1 = (t+1) * 128;
            uint32_t koff = (buf ? FK0_OFF : FK1_OFF);
            const __half* src = kvbase + (size_t)(j1 + ldr)*(3*DIM) + DIM + h*HDm + ldc;
            uint32_t da = smbase + (koff + ldr*QSTR + (ldc>>1))*4;
            cp16(da, src); cp16(da+16, src+8); cp16(da+32, src+16); cp16(da+48, src+24);
        }
        CP_COMMIT();

        // S = Q K^T
        float S[16][4];
        #pragma unroll
        for (int nt = 0; nt < 16; nt++){
            S[nt][0] = S[nt][1] = S[nt][2] = S[nt][3] = 0.f;
            #pragma unroll
            for (int ks = 0; ks < 4; ks++){
                int cb = nt*8 + qr;
                uint32_t b0 = Ks[cb*QSTR + ks*8 + qc];
                uint32_t b1 = Ks[cb*QSTR + ks*8 + 4 + qc];
                mma_f16(S[nt], aQ[ks], b0, b1);
            }
        }

        // online softmax
        float mx0 = -INFINITY, mx1 = -INFINITY;
        #pragma unroll
        for (int nt = 0; nt < 16; nt++){
            mx0 = fmaxf(mx0, fmaxf(S[nt][0], S[nt][1]));
            mx1 = fmaxf(mx1, fmaxf(S[nt][2], S[nt][3]));
        }
        mx0 = fmaxf(mx0, __shfl_xor_sync(0xFFFFFFFFu, mx0, 1));
        mx0 = fmaxf(mx0, __shfl_xor_sync(0xFFFFFFFFu, mx0, 2));
        mx1 = fmaxf(mx1, __shfl_xor_sync(0xFFFFFFFFu, mx1, 1));
        mx1 = fmaxf(mx1, __shfl_xor_sync(0xFFFFFFFFu, mx1, 2));
        float nm0 = fmaxf(m0, mx0), nm1 = fmaxf(m1, mx1);
        float sc0 = __expf(m0 - nm0), sc1 = __expf(m1 - nm1);
        m0 = nm0; m1 = nm1;
        float rs0 = 0.f, rs1 = 0.f;
        #pragma unroll
        for (int nt = 0; nt < 16; nt++){
            float p0 = __expf(S[nt][0] - nm0);
            float p1 = __expf(S[nt][1] - nm0);
            float p2 = __expf(S[nt][2] - nm1);
            float p3 = __expf(S[nt][3] - nm1);
            S[nt][0] = p0; S[nt][1] = p1; S[nt][2] = p2; S[nt][3] = p3;
            rs0 += p0 + p1; rs1 += p2 + p3;
        }
        rs0 += __shfl_xor_sync(0xFFFFFFFFu, rs0, 1);
        rs0 += __shfl_xor_sync(0xFFFFFFFFu, rs0, 2);
        rs1 += __shfl_xor_sync(0xFFFFFFFFu, rs1, 1);
        rs1 += __shfl_xor_sync(0xFFFFFFFFu, rs1, 2);
        l0 = l0 * sc0 + rs0;
        l1 = l1 * sc1 + rs1;
        #pragma unroll
        for (int nt = 0; nt < 8; nt++){
            Oacc[nt][0] *= sc0; Oacc[nt][1] *= sc0;
            Oacc[nt][2] *= sc1; Oacc[nt][3] *= sc1;
        }

        // write P tiles to smem (f16) — last use of S
        {
            int r0 = w*16 + qr, r1 = r0 + 8;
            #pragma unroll
            for (int nt = 0; nt < 16; nt++){
                Ps[r0*68 + nt*4 + qc] = pkh2(S[nt][0], S[nt][1]);
                Ps[r1*68 + nt*4 + qc] = pkh2(S[nt][2], S[nt][3]);
            }
        }

        // prefetch V(t+1) into regs — S is dead now, no register-pressure peak;
        // latency hidden by barrier B + the 64-MMA PV loop
        if (t + 1 < T){
            const __half* vp = kvbase + (size_t)((t+1)*128 + 2*jp)*(3*DIM) + 2*DIM + h*HDm + dg;
            uint4 a0 = *(const uint4*)(vp);
            uint4 a1 = *(const uint4*)(vp + 8);
            uint4 b0v = *(const uint4*)(vp + 3*DIM);
            uint4 b1v = *(const uint4*)(vp + 3*DIM + 8);
            av[0]=a0.x; av[1]=a0.y; av[2]=a0.z; av[3]=a0.w;
            av[4]=a1.x; av[5]=a1.y; av[6]=a1.z; av[7]=a1.w;
            bv[0]=b0v.x; bv[1]=b0v.y; bv[2]=b0v.z; bv[3]=b0v.w;
            bv[4]=b1v.x; bv[5]=b1v.y; bv[6]=b1v.z; bv[7]=b1v.w;
        }
        __syncthreads();     // B: P + Vt[buf] ready for all

        // O += P V
        #pragma unroll
        for (int ks = 0; ks < 8; ks++){
            uint32_t aP[4];
            int r0 = w*16 + qr, r1 = r0 + 8;
            aP[0] = Ps[r0*68 + ks*8 + qc];
            aP[1] = Ps[r1*68 + ks*8 + qc];
            aP[2] = Ps[r0*68 + ks*8 + 4 + qc];
            aP[3] = Ps[r1*68 + ks*8 + 4 + qc];
            #pragma unroll
            for (int nt = 0; nt < 8; nt++){
                int drow = nt*8 + qr;
                int swz = (nt >> 1) << 3;
                uint32_t b0 = Vt[drow*68 + ((ks*8 + qc) ^ swz)];
                uint32_t b1 = Vt[drow*68 + ((ks*8 + 4 + qc) ^ swz)];
                mma_f16(Oacc[nt], aP, b0, b1);
            }
        }
    }

    float il0 = 1.f / l0, il1 = 1.f / l1;
    int row0 = i0 + w*16 + qr, row1 = row0 + 8;
    #pragma unroll
    for (int nt = 0; nt < 8; nt++){
        int col = h*HDm + nt*8 + 2*qc;
        *(uint32_t*)(O + ((size_t)(b*SEQ) + row0)*DIM + col) =
            pkh2(Oacc[nt][0]*il0, Oacc[nt][1]*il0);
        *(uint32_t*)(O + ((size_t)(b*SEQ) + row1)*DIM + col) =
            pkh2(Oacc[nt][2]*il1, Oacc[nt][3]*il1);
    }
}

// ---------------- gated GELU (f16 in, f16 out) ----------------
__global__ void glu_kernel(const __half* __restrict__ Hh, __half* __restrict__ Hg){
    size_t i8 = ((size_t)blockIdx.x * 256 + threadIdx.x) * 8;
    size_t m = i8 / FFm, f = i8 % FFm;
    uint4 hx4 = *(const uint4*)(Hh + m*(2*FFm) + f);
    uint4 g4  = *(const uint4*)(Hh + m*(2*FFm) + FFm + f);
    const uint32_t* hxp = &hx4.x;
    const uint32_t* gp  = &g4.x;
    uint4 o;
    uint32_t* op = &o.x;
    #pragma unroll
    for (int i = 0; i < 4; i++){
        __half2 hh = *reinterpret_cast<const __half2*>(&hxp[i]);
        __half2 gg = *reinterpret_cast<const __half2*>(&gp[i]);
        float2 hf = __half22float2(hh);
        float2 gf = __half22float2(gg);
        op[i] = pkh2(hf.x * geluf(gf.x), hf.y * geluf(gf.y));
    }
    *(uint4*)(Hg + i8) = o;
}

// ---------------- launch ----------------
extern "C" void kernel_launch(void* const* d_in, const int* in_sizes, int n_in,
                              void* d_out, int out_size){
    const float* x       = (const float*)d_in[0];
    const float* theta   = (const float*)d_in[1];
    const float* fmaps   = (const float*)d_in[2];
    const float* coords  = (const float*)d_in[3];
    const float* w_corr  = (const float*)d_in[4];
    const float* norm1   = (const float*)d_in[5];
    const float* sq      = (const float*)d_in[6];
    const float* sk      = (const float*)d_in[7];
    const float* w_qkv   = (const float*)d_in[8];
    const float* w_out   = (const float*)d_in[9];
    const float* norm2   = (const float*)d_in[10];
    const float* w_ff1   = (const float*)d_in[11];
    const float* b_ff1   = (const float*)d_in[12];
    const float* w_ff2   = (const float*)d_in[13];
    float* out = (float*)d_out;

    float *p_x, *p_x2;
    __half *p_feats, *p_xn, *p_qkvh, *p_o, *p_xn2, *p_hh, *p_hg;
    __half *p_wc, *p_wq, *p_wo, *p_w1, *p_w2;
    cudaGetSymbolAddress((void**)&p_x,     g_x);
    cudaGetSymbolAddress((void**)&p_x2,    g_x2);
    cudaGetSymbolAddress((void**)&p_feats, g_feats_h);
    cudaGetSymbolAddress((void**)&p_xn,    g_xn_h);
    cudaGetSymbolAddress((void**)&p_qkvh,  g_qkv_h);
    cudaGetSymbolAddress((void**)&p_o,     g_o_h);
    cudaGetSymbolAddress((void**)&p_xn2,   g_xn2_h);
    cudaGetSymbolAddress((void**)&p_hh,    g_hh);
    cudaGetSymbolAddress((void**)&p_hg,    g_hg_h);
    cudaGetSymbolAddress((void**)&p_wc,    g_wcorr_h);
    cudaGetSymbolAddress((void**)&p_wq,    g_wqkv_h);
    cudaGetSymbolAddress((void**)&p_wo,    g_wout_h);
    cudaGetSymbolAddress((void**)&p_w1,    g_wff1_h);
    cudaGetSymbolAddress((void**)&p_w2,    g_wff2_h);

    static bool cfg = false;
    if (!cfg){
        cudaFuncSetAttribute(fattn_kernel, cudaFuncAttributeMaxDynamicSharedMemorySize,
                             ATTN_SMEM);
        cudaFuncSetAttribute(gemm_f16, cudaFuncAttributeMaxDynamicSharedMemorySize,
                             GEMM_SMEM);
        cudaFuncSetAttribute(gemm_f16_hout, cudaFuncAttributeMaxDynamicSharedMemorySize,
                             GEMM_SMEM);
        cfg = true;
    }

    const int M = Bsz * SEQ;   // 8192

    wconv_kernel<<<(WC_TOT + 255)/256, 256>>>(w_corr, w_qkv, w_out, w_ff1, w_ff2);
    bilinear_kernel<<<M, C2m>>>(fmaps, coords);
    gemm_f16<<<dim3(DIM/128, M/128), 256, GEMM_SMEM>>>(p_feats, p_wc, nullptr, x, p_x, M, DIM, C2m);
    rmsnorm_kernel<<<M, 128>>>(p_x, norm1, p_xn);
    gemm_f16_hout<<<dim3(3*DIM/128, M/128), 256, GEMM_SMEM>>>(p_xn, p_wq, nullptr, p_qkvh, M, 3*DIM, DIM);
    qkprep_kernel<<<M*NH*2/8, 256>>>(p_qkvh, theta, sq, sk);
    fattn_kernel<<<Bsz*NH*(SEQ/128), 256, ATTN_SMEM>>>(p_qkvh, p_o);
    gemm_f16<<<dim3(DIM/128, M/128), 256, GEMM_SMEM>>>(p_o, p_wo, nullptr, p_x, p_x2, M, DIM, DIM);
    rmsnorm_kernel<<<M, 128>>>(p_x2, norm2, p_xn2);
    gemm_f16_hout<<<dim3(2*FFm/128, M/128), 256, GEMM_SMEM>>>(p_xn2, p_w1, b_ff1, p_hh, M, 2*FFm, DIM);
    glu_kernel<<<(Bsz*SEQ*FFm)/2048, 256>>>(p_hh, p_hg);
    gemm_f16<<<dim3(DIM/128, M/128), 256, GEMM_SMEM>>>(p_hg, p_w2, nullptr, p_x2, out, M, DIM, FFm);
}